// round 2
// baseline (speedup 1.0000x reference)
#include <cuda_runtime.h>
#include <math.h>

// Problem constants
#define Bn   4
#define Sn   4096
#define Dn   1024
#define Hn   16
#define HDn  64
#define SEGn 64
#define NSn  64
#define NTOK (Bn*Sn)          // 16384
#define NEGV (-1.0e10f)

// ---------------------------------------------------------------------------
// Scratch (device globals: the sanctioned alloc-free workaround)
// ---------------------------------------------------------------------------
__device__ float g_q      [(size_t)NTOK*Dn];
__device__ float g_k      [(size_t)NTOK*Dn];
__device__ float g_v      [(size_t)NTOK*Dn];
__device__ float g_rowattn[(size_t)NTOK*Dn];
__device__ float g_t1     [(size_t)NTOK*Dn];   // rowattn@Wrow_out + x
__device__ float g_t2     [(size_t)NTOK*Dn];   // LN(...)
__device__ float g_krow   [(size_t)NTOK*Dn];   // @Wk2
__device__ float g_merged [(size_t)NTOK*Dn];
__device__ float g_joint  [(size_t)NTOK*Hn*128]; // [t][h][0:64 local | 64:128 global]

// Buffer selection without host-side symbol lookups
__device__ __forceinline__ const float* apick(const float* ext, int id){
    switch(id){ case 1: return g_rowattn; case 2: return g_t2; case 3: return g_merged; }
    return ext;
}
__device__ __forceinline__ float* cpick(float* ext, int id){
    switch(id){ case 1: return g_q; case 2: return g_k; case 3: return g_v;
                case 4: return g_t1; case 5: return g_krow; }
    return ext;
}

// ---------------------------------------------------------------------------
// SGEMM: C[M=16384, 1024] = alpha * A[M,1024] @ Bw[1024,1024] (+ R)
// 128x128 tile, BK=16, 256 threads, 8x8 microtile
// ---------------------------------------------------------------------------
__global__ void __launch_bounds__(256,2)
sgemm_kernel(const float* __restrict__ Aext, int Aid,
             const float* __restrict__ Bw,
             float* Cext, int Cid,
             const float* __restrict__ R, float alpha)
{
    const float* A = apick(Aext, Aid);
    float*       C = cpick(Cext, Cid);

    __shared__ float As[16][132];   // transposed A tile, padded
    __shared__ float Bs[16][128];

    int tid = threadIdx.x;
    int tx = tid & 15, ty = tid >> 4;
    int rowBase = blockIdx.y * 128;
    int colBase = blockIdx.x * 128;

    float acc[8][8];
    #pragma unroll
    for (int i=0;i<8;i++)
        #pragma unroll
        for (int j=0;j<8;j++) acc[i][j]=0.f;

    for (int k0 = 0; k0 < Dn; k0 += 16) {
        #pragma unroll
        for (int t2 = 0; t2 < 2; t2++) {
            int idx = tid + t2*256;
            int r  = idx >> 2;
            int c4 = (idx & 3) << 2;
            float4 av = *(const float4*)(A + (size_t)(rowBase + r)*Dn + k0 + c4);
            As[c4+0][r]=av.x; As[c4+1][r]=av.y; As[c4+2][r]=av.z; As[c4+3][r]=av.w;
            int rB = idx >> 5;
            int cB = (idx & 31) << 2;
            *(float4*)&Bs[rB][cB] = *(const float4*)(Bw + (size_t)(k0+rB)*Dn + colBase + cB);
        }
        __syncthreads();
        #pragma unroll
        for (int kk = 0; kk < 16; kk++) {
            float a[8], bb[8];
            *(float4*)(a)    = *(const float4*)&As[kk][ty*8];
            *(float4*)(a+4)  = *(const float4*)&As[kk][ty*8+4];
            *(float4*)(bb)   = *(const float4*)&Bs[kk][tx*8];
            *(float4*)(bb+4) = *(const float4*)&Bs[kk][tx*8+4];
            #pragma unroll
            for (int i=0;i<8;i++)
                #pragma unroll
                for (int j=0;j<8;j++) acc[i][j] += a[i]*bb[j];
        }
        __syncthreads();
    }

    #pragma unroll
    for (int i=0;i<8;i++){
        size_t off = (size_t)(rowBase + ty*8 + i)*Dn + colBase + tx*8;
        #pragma unroll
        for (int j4=0;j4<2;j4++){
            float4 v;
            v.x = alpha*acc[i][j4*4+0];
            v.y = alpha*acc[i][j4*4+1];
            v.z = alpha*acc[i][j4*4+2];
            v.w = alpha*acc[i][j4*4+3];
            if (R){
                float4 rv = *(const float4*)(R + off + j4*4);
                v.x+=rv.x; v.y+=rv.y; v.z+=rv.z; v.w+=rv.w;
            }
            *(float4*)(C + off + j4*4) = v;
        }
    }
}

// ---------------------------------------------------------------------------
// Local attention per (h, seg, b):
//   logits = q@k^T (64x64); masked logits -> joint[:,0:64];
//   row_probs = softmax(unmasked); row_attn = row_probs@v -> g_rowattn
// ---------------------------------------------------------------------------
__global__ void __launch_bounds__(256)
local_attn_kernel()
{
    extern __shared__ float sm[];
    float* qs = sm;               // [64][65]
    float* ks = sm + 64*65;       // [64][65] (reused for probs)
    float* vs = sm + 2*64*65;     // [64][65]

    int h = blockIdx.x, seg = blockIdx.y, b = blockIdx.z;
    int tid = threadIdx.x;
    size_t tok0 = ((size_t)b*NSn + seg)*SEGn;

    for (int i = tid; i < 64*64; i += 256) {
        int r = i >> 6, c = i & 63;
        size_t off = (tok0 + r)*Dn + h*HDn + c;
        qs[r*65+c] = g_q[off];
        ks[r*65+c] = g_k[off];
        vs[r*65+c] = g_v[off];
    }
    __syncthreads();

    int row = tid >> 2, quad = tid & 3;    // row owns the query, quad owns 16 keys
    float lg[16];
    #pragma unroll
    for (int c=0;c<16;c++) lg[c]=0.f;
    for (int d = 0; d < 64; d++) {
        float qd = qs[row*65+d];
        #pragma unroll
        for (int c=0;c<16;c++) lg[c] += qd * ks[(quad*16+c)*65 + d];
    }

    // masked logits into joint buffer (mask: future key within segment)
    size_t jb = ((tok0 + row)*Hn + h)*128;
    #pragma unroll
    for (int c=0;c<16;c++) {
        int col = quad*16+c;
        g_joint[jb + col] = lg[c] + (row < col ? NEGV : 0.f);
    }

    // UNMASKED softmax across the 64 keys (spread over quad of 4 lanes)
    float m = -1e30f;
    #pragma unroll
    for (int c=0;c<16;c++) m = fmaxf(m, lg[c]);
    m = fmaxf(m, __shfl_xor_sync(0xffffffffu, m, 1));
    m = fmaxf(m, __shfl_xor_sync(0xffffffffu, m, 2));
    float ssum = 0.f;
    #pragma unroll
    for (int c=0;c<16;c++){ lg[c] = __expf(lg[c]-m); ssum += lg[c]; }
    ssum += __shfl_xor_sync(0xffffffffu, ssum, 1);
    ssum += __shfl_xor_sync(0xffffffffu, ssum, 2);
    float inv = 1.f/ssum;

    __syncthreads();                       // everyone done reading ks
    #pragma unroll
    for (int c=0;c<16;c++) ks[row*65 + quad*16 + c] = lg[c];   // unnormalized probs
    __syncthreads();

    // row_attn[row][quad*16+dd] = sum_c p[row][c]*v[c][...] * inv
    float o[16];
    #pragma unroll
    for (int dd=0;dd<16;dd++) o[dd]=0.f;
    for (int c2=0;c2<64;c2++){
        float p = ks[row*65+c2];
        #pragma unroll
        for (int dd=0;dd<16;dd++) o[dd] += p * vs[c2*65 + quad*16 + dd];
    }
    size_t ob = (tok0+row)*Dn + h*HDn + quad*16;
    #pragma unroll
    for (int dd=0;dd<16;dd++) g_rowattn[ob+dd] = o[dd]*inv;
}

// ---------------------------------------------------------------------------
// LayerNorm over D=1024 per token: g_t2 = LN(g_t1)*scale + bias
// ---------------------------------------------------------------------------
__global__ void __launch_bounds__(256)
ln_kernel(const float* __restrict__ scale, const float* __restrict__ bias)
{
    size_t row = blockIdx.x;
    int tid = threadIdx.x;
    float4 v = ((const float4*)(g_t1 + row*Dn))[tid];
    float s  = v.x+v.y+v.z+v.w;
    float ss = v.x*v.x+v.y*v.y+v.z*v.z+v.w*v.w;
    #pragma unroll
    for (int o=16;o;o>>=1){
        s  += __shfl_xor_sync(0xffffffffu, s, o);
        ss += __shfl_xor_sync(0xffffffffu, ss, o);
    }
    __shared__ float sh[16];
    int w = tid>>5, lane = tid&31;
    if (lane==0){ sh[w]=s; sh[8+w]=ss; }
    __syncthreads();
    if (tid==0){
        float a=0.f,b2=0.f;
        #pragma unroll
        for (int i=0;i<8;i++){ a+=sh[i]; b2+=sh[8+i]; }
        float mu  = a*(1.f/Dn);
        float var = b2*(1.f/Dn) - mu*mu;
        sh[0]=mu; sh[1]=rsqrtf(var + 1e-6f);
    }
    __syncthreads();
    float mu = sh[0], rstd = sh[1];
    float4 sc = ((const float4*)scale)[tid];
    float4 bi = ((const float4*)bias)[tid];
    float4 o4;
    o4.x=(v.x-mu)*rstd*sc.x+bi.x;
    o4.y=(v.y-mu)*rstd*sc.y+bi.y;
    o4.z=(v.z-mu)*rstd*sc.z+bi.z;
    o4.w=(v.w-mu)*rstd*sc.w+bi.w;
    ((float4*)(g_t2 + row*Dn))[tid] = o4;
}

// ---------------------------------------------------------------------------
// Global logits per (h, l, b): across segments at fixed in-segment position l
//   G[qseg][kseg] = q[b,qseg,l,h,:] . krow[b,kseg,l,h,:]; mask qseg<=kseg
// ---------------------------------------------------------------------------
__global__ void __launch_bounds__(256)
global_logits_kernel()
{
    __shared__ float qg[64][65];
    __shared__ float kg[64][65];
    int h = blockIdx.x, l = blockIdx.y, b = blockIdx.z;
    int tid = threadIdx.x;
    for (int i = tid; i < 64*64; i += 256){
        int r = i>>6, c = i&63;
        size_t t = ((size_t)b*NSn + r)*SEGn + l;
        qg[r][c] = g_q   [t*Dn + h*HDn + c];
        kg[r][c] = g_krow[t*Dn + h*HDn + c];
    }
    __syncthreads();
    int row = tid>>2, quad = tid&3;
    float lg[16];
    #pragma unroll
    for (int c=0;c<16;c++) lg[c]=0.f;
    for (int d=0; d<64; d++){
        float qd = qg[row][d];
        #pragma unroll
        for (int c=0;c<16;c++) lg[c] += qd * kg[quad*16+c][d];
    }
    size_t t  = ((size_t)b*NSn + row)*SEGn + l;
    size_t jb = (t*Hn + h)*128 + 64;
    #pragma unroll
    for (int c=0;c<16;c++){
        int col = quad*16+c;
        g_joint[jb + col] = lg[c] + (row <= col ? NEGV : 0.f);
    }
}

// ---------------------------------------------------------------------------
// Joint softmax over 128-wide rows of g_joint (one warp per row, in place)
// ---------------------------------------------------------------------------
__global__ void __launch_bounds__(256)
joint_softmax_kernel()
{
    size_t r = (size_t)blockIdx.x*8 + (threadIdx.x>>5);
    int lane = threadIdx.x & 31;
    float4* p = (float4*)(g_joint + r*128);
    float4 v = p[lane];
    float m = fmaxf(fmaxf(v.x,v.y),fmaxf(v.z,v.w));
    #pragma unroll
    for (int o=16;o;o>>=1) m = fmaxf(m, __shfl_xor_sync(0xffffffffu,m,o));
    v.x = __expf(v.x-m); v.y = __expf(v.y-m);
    v.z = __expf(v.z-m); v.w = __expf(v.w-m);
    float s = v.x+v.y+v.z+v.w;
    #pragma unroll
    for (int o=16;o;o>>=1) s += __shfl_xor_sync(0xffffffffu,s,o);
    float inv = 1.f/s;
    v.x*=inv; v.y*=inv; v.z*=inv; v.w*=inv;
    p[lane] = v;
}

// ---------------------------------------------------------------------------
// local_merged per (h, seg, b): merged = latt @ v   (writes merged)
// ---------------------------------------------------------------------------
__global__ void __launch_bounds__(256)
local_merged_kernel()
{
    __shared__ float ps[64][65];
    __shared__ float vs[64][65];
    int h = blockIdx.x, seg = blockIdx.y, b = blockIdx.z;
    int tid = threadIdx.x;
    size_t tok0 = ((size_t)b*NSn + seg)*SEGn;
    for (int i=tid;i<64*64;i+=256){
        int r=i>>6,c=i&63;
        ps[r][c] = g_joint[((tok0+r)*Hn+h)*128 + c];
        vs[r][c] = g_v[(tok0+r)*Dn + h*HDn + c];
    }
    __syncthreads();
    int row=tid>>2, quad=tid&3;
    float o[16];
    #pragma unroll
    for (int dd=0;dd<16;dd++) o[dd]=0.f;
    for (int c=0;c<64;c++){
        float pv = ps[row][c];
        #pragma unroll
        for (int dd=0;dd<16;dd++) o[dd]+=pv*vs[c][quad*16+dd];
    }
    size_t ob=(tok0+row)*Dn + h*HDn + quad*16;
    #pragma unroll
    for (int dd=0;dd<16;dd++) g_merged[ob+dd]=o[dd];
}

// ---------------------------------------------------------------------------
// global_merged per (h, l, b): merged += gatt @ row_attn (over segments)
// ---------------------------------------------------------------------------
__global__ void __launch_bounds__(256)
global_merged_kernel()
{
    __shared__ float ga[64][65];
    __shared__ float ra[64][65];
    int h = blockIdx.x, l = blockIdx.y, b = blockIdx.z;
    int tid = threadIdx.x;
    for (int i=tid;i<64*64;i+=256){
        int r=i>>6,c=i&63;
        size_t t = ((size_t)b*NSn + r)*SEGn + l;
        ga[r][c] = g_joint[(t*Hn+h)*128 + 64 + c];
        ra[r][c] = g_rowattn[t*Dn + h*HDn + c];
    }
    __syncthreads();
    int row=tid>>2, quad=tid&3;
    float o[16];
    #pragma unroll
    for (int dd=0;dd<16;dd++) o[dd]=0.f;
    for (int c=0;c<64;c++){
        float gv = ga[row][c];
        #pragma unroll
        for (int dd=0;dd<16;dd++) o[dd]+=gv*ra[c][quad*16+dd];
    }
    size_t t  = ((size_t)b*NSn + row)*SEGn + l;
    size_t ob = t*Dn + h*HDn + quad*16;
    #pragma unroll
    for (int dd=0;dd<16;dd++) g_merged[ob+dd] += o[dd];
}

// ---------------------------------------------------------------------------
// Launch
// ---------------------------------------------------------------------------
extern "C" void kernel_launch(void* const* d_in, const int* in_sizes, int n_in,
                              void* d_out, int out_size)
{
    const float* x    = (const float*)d_in[0];
    const float* Wq   = (const float*)d_in[1];
    const float* Wk   = (const float*)d_in[2];
    const float* Wv   = (const float*)d_in[3];
    const float* Wro  = (const float*)d_in[4];
    const float* lns  = (const float*)d_in[5];
    const float* lnb  = (const float*)d_in[6];
    const float* Wk2  = (const float*)d_in[7];
    const float* Wout = (const float*)d_in[8];
    float* out = (float*)d_out;

    const int LA_SMEM = 3*64*65*4;   // 49,920 B > 48 KB static limit
    cudaFuncSetAttribute(local_attn_kernel,
                         cudaFuncAttributeMaxDynamicSharedMemorySize, LA_SMEM);

    dim3 gg(8, 128);            // GEMM grid: 1024/128 cols x 16384/128 rows
    dim3 ga(Hn, NSn, Bn);       // per (h, seg, b)
    dim3 gl(Hn, SEGn, Bn);      // per (h, l, b)

    // Projections
    sgemm_kernel<<<gg,256>>>(x,0, Wq, nullptr,1, nullptr, 0.125f);  // q * 1/sqrt(64)
    sgemm_kernel<<<gg,256>>>(x,0, Wk, nullptr,2, nullptr, 1.f);
    sgemm_kernel<<<gg,256>>>(x,0, Wv, nullptr,3, nullptr, 1.f);

    // Local attention (logits -> joint, row_attn)
    local_attn_kernel<<<ga,256,LA_SMEM>>>();

    // key_row = row_attn @ Wrow_out + x ; LN ; @ Wk2
    sgemm_kernel<<<gg,256>>>(nullptr,1, Wro, nullptr,4, x, 1.f);
    ln_kernel<<<NTOK,256>>>(lns, lnb);
    sgemm_kernel<<<gg,256>>>(nullptr,2, Wk2, nullptr,5, nullptr, 1.f);

    // Global logits, joint softmax, merges
    global_logits_kernel<<<gl,256>>>();
    joint_softmax_kernel<<<(NTOK*Hn)/8,256>>>();
    local_merged_kernel<<<ga,256>>>();
    global_merged_kernel<<<gl,256>>>();

    // Output projection
    sgemm_kernel<<<gg,256>>>(nullptr,3, Wout, out,0, nullptr, 1.f);
}

// round 5
// speedup vs baseline: 1.6986x; 1.6986x over previous
#include <cuda_runtime.h>
#include <cuda_bf16.h>
#include <math.h>
#include <stdint.h>

// Problem constants
#define Bn   4
#define Sn   4096
#define Dn   1024
#define Hn   16
#define HDn  64
#define SEGn 64
#define NSn  64
#define NTOK (Bn*Sn)          // 16384
#define NEGV (-1.0e10f)

// ---------------------------------------------------------------------------
// Scratch (device globals)
// ---------------------------------------------------------------------------
__device__ float g_q      [(size_t)NTOK*Dn];
__device__ float g_k      [(size_t)NTOK*Dn];
__device__ float g_v      [(size_t)NTOK*Dn];
__device__ float g_rowattn[(size_t)NTOK*Dn];
__device__ float g_t1     [(size_t)NTOK*Dn];
__device__ float g_t2     [(size_t)NTOK*Dn];
__device__ float g_krow   [(size_t)NTOK*Dn];
__device__ float g_merged [(size_t)NTOK*Dn];
__device__ float g_joint  [(size_t)NTOK*Hn*128];

// Split-bf16 staging
__device__ __nv_bfloat16 g_ahi [(size_t)NTOK*Dn];
__device__ __nv_bfloat16 g_alo [(size_t)NTOK*Dn];
__device__ __nv_bfloat16 g_wthi[(size_t)6*Dn*Dn];   // WT[w][n][k] = W[w][k][n]
__device__ __nv_bfloat16 g_wtlo[(size_t)6*Dn*Dn];

__device__ __forceinline__ const float* apick(const float* ext, int id){
    switch(id){ case 1: return g_rowattn; case 2: return g_t2; case 3: return g_merged; }
    return ext;
}
__device__ __forceinline__ float* cpick(float* ext, int id){
    switch(id){ case 1: return g_q; case 2: return g_k; case 3: return g_v;
                case 4: return g_t1; case 5: return g_krow; }
    return ext;
}

__device__ __forceinline__ uint32_t smem_u32(const void* p){
    uint32_t a;
    asm("{ .reg .u64 t; cvta.to.shared.u64 t, %1; cvt.u32.u64 %0, t; }" : "=r"(a) : "l"(p));
    return a;
}
__device__ __forceinline__ void cp_async16(uint32_t dst, const void* src){
    asm volatile("cp.async.cg.shared.global [%0], [%1], 16;" :: "r"(dst), "l"(src) : "memory");
}
__device__ __forceinline__ void cp_commit(){
    asm volatile("cp.async.commit_group;" ::: "memory");
}
template<int N> __device__ __forceinline__ void cp_wait(){
    asm volatile("cp.async.wait_group %0;" :: "n"(N) : "memory");
}
__device__ __forceinline__ void mma16816(float* c, const uint32_t* a, const uint32_t* b){
    asm volatile("mma.sync.aligned.m16n8k16.row.col.f32.bf16.bf16.f32 "
                 "{%0,%1,%2,%3}, {%4,%5,%6,%7}, {%8,%9}, {%0,%1,%2,%3};"
                 : "+f"(c[0]), "+f"(c[1]), "+f"(c[2]), "+f"(c[3])
                 : "r"(a[0]), "r"(a[1]), "r"(a[2]), "r"(a[3]), "r"(b[0]), "r"(b[1]));
}

// ---------------------------------------------------------------------------
// Split conversion: activations fp32 -> (hi,lo) bf16
// ---------------------------------------------------------------------------
__global__ void __launch_bounds__(256)
convert_act(const float* __restrict__ ext, int id)
{
    const float* src = apick(ext, id);
    size_t i = (size_t)blockIdx.x*256 + threadIdx.x;
    float4 v = ((const float4*)src)[i];
    __nv_bfloat16 hx = __float2bfloat16_rn(v.x);
    __nv_bfloat16 hy = __float2bfloat16_rn(v.y);
    __nv_bfloat16 hz = __float2bfloat16_rn(v.z);
    __nv_bfloat16 hw = __float2bfloat16_rn(v.w);
    __nv_bfloat16 lx = __float2bfloat16_rn(v.x - __bfloat162float(hx));
    __nv_bfloat16 ly = __float2bfloat16_rn(v.y - __bfloat162float(hy));
    __nv_bfloat16 lz = __float2bfloat16_rn(v.z - __bfloat162float(hz));
    __nv_bfloat16 lw = __float2bfloat16_rn(v.w - __bfloat162float(hw));
    __nv_bfloat162 h0(hx,hy), h1(hz,hw), l0(lx,ly), l1(lz,lw);
    uint2 hv, lv;
    hv.x = *(uint32_t*)&h0; hv.y = *(uint32_t*)&h1;
    lv.x = *(uint32_t*)&l0; lv.y = *(uint32_t*)&l1;
    ((uint2*)g_ahi)[i] = hv;
    ((uint2*)g_alo)[i] = lv;
}

// ---------------------------------------------------------------------------
// Weight transpose+split: WT[w][n][k] = split(W[w][k][n])
// ---------------------------------------------------------------------------
__global__ void __launch_bounds__(256)
convert_wt(const float* __restrict__ W0, const float* __restrict__ W1,
           const float* __restrict__ W2, const float* __restrict__ W3,
           const float* __restrict__ W4, const float* __restrict__ W5)
{
    const float* Ws[6] = {W0,W1,W2,W3,W4,W5};
    const float* W = Ws[blockIdx.z];
    __shared__ float tile[32][33];
    int n0 = blockIdx.x*32, k0 = blockIdx.y*32;
    int tx = threadIdx.x & 31, ty = threadIdx.x >> 5;
    #pragma unroll
    for (int j = 0; j < 4; j++){
        int r = ty + j*8;
        tile[r][tx] = W[(size_t)(k0+r)*Dn + n0 + tx];
    }
    __syncthreads();
    size_t wbase = (size_t)blockIdx.z*Dn*Dn;
    #pragma unroll
    for (int j = 0; j < 4; j++){
        int r = ty + j*8;
        float a = tile[tx][r];
        __nv_bfloat16 hi = __float2bfloat16_rn(a);
        __nv_bfloat16 lo = __float2bfloat16_rn(a - __bfloat162float(hi));
        size_t o = wbase + (size_t)(n0+r)*Dn + k0 + tx;
        g_wthi[o] = hi;
        g_wtlo[o] = lo;
    }
}

// ---------------------------------------------------------------------------
// HMMA GEMM: C[16384,1024] = alpha * A @ W[widx] (+R)
// Split-bf16, 3 mma products. Tile 128x128, BK=64, double-buffered cp.async.
// smem per buffer: 4 matrices x [128][72] bf16 = 73728 B; two buffers.
// ---------------------------------------------------------------------------
#define AST  72
#define TSZB (128*AST*2)          // 18432 B per matrix
#define BUFB (4*TSZB)             // 73728 B per buffer
#define HG_SMEM (2*BUFB)          // 147456 B

__global__ void __launch_bounds__(256)
hmma_gemm(int widx, float* Cext, int Cid, const float* __restrict__ R, float alpha)
{
    extern __shared__ char smem[];
    uint32_t sb = smem_u32(smem);
    int tid = threadIdx.x, lane = tid & 31, wid = tid >> 5;
    int wm = wid & 1, wn = wid >> 1;           // 2 x 4 warp grid
    int m0 = blockIdx.y*128, n0 = blockIdx.x*128;
    float* C = cpick(Cext, Cid);

    const __nv_bfloat16* srcs[4];
    srcs[0] = g_ahi  + (size_t)m0*Dn;
    srcs[1] = g_alo  + (size_t)m0*Dn;
    srcs[2] = g_wthi + (size_t)widx*Dn*Dn + (size_t)n0*Dn;
    srcs[3] = g_wtlo + (size_t)widx*Dn*Dn + (size_t)n0*Dn;

    // fill chunk c into buffer `buf`
    auto fill = [&](int c, int buf){
        int k0 = c*64;
        uint32_t base = sb + buf*BUFB;
        #pragma unroll
        for (int t = 0; t < 4; t++){
            #pragma unroll
            for (int it = 0; it < 4; it++){
                int idx = it*256 + tid;
                int r = idx >> 3, cc = idx & 7;
                cp_async16(base + t*TSZB + r*(AST*2) + cc*16,
                           srcs[t] + (size_t)r*Dn + k0 + cc*8);
            }
        }
        cp_commit();
    };

    float acc[4][4][4];
    #pragma unroll
    for (int i=0;i<4;i++)
        #pragma unroll
        for (int j=0;j<4;j++)
            #pragma unroll
            for (int q=0;q<4;q++) acc[i][j][q]=0.f;

    fill(0, 0);

    for (int c = 0; c < 16; c++){
        int buf = c & 1;
        if (c < 15){ fill(c+1, buf^1); cp_wait<1>(); }
        else       { cp_wait<0>(); }
        __syncthreads();

        const __nv_bfloat16* Ah = (const __nv_bfloat16*)(smem + buf*BUFB);
        const __nv_bfloat16* Al = (const __nv_bfloat16*)(smem + buf*BUFB + TSZB);
        const __nv_bfloat16* Bh = (const __nv_bfloat16*)(smem + buf*BUFB + 2*TSZB);
        const __nv_bfloat16* Bl = (const __nv_bfloat16*)(smem + buf*BUFB + 3*TSZB);

        #pragma unroll
        for (int ks = 0; ks < 4; ks++){
            int k16 = ks*16;
            uint32_t ah[4][4], al[4][4], bh[4][2], bl[4][2];
            #pragma unroll
            for (int i = 0; i < 4; i++){
                int row = wm*64 + i*16 + (lane>>2);
                int off = row*AST + k16 + 2*(lane&3);
                ah[i][0] = *(const uint32_t*)(Ah + off);
                ah[i][1] = *(const uint32_t*)(Ah + off + 8*AST);
                ah[i][2] = *(const uint32_t*)(Ah + off + 8);
                ah[i][3] = *(const uint32_t*)(Ah + off + 8*AST + 8);
                al[i][0] = *(const uint32_t*)(Al + off);
                al[i][1] = *(const uint32_t*)(Al + off + 8*AST);
                al[i][2] = *(const uint32_t*)(Al + off + 8);
                al[i][3] = *(const uint32_t*)(Al + off + 8*AST + 8);
            }
            #pragma unroll
            for (int j = 0; j < 4; j++){
                int nrow = wn*32 + j*8 + (lane>>2);
                int off = nrow*AST + k16 + 2*(lane&3);
                bh[j][0] = *(const uint32_t*)(Bh + off);
                bh[j][1] = *(const uint32_t*)(Bh + off + 8);
                bl[j][0] = *(const uint32_t*)(Bl + off);
                bl[j][1] = *(const uint32_t*)(Bl + off + 8);
            }
            #pragma unroll
            for (int i = 0; i < 4; i++)
                #pragma unroll
                for (int j = 0; j < 4; j++){
                    mma16816(acc[i][j], ah[i], bh[j]);
                    mma16816(acc[i][j], ah[i], bl[j]);
                    mma16816(acc[i][j], al[i], bh[j]);
                }
        }
        __syncthreads();
    }

    // Epilogue
    #pragma unroll
    for (int i = 0; i < 4; i++){
        int row = m0 + wm*64 + i*16 + (lane>>2);
        #pragma unroll
        for (int j = 0; j < 4; j++){
            int col = n0 + wn*32 + j*8 + 2*(lane&3);
            size_t o0 = (size_t)row*Dn + col;
            size_t o1 = (size_t)(row+8)*Dn + col;
            float2 v0, v1;
            v0.x = alpha*acc[i][j][0]; v0.y = alpha*acc[i][j][1];
            v1.x = alpha*acc[i][j][2]; v1.y = alpha*acc[i][j][3];
            if (R){
                float2 r0 = *(const float2*)(R + o0);
                float2 r1 = *(const float2*)(R + o1);
                v0.x += r0.x; v0.y += r0.y; v1.x += r1.x; v1.y += r1.y;
            }
            *(float2*)(C + o0) = v0;
            *(float2*)(C + o1) = v1;
        }
    }
}

// ---------------------------------------------------------------------------
// Local attention per (h, seg, b)
// ---------------------------------------------------------------------------
__global__ void __launch_bounds__(256)
local_attn_kernel()
{
    extern __shared__ float sm[];
    float* qs = sm;
    float* ks = sm + 64*65;
    float* vs = sm + 2*64*65;

    int h = blockIdx.x, seg = blockIdx.y, b = blockIdx.z;
    int tid = threadIdx.x;
    size_t tok0 = ((size_t)b*NSn + seg)*SEGn;

    for (int i = tid; i < 64*64; i += 256) {
        int r = i >> 6, c = i & 63;
        size_t off = (tok0 + r)*Dn + h*HDn + c;
        qs[r*65+c] = g_q[off];
        ks[r*65+c] = g_k[off];
        vs[r*65+c] = g_v[off];
    }
    __syncthreads();

    int row = tid >> 2, quad = tid & 3;
    float lg[16];
    #pragma unroll
    for (int c=0;c<16;c++) lg[c]=0.f;
    for (int d = 0; d < 64; d++) {
        float qd = qs[row*65+d];
        #pragma unroll
        for (int c=0;c<16;c++) lg[c] += qd * ks[(quad*16+c)*65 + d];
    }

    size_t jb = ((tok0 + row)*Hn + h)*128;
    #pragma unroll
    for (int c=0;c<16;c++) {
        int col = quad*16+c;
        g_joint[jb + col] = lg[c] + (row < col ? NEGV : 0.f);
    }

    float m = -1e30f;
    #pragma unroll
    for (int c=0;c<16;c++) m = fmaxf(m, lg[c]);
    m = fmaxf(m, __shfl_xor_sync(0xffffffffu, m, 1));
    m = fmaxf(m, __shfl_xor_sync(0xffffffffu, m, 2));
    float ssum = 0.f;
    #pragma unroll
    for (int c=0;c<16;c++){ lg[c] = __expf(lg[c]-m); ssum += lg[c]; }
    ssum += __shfl_xor_sync(0xffffffffu, ssum, 1);
    ssum += __shfl_xor_sync(0xffffffffu, ssum, 2);
    float inv = 1.f/ssum;

    __syncthreads();
    #pragma unroll
    for (int c=0;c<16;c++) ks[row*65 + quad*16 + c] = lg[c];
    __syncthreads();

    float o[16];
    #pragma unroll
    for (int dd=0;dd<16;dd++) o[dd]=0.f;
    for (int c2=0;c2<64;c2++){
        float p = ks[row*65+c2];
        #pragma unroll
        for (int dd=0;dd<16;dd++) o[dd] += p * vs[c2*65 + quad*16 + dd];
    }
    size_t ob = (tok0+row)*Dn + h*HDn + quad*16;
    #pragma unroll
    for (int dd=0;dd<16;dd++) g_rowattn[ob+dd] = o[dd]*inv;
}

// ---------------------------------------------------------------------------
// LayerNorm over D=1024 per token
// ---------------------------------------------------------------------------
__global__ void __launch_bounds__(256)
ln_kernel(const float* __restrict__ scale, const float* __restrict__ bias)
{
    size_t row = blockIdx.x;
    int tid = threadIdx.x;
    float4 v = ((const float4*)(g_t1 + row*Dn))[tid];
    float s  = v.x+v.y+v.z+v.w;
    float ss = v.x*v.x+v.y*v.y+v.z*v.z+v.w*v.w;
    #pragma unroll
    for (int o=16;o;o>>=1){
        s  += __shfl_xor_sync(0xffffffffu, s, o);
        ss += __shfl_xor_sync(0xffffffffu, ss, o);
    }
    __shared__ float sh[16];
    int w = tid>>5, lane = tid&31;
    if (lane==0){ sh[w]=s; sh[8+w]=ss; }
    __syncthreads();
    if (tid==0){
        float a=0.f,b2=0.f;
        #pragma unroll
        for (int i=0;i<8;i++){ a+=sh[i]; b2+=sh[8+i]; }
        float mu  = a*(1.f/Dn);
        float var = b2*(1.f/Dn) - mu*mu;
        sh[0]=mu; sh[1]=rsqrtf(var + 1e-6f);
    }
    __syncthreads();
    float mu = sh[0], rstd = sh[1];
    float4 sc = ((const float4*)scale)[tid];
    float4 bi = ((const float4*)bias)[tid];
    float4 o4;
    o4.x=(v.x-mu)*rstd*sc.x+bi.x;
    o4.y=(v.y-mu)*rstd*sc.y+bi.y;
    o4.z=(v.z-mu)*rstd*sc.z+bi.z;
    o4.w=(v.w-mu)*rstd*sc.w+bi.w;
    ((float4*)(g_t2 + row*Dn))[tid] = o4;
}

// ---------------------------------------------------------------------------
// Global logits per (h, l, b)
// ---------------------------------------------------------------------------
__global__ void __launch_bounds__(256)
global_logits_kernel()
{
    __shared__ float qg[64][65];
    __shared__ float kg[64][65];
    int h = blockIdx.x, l = blockIdx.y, b = blockIdx.z;
    int tid = threadIdx.x;
    for (int i = tid; i < 64*64; i += 256){
        int r = i>>6, c = i&63;
        size_t t = ((size_t)b*NSn + r)*SEGn + l;
        qg[r][c] = g_q   [t*Dn + h*HDn + c];
        kg[r][c] = g_krow[t*Dn + h*HDn + c];
    }
    __syncthreads();
    int row = tid>>2, quad = tid&3;
    float lg[16];
    #pragma unroll
    for (int c=0;c<16;c++) lg[c]=0.f;
    for (int d=0; d<64; d++){
        float qd = qg[row][d];
        #pragma unroll
        for (int c=0;c<16;c++) lg[c] += qd * kg[quad*16+c][d];
    }
    size_t t  = ((size_t)b*NSn + row)*SEGn + l;
    size_t jb = (t*Hn + h)*128 + 64;
    #pragma unroll
    for (int c=0;c<16;c++){
        int col = quad*16+c;
        g_joint[jb + col] = lg[c] + (row <= col ? NEGV : 0.f);
    }
}

// ---------------------------------------------------------------------------
// Joint softmax over 128-wide rows of g_joint
// ---------------------------------------------------------------------------
__global__ void __launch_bounds__(256)
joint_softmax_kernel()
{
    size_t r = (size_t)blockIdx.x*8 + (threadIdx.x>>5);
    int lane = threadIdx.x & 31;
    float4* p = (float4*)(g_joint + r*128);
    float4 v = p[lane];
    float m = fmaxf(fmaxf(v.x,v.y),fmaxf(v.z,v.w));
    #pragma unroll
    for (int o=16;o;o>>=1) m = fmaxf(m, __shfl_xor_sync(0xffffffffu,m,o));
    v.x = __expf(v.x-m); v.y = __expf(v.y-m);
    v.z = __expf(v.z-m); v.w = __expf(v.w-m);
    float s = v.x+v.y+v.z+v.w;
    #pragma unroll
    for (int o=16;o;o>>=1) s += __shfl_xor_sync(0xffffffffu,s,o);
    float inv = 1.f/s;
    v.x*=inv; v.y*=inv; v.z*=inv; v.w*=inv;
    p[lane] = v;
}

// ---------------------------------------------------------------------------
// local_merged per (h, seg, b)
// ---------------------------------------------------------------------------
__global__ void __launch_bounds__(256)
local_merged_kernel()
{
    __shared__ float ps[64][65];
    __shared__ float vs[64][65];
    int h = blockIdx.x, seg = blockIdx.y, b = blockIdx.z;
    int tid = threadIdx.x;
    size_t tok0 = ((size_t)b*NSn + seg)*SEGn;
    for (int i=tid;i<64*64;i+=256){
        int r=i>>6,c=i&63;
        ps[r][c] = g_joint[((tok0+r)*Hn+h)*128 + c];
        vs[r][c] = g_v[(tok0+r)*Dn + h*HDn + c];
    }
    __syncthreads();
    int row=tid>>2, quad=tid&3;
    float o[16];
    #pragma unroll
    for (int dd=0;dd<16;dd++) o[dd]=0.f;
    for (int c=0;c<64;c++){
        float pv = ps[row][c];
        #pragma unroll
        for (int dd=0;dd<16;dd++) o[dd]+=pv*vs[c][quad*16+dd];
    }
    size_t ob=(tok0+row)*Dn + h*HDn + quad*16;
    #pragma unroll
    for (int dd=0;dd<16;dd++) g_merged[ob+dd]=o[dd];
}

// ---------------------------------------------------------------------------
// global_merged per (h, l, b)
// ---------------------------------------------------------------------------
__global__ void __launch_bounds__(256)
global_merged_kernel()
{
    __shared__ float ga[64][65];
    __shared__ float ra[64][65];
    int h = blockIdx.x, l = blockIdx.y, b = blockIdx.z;
    int tid = threadIdx.x;
    for (int i=tid;i<64*64;i+=256){
        int r=i>>6,c=i&63;
        size_t t = ((size_t)b*NSn + r)*SEGn + l;
        ga[r][c] = g_joint[(t*Hn+h)*128 + 64 + c];
        ra[r][c] = g_rowattn[t*Dn + h*HDn + c];
    }
    __syncthreads();
    int row=tid>>2, quad=tid&3;
    float o[16];
    #pragma unroll
    for (int dd=0;dd<16;dd++) o[dd]=0.f;
    for (int c=0;c<64;c++){
        float gv = ga[row][c];
        #pragma unroll
        for (int dd=0;dd<16;dd++) o[dd]+=gv*ra[c][quad*16+dd];
    }
    size_t t  = ((size_t)b*NSn + row)*SEGn + l;
    size_t ob = t*Dn + h*HDn + quad*16;
    #pragma unroll
    for (int dd=0;dd<16;dd++) g_merged[ob+dd] += o[dd];
}

// ---------------------------------------------------------------------------
// Launch
// ---------------------------------------------------------------------------
extern "C" void kernel_launch(void* const* d_in, const int* in_sizes, int n_in,
                              void* d_out, int out_size)
{
    const float* x    = (const float*)d_in[0];
    const float* Wq   = (const float*)d_in[1];
    const float* Wk   = (const float*)d_in[2];
    const float* Wv   = (const float*)d_in[3];
    const float* Wro  = (const float*)d_in[4];
    const float* lns  = (const float*)d_in[5];
    const float* lnb  = (const float*)d_in[6];
    const float* Wk2  = (const float*)d_in[7];
    const float* Wout = (const float*)d_in[8];
    float* out = (float*)d_out;

    const int LA_SMEM = 3*64*65*4;
    cudaFuncSetAttribute(local_attn_kernel,
                         cudaFuncAttributeMaxDynamicSharedMemorySize, LA_SMEM);
    cudaFuncSetAttribute(hmma_gemm,
                         cudaFuncAttributeMaxDynamicSharedMemorySize, HG_SMEM);

    dim3 gg(8, 128);
    dim3 ga(Hn, NSn, Bn);
    dim3 gl(Hn, SEGn, Bn);
    const int ACT_BLKS = (NTOK*Dn/4)/256;

    convert_wt<<<dim3(32,32,6),256>>>(Wq, Wk, Wv, Wro, Wk2, Wout);

    convert_act<<<ACT_BLKS,256>>>(x, 0);
    hmma_gemm<<<gg,256,HG_SMEM>>>(0, nullptr,1, nullptr, 0.125f);   // q
    hmma_gemm<<<gg,256,HG_SMEM>>>(1, nullptr,2, nullptr, 1.f);      // k
    hmma_gemm<<<gg,256,HG_SMEM>>>(2, nullptr,3, nullptr, 1.f);      // v

    local_attn_kernel<<<ga,256,LA_SMEM>>>();

    convert_act<<<ACT_BLKS,256>>>(nullptr, 1);                      // rowattn
    hmma_gemm<<<gg,256,HG_SMEM>>>(3, nullptr,4, x, 1.f);            // t1
    ln_kernel<<<NTOK,256>>>(lns, lnb);
    convert_act<<<ACT_BLKS,256>>>(nullptr, 2);                      // t2
    hmma_gemm<<<gg,256,HG_SMEM>>>(4, nullptr,5, nullptr, 1.f);      // krow

    global_logits_kernel<<<gl,256>>>();
    joint_softmax_kernel<<<(NTOK*Hn)/8,256>>>();
    local_merged_kernel<<<ga,256>>>();
    global_merged_kernel<<<gl,256>>>();

    convert_act<<<ACT_BLKS,256>>>(nullptr, 3);                      // merged
    hmma_gemm<<<gg,256,HG_SMEM>>>(5, out,0, nullptr, 1.f);
}

// round 6
// speedup vs baseline: 1.7044x; 1.0034x over previous
#include <cuda_runtime.h>
#include <cuda_bf16.h>
#include <math.h>
#include <stdint.h>

// Problem constants
#define Bn   4
#define Sn   4096
#define Dn   1024
#define Hn   16
#define HDn  64
#define SEGn 64
#define NSn  64
#define NTOK (Bn*Sn)          // 16384
#define NEGV (-1.0e10f)

// ---------------------------------------------------------------------------
// Scratch (device globals)
// ---------------------------------------------------------------------------
__device__ float g_q      [(size_t)NTOK*Dn];
__device__ float g_k      [(size_t)NTOK*Dn];
__device__ float g_v      [(size_t)NTOK*Dn];
__device__ float g_rowattn[(size_t)NTOK*Dn];
__device__ float g_t1     [(size_t)NTOK*Dn];
__device__ float g_t2     [(size_t)NTOK*Dn];
__device__ float g_krow   [(size_t)NTOK*Dn];
__device__ float g_merged [(size_t)NTOK*Dn];
__device__ float g_joint  [(size_t)NTOK*Hn*128];

// Split-bf16 staging
__device__ __nv_bfloat16 g_ahi [(size_t)NTOK*Dn];
__device__ __nv_bfloat16 g_alo [(size_t)NTOK*Dn];
__device__ __nv_bfloat16 g_wthi[(size_t)6*Dn*Dn];   // WT[w][n][k] = W[w][k][n]
__device__ __nv_bfloat16 g_wtlo[(size_t)6*Dn*Dn];

__device__ __forceinline__ const float* apick(const float* ext, int id){
    switch(id){ case 1: return g_rowattn; case 2: return g_t2; case 3: return g_merged; }
    return ext;
}
__device__ __forceinline__ float* cpick(float* ext, int id){
    switch(id){ case 1: return g_q; case 2: return g_k; case 3: return g_v;
                case 4: return g_t1; case 5: return g_krow; }
    return ext;
}

__device__ __forceinline__ uint32_t smem_u32(const void* p){
    uint32_t a;
    asm("{ .reg .u64 t; cvta.to.shared.u64 t, %1; cvt.u32.u64 %0, t; }" : "=r"(a) : "l"(p));
    return a;
}
__device__ __forceinline__ void cp_async16(uint32_t dst, const void* src){
    asm volatile("cp.async.cg.shared.global [%0], [%1], 16;" :: "r"(dst), "l"(src) : "memory");
}
__device__ __forceinline__ void cp_commit(){
    asm volatile("cp.async.commit_group;" ::: "memory");
}
template<int N> __device__ __forceinline__ void cp_wait(){
    asm volatile("cp.async.wait_group %0;" :: "n"(N) : "memory");
}
__device__ __forceinline__ void mma16816(float* c, const uint32_t* a, const uint32_t* b){
    asm volatile("mma.sync.aligned.m16n8k16.row.col.f32.bf16.bf16.f32 "
                 "{%0,%1,%2,%3}, {%4,%5,%6,%7}, {%8,%9}, {%0,%1,%2,%3};"
                 : "+f"(c[0]), "+f"(c[1]), "+f"(c[2]), "+f"(c[3])
                 : "r"(a[0]), "r"(a[1]), "r"(a[2]), "r"(a[3]), "r"(b[0]), "r"(b[1]));
}

// ---------------------------------------------------------------------------
// Split conversion: activations fp32 -> (hi,lo) bf16
// ---------------------------------------------------------------------------
__global__ void __launch_bounds__(256)
convert_act(const float* __restrict__ ext, int id)
{
    const float* src = apick(ext, id);
    size_t i = (size_t)blockIdx.x*256 + threadIdx.x;
    float4 v = ((const float4*)src)[i];
    __nv_bfloat16 hx = __float2bfloat16_rn(v.x);
    __nv_bfloat16 hy = __float2bfloat16_rn(v.y);
    __nv_bfloat16 hz = __float2bfloat16_rn(v.z);
    __nv_bfloat16 hw = __float2bfloat16_rn(v.w);
    __nv_bfloat16 lx = __float2bfloat16_rn(v.x - __bfloat162float(hx));
    __nv_bfloat16 ly = __float2bfloat16_rn(v.y - __bfloat162float(hy));
    __nv_bfloat16 lz = __float2bfloat16_rn(v.z - __bfloat162float(hz));
    __nv_bfloat16 lw = __float2bfloat16_rn(v.w - __bfloat162float(hw));
    __nv_bfloat162 h0(hx,hy), h1(hz,hw), l0(lx,ly), l1(lz,lw);
    uint2 hv, lv;
    hv.x = *(uint32_t*)&h0; hv.y = *(uint32_t*)&h1;
    lv.x = *(uint32_t*)&l0; lv.y = *(uint32_t*)&l1;
    ((uint2*)g_ahi)[i] = hv;
    ((uint2*)g_alo)[i] = lv;
}

// ---------------------------------------------------------------------------
// Weight transpose+split: WT[w][n][k] = split(W[w][k][n])
// ---------------------------------------------------------------------------
__global__ void __launch_bounds__(256)
convert_wt(const float* __restrict__ W0, const float* __restrict__ W1,
           const float* __restrict__ W2, const float* __restrict__ W3,
           const float* __restrict__ W4, const float* __restrict__ W5)
{
    const float* Ws[6] = {W0,W1,W2,W3,W4,W5};
    const float* W = Ws[blockIdx.z];
    __shared__ float tile[32][33];
    int n0 = blockIdx.x*32, k0 = blockIdx.y*32;
    int tx = threadIdx.x & 31, ty = threadIdx.x >> 5;
    #pragma unroll
    for (int j = 0; j < 4; j++){
        int r = ty + j*8;
        tile[r][tx] = W[(size_t)(k0+r)*Dn + n0 + tx];
    }
    __syncthreads();
    size_t wbase = (size_t)blockIdx.z*Dn*Dn;
    #pragma unroll
    for (int j = 0; j < 4; j++){
        int r = ty + j*8;
        float a = tile[tx][r];
        __nv_bfloat16 hi = __float2bfloat16_rn(a);
        __nv_bfloat16 lo = __float2bfloat16_rn(a - __bfloat162float(hi));
        size_t o = wbase + (size_t)(n0+r)*Dn + k0 + tx;
        g_wthi[o] = hi;
        g_wtlo[o] = lo;
    }
}

// ---------------------------------------------------------------------------
// HMMA GEMM: C[16384,1024] = alpha * A @ W[widx] (+R)
// Split-bf16, 3 mma products. Tile 128x128, BK=64, double-buffered cp.async.
// smem per buffer: 4 matrices x [128][72] bf16 = 73728 B; two buffers.
// ---------------------------------------------------------------------------
#define AST  72
#define TSZB (128*AST*2)          // 18432 B per matrix
#define BUFB (4*TSZB)             // 73728 B per buffer
#define HG_SMEM (2*BUFB)          // 147456 B

__global__ void __launch_bounds__(256)
hmma_gemm(int widx, float* Cext, int Cid, const float* __restrict__ R, float alpha)
{
    extern __shared__ char smem[];
    uint32_t sb = smem_u32(smem);
    int tid = threadIdx.x, lane = tid & 31, wid = tid >> 5;
    int wm = wid & 1, wn = wid >> 1;           // 2 x 4 warp grid
    int m0 = blockIdx.y*128, n0 = blockIdx.x*128;
    float* C = cpick(Cext, Cid);

    const __nv_bfloat16* srcs[4];
    srcs[0] = g_ahi  + (size_t)m0*Dn;
    srcs[1] = g_alo  + (size_t)m0*Dn;
    srcs[2] = g_wthi + (size_t)widx*Dn*Dn + (size_t)n0*Dn;
    srcs[3] = g_wtlo + (size_t)widx*Dn*Dn + (size_t)n0*Dn;

    // fill chunk c into buffer `buf`
    auto fill = [&](int c, int buf){
        int k0 = c*64;
        uint32_t base = sb + buf*BUFB;
        #pragma unroll
        for (int t = 0; t < 4; t++){
            #pragma unroll
            for (int it = 0; it < 4; it++){
                int idx = it*256 + tid;
                int r = idx >> 3, cc = idx & 7;
                cp_async16(base + t*TSZB + r*(AST*2) + cc*16,
                           srcs[t] + (size_t)r*Dn + k0 + cc*8);
            }
        }
        cp_commit();
    };

    float acc[4][4][4];
    #pragma unroll
    for (int i=0;i<4;i++)
        #pragma unroll
        for (int j=0;j<4;j++)
            #pragma unroll
            for (int q=0;q<4;q++) acc[i][j][q]=0.f;

    fill(0, 0);

    for (int c = 0; c < 16; c++){
        int buf = c & 1;
        if (c < 15){ fill(c+1, buf^1); cp_wait<1>(); }
        else       { cp_wait<0>(); }
        __syncthreads();

        const __nv_bfloat16* Ah = (const __nv_bfloat16*)(smem + buf*BUFB);
        const __nv_bfloat16* Al = (const __nv_bfloat16*)(smem + buf*BUFB + TSZB);
        const __nv_bfloat16* Bh = (const __nv_bfloat16*)(smem + buf*BUFB + 2*TSZB);
        const __nv_bfloat16* Bl = (const __nv_bfloat16*)(smem + buf*BUFB + 3*TSZB);

        #pragma unroll
        for (int ks = 0; ks < 4; ks++){
            int k16 = ks*16;
            uint32_t ah[4][4], al[4][4], bh[4][2], bl[4][2];
            #pragma unroll
            for (int i = 0; i < 4; i++){
                int row = wm*64 + i*16 + (lane>>2);
                int off = row*AST + k16 + 2*(lane&3);
                ah[i][0] = *(const uint32_t*)(Ah + off);
                ah[i][1] = *(const uint32_t*)(Ah + off + 8*AST);
                ah[i][2] = *(const uint32_t*)(Ah + off + 8);
                ah[i][3] = *(const uint32_t*)(Ah + off + 8*AST + 8);
                al[i][0] = *(const uint32_t*)(Al + off);
                al[i][1] = *(const uint32_t*)(Al + off + 8*AST);
                al[i][2] = *(const uint32_t*)(Al + off + 8);
                al[i][3] = *(const uint32_t*)(Al + off + 8*AST + 8);
            }
            #pragma unroll
            for (int j = 0; j < 4; j++){
                int nrow = wn*32 + j*8 + (lane>>2);
                int off = nrow*AST + k16 + 2*(lane&3);
                bh[j][0] = *(const uint32_t*)(Bh + off);
                bh[j][1] = *(const uint32_t*)(Bh + off + 8);
                bl[j][0] = *(const uint32_t*)(Bl + off);
                bl[j][1] = *(const uint32_t*)(Bl + off + 8);
            }
            #pragma unroll
            for (int i = 0; i < 4; i++)
                #pragma unroll
                for (int j = 0; j < 4; j++){
                    mma16816(acc[i][j], ah[i], bh[j]);
                    mma16816(acc[i][j], ah[i], bl[j]);
                    mma16816(acc[i][j], al[i], bh[j]);
                }
        }
        __syncthreads();
    }

    // Epilogue
    #pragma unroll
    for (int i = 0; i < 4; i++){
        int row = m0 + wm*64 + i*16 + (lane>>2);
        #pragma unroll
        for (int j = 0; j < 4; j++){
            int col = n0 + wn*32 + j*8 + 2*(lane&3);
            size_t o0 = (size_t)row*Dn + col;
            size_t o1 = (size_t)(row+8)*Dn + col;
            float2 v0, v1;
            v0.x = alpha*acc[i][j][0]; v0.y = alpha*acc[i][j][1];
            v1.x = alpha*acc[i][j][2]; v1.y = alpha*acc[i][j][3];
            if (R){
                float2 r0 = *(const float2*)(R + o0);
                float2 r1 = *(const float2*)(R + o1);
                v0.x += r0.x; v0.y += r0.y; v1.x += r1.x; v1.y += r1.y;
            }
            *(float2*)(C + o0) = v0;
            *(float2*)(C + o1) = v1;
        }
    }
}

// ---------------------------------------------------------------------------
// Local attention per (h, seg, b)
// ---------------------------------------------------------------------------
__global__ void __launch_bounds__(256)
local_attn_kernel()
{
    extern __shared__ float sm[];
    float* qs = sm;
    float* ks = sm + 64*65;
    float* vs = sm + 2*64*65;

    int h = blockIdx.x, seg = blockIdx.y, b = blockIdx.z;
    int tid = threadIdx.x;
    size_t tok0 = ((size_t)b*NSn + seg)*SEGn;

    for (int i = tid; i < 64*64; i += 256) {
        int r = i >> 6, c = i & 63;
        size_t off = (tok0 + r)*Dn + h*HDn + c;
        qs[r*65+c] = g_q[off];
        ks[r*65+c] = g_k[off];
        vs[r*65+c] = g_v[off];
    }
    __syncthreads();

    int row = tid >> 2, quad = tid & 3;
    float lg[16];
    #pragma unroll
    for (int c=0;c<16;c++) lg[c]=0.f;
    for (int d = 0; d < 64; d++) {
        float qd = qs[row*65+d];
        #pragma unroll
        for (int c=0;c<16;c++) lg[c] += qd * ks[(quad*16+c)*65 + d];
    }

    size_t jb = ((tok0 + row)*Hn + h)*128;
    #pragma unroll
    for (int c=0;c<16;c++) {
        int col = quad*16+c;
        g_joint[jb + col] = lg[c] + (row < col ? NEGV : 0.f);
    }

    float m = -1e30f;
    #pragma unroll
    for (int c=0;c<16;c++) m = fmaxf(m, lg[c]);
    m = fmaxf(m, __shfl_xor_sync(0xffffffffu, m, 1));
    m = fmaxf(m, __shfl_xor_sync(0xffffffffu, m, 2));
    float ssum = 0.f;
    #pragma unroll
    for (int c=0;c<16;c++){ lg[c] = __expf(lg[c]-m); ssum += lg[c]; }
    ssum += __shfl_xor_sync(0xffffffffu, ssum, 1);
    ssum += __shfl_xor_sync(0xffffffffu, ssum, 2);
    float inv = 1.f/ssum;

    __syncthreads();
    #pragma unroll
    for (int c=0;c<16;c++) ks[row*65 + quad*16 + c] = lg[c];
    __syncthreads();

    float o[16];
    #pragma unroll
    for (int dd=0;dd<16;dd++) o[dd]=0.f;
    for (int c2=0;c2<64;c2++){
        float p = ks[row*65+c2];
        #pragma unroll
        for (int dd=0;dd<16;dd++) o[dd] += p * vs[c2*65 + quad*16 + dd];
    }
    size_t ob = (tok0+row)*Dn + h*HDn + quad*16;
    #pragma unroll
    for (int dd=0;dd<16;dd++) g_rowattn[ob+dd] = o[dd]*inv;
}

// ---------------------------------------------------------------------------
// LayerNorm over D=1024 per token
// ---------------------------------------------------------------------------
__global__ void __launch_bounds__(256)
ln_kernel(const float* __restrict__ scale, const float* __restrict__ bias)
{
    size_t row = blockIdx.x;
    int tid = threadIdx.x;
    float4 v = ((const float4*)(g_t1 + row*Dn))[tid];
    float s  = v.x+v.y+v.z+v.w;
    float ss = v.x*v.x+v.y*v.y+v.z*v.z+v.w*v.w;
    #pragma unroll
    for (int o=16;o;o>>=1){
        s  += __shfl_xor_sync(0xffffffffu, s, o);
        ss += __shfl_xor_sync(0xffffffffu, ss, o);
    }
    __shared__ float sh[16];
    int w = tid>>5, lane = tid&31;
    if (lane==0){ sh[w]=s; sh[8+w]=ss; }
    __syncthreads();
    if (tid==0){
        float a=0.f,b2=0.f;
        #pragma unroll
        for (int i=0;i<8;i++){ a+=sh[i]; b2+=sh[8+i]; }
        float mu  = a*(1.f/Dn);
        float var = b2*(1.f/Dn) - mu*mu;
        sh[0]=mu; sh[1]=rsqrtf(var + 1e-6f);
    }
    __syncthreads();
    float mu = sh[0], rstd = sh[1];
    float4 sc = ((const float4*)scale)[tid];
    float4 bi = ((const float4*)bias)[tid];
    float4 o4;
    o4.x=(v.x-mu)*rstd*sc.x+bi.x;
    o4.y=(v.y-mu)*rstd*sc.y+bi.y;
    o4.z=(v.z-mu)*rstd*sc.z+bi.z;
    o4.w=(v.w-mu)*rstd*sc.w+bi.w;
    ((float4*)(g_t2 + row*Dn))[tid] = o4;
}

// ---------------------------------------------------------------------------
// Global logits per (h, l, b)
// ---------------------------------------------------------------------------
__global__ void __launch_bounds__(256)
global_logits_kernel()
{
    __shared__ float qg[64][65];
    __shared__ float kg[64][65];
    int h = blockIdx.x, l = blockIdx.y, b = blockIdx.z;
    int tid = threadIdx.x;
    for (int i = tid; i < 64*64; i += 256){
        int r = i>>6, c = i&63;
        size_t t = ((size_t)b*NSn + r)*SEGn + l;
        qg[r][c] = g_q   [t*Dn + h*HDn + c];
        kg[r][c] = g_krow[t*Dn + h*HDn + c];
    }
    __syncthreads();
    int row = tid>>2, quad = tid&3;
    float lg[16];
    #pragma unroll
    for (int c=0;c<16;c++) lg[c]=0.f;
    for (int d=0; d<64; d++){
        float qd = qg[row][d];
        #pragma unroll
        for (int c=0;c<16;c++) lg[c] += qd * kg[quad*16+c][d];
    }
    size_t t  = ((size_t)b*NSn + row)*SEGn + l;
    size_t jb = (t*Hn + h)*128 + 64;
    #pragma unroll
    for (int c=0;c<16;c++){
        int col = quad*16+c;
        g_joint[jb + col] = lg[c] + (row <= col ? NEGV : 0.f);
    }
}

// ---------------------------------------------------------------------------
// Joint softmax over 128-wide rows of g_joint
// ---------------------------------------------------------------------------
__global__ void __launch_bounds__(256)
joint_softmax_kernel()
{
    size_t r = (size_t)blockIdx.x*8 + (threadIdx.x>>5);
    int lane = threadIdx.x & 31;
    float4* p = (float4*)(g_joint + r*128);
    float4 v = p[lane];
    float m = fmaxf(fmaxf(v.x,v.y),fmaxf(v.z,v.w));
    #pragma unroll
    for (int o=16;o;o>>=1) m = fmaxf(m, __shfl_xor_sync(0xffffffffu,m,o));
    v.x = __expf(v.x-m); v.y = __expf(v.y-m);
    v.z = __expf(v.z-m); v.w = __expf(v.w-m);
    float s = v.x+v.y+v.z+v.w;
    #pragma unroll
    for (int o=16;o;o>>=1) s += __shfl_xor_sync(0xffffffffu,s,o);
    float inv = 1.f/s;
    v.x*=inv; v.y*=inv; v.z*=inv; v.w*=inv;
    p[lane] = v;
}

// ---------------------------------------------------------------------------
// local_merged per (h, seg, b)
// ---------------------------------------------------------------------------
__global__ void __launch_bounds__(256)
local_merged_kernel()
{
    __shared__ float ps[64][65];
    __shared__ float vs[64][65];
    int h = blockIdx.x, seg = blockIdx.y, b = blockIdx.z;
    int tid = threadIdx.x;
    size_t tok0 = ((size_t)b*NSn + seg)*SEGn;
    for (int i=tid;i<64*64;i+=256){
        int r=i>>6,c=i&63;
        ps[r][c] = g_joint[((tok0+r)*Hn+h)*128 + c];
        vs[r][c] = g_v[(tok0+r)*Dn + h*HDn + c];
    }
    __syncthreads();
    int row=tid>>2, quad=tid&3;
    float o[16];
    #pragma unroll
    for (int dd=0;dd<16;dd++) o[dd]=0.f;
    for (int c=0;c<64;c++){
        float pv = ps[row][c];
        #pragma unroll
        for (int dd=0;dd<16;dd++) o[dd]+=pv*vs[c][quad*16+dd];
    }
    size_t ob=(tok0+row)*Dn + h*HDn + quad*16;
    #pragma unroll
    for (int dd=0;dd<16;dd++) g_merged[ob+dd]=o[dd];
}

// ---------------------------------------------------------------------------
// global_merged per (h, l, b)
// ---------------------------------------------------------------------------
__global__ void __launch_bounds__(256)
global_merged_kernel()
{
    __shared__ float ga[64][65];
    __shared__ float ra[64][65];
    int h = blockIdx.x, l = blockIdx.y, b = blockIdx.z;
    int tid = threadIdx.x;
    for (int i=tid;i<64*64;i+=256){
        int r=i>>6,c=i&63;
        size_t t = ((size_t)b*NSn + r)*SEGn + l;
        ga[r][c] = g_joint[(t*Hn+h)*128 + 64 + c];
        ra[r][c] = g_rowattn[t*Dn + h*HDn + c];
    }
    __syncthreads();
    int row=tid>>2, quad=tid&3;
    float o[16];
    #pragma unroll
    for (int dd=0;dd<16;dd++) o[dd]=0.f;
    for (int c=0;c<64;c++){
        float gv = ga[row][c];
        #pragma unroll
        for (int dd=0;dd<16;dd++) o[dd]+=gv*ra[c][quad*16+dd];
    }
    size_t t  = ((size_t)b*NSn + row)*SEGn + l;
    size_t ob = t*Dn + h*HDn + quad*16;
    #pragma unroll
    for (int dd=0;dd<16;dd++) g_merged[ob+dd] += o[dd];
}

// ---------------------------------------------------------------------------
// Launch
// ---------------------------------------------------------------------------
extern "C" void kernel_launch(void* const* d_in, const int* in_sizes, int n_in,
                              void* d_out, int out_size)
{
    const float* x    = (const float*)d_in[0];
    const float* Wq   = (const float*)d_in[1];
    const float* Wk   = (const float*)d_in[2];
    const float* Wv   = (const float*)d_in[3];
    const float* Wro  = (const float*)d_in[4];
    const float* lns  = (const float*)d_in[5];
    const float* lnb  = (const float*)d_in[6];
    const float* Wk2  = (const float*)d_in[7];
    const float* Wout = (const float*)d_in[8];
    float* out = (float*)d_out;

    const int LA_SMEM = 3*64*65*4;
    cudaFuncSetAttribute(local_attn_kernel,
                         cudaFuncAttributeMaxDynamicSharedMemorySize, LA_SMEM);
    cudaFuncSetAttribute(hmma_gemm,
                         cudaFuncAttributeMaxDynamicSharedMemorySize, HG_SMEM);

    dim3 gg(8, 128);
    dim3 ga(Hn, NSn, Bn);
    dim3 gl(Hn, SEGn, Bn);
    const int ACT_BLKS = (NTOK*Dn/4)/256;

    convert_wt<<<dim3(32,32,6),256>>>(Wq, Wk, Wv, Wro, Wk2, Wout);

    convert_act<<<ACT_BLKS,256>>>(x, 0);
    hmma_gemm<<<gg,256,HG_SMEM>>>(0, nullptr,1, nullptr, 0.125f);   // q
    hmma_gemm<<<gg,256,HG_SMEM>>>(1, nullptr,2, nullptr, 1.f);      // k
    hmma_gemm<<<gg,256,HG_SMEM>>>(2, nullptr,3, nullptr, 1.f);      // v

    local_attn_kernel<<<ga,256,LA_SMEM>>>();

    convert_act<<<ACT_BLKS,256>>>(nullptr, 1);                      // rowattn
    hmma_gemm<<<gg,256,HG_SMEM>>>(3, nullptr,4, x, 1.f);            // t1
    ln_kernel<<<NTOK,256>>>(lns, lnb);
    convert_act<<<ACT_BLKS,256>>>(nullptr, 2);                      // t2
    hmma_gemm<<<gg,256,HG_SMEM>>>(4, nullptr,5, nullptr, 1.f);      // krow

    global_logits_kernel<<<gl,256>>>();
    joint_softmax_kernel<<<(NTOK*Hn)/8,256>>>();
    local_merged_kernel<<<ga,256>>>();
    global_merged_kernel<<<gl,256>>>();

    convert_act<<<ACT_BLKS,256>>>(nullptr, 3);                      // merged
    hmma_gemm<<<gg,256,HG_SMEM>>>(5, out,0, nullptr, 1.f);
}

// round 7
// speedup vs baseline: 2.1015x; 1.2330x over previous
#include <cuda_runtime.h>
#include <cuda_bf16.h>
#include <math.h>
#include <stdint.h>

// Problem constants
#define Bn   4
#define Sn   4096
#define Dn   1024
#define Hn   16
#define HDn  64
#define SEGn 64
#define NSn  64
#define NTOK (Bn*Sn)          // 16384
#define NEGV (-1.0e10f)

// ---------------------------------------------------------------------------
// Scratch (device globals)
// ---------------------------------------------------------------------------
__device__ float g_q      [(size_t)NTOK*Dn];
__device__ float g_k      [(size_t)NTOK*Dn];
__device__ float g_v      [(size_t)NTOK*Dn];
__device__ float g_rowattn[(size_t)NTOK*Dn];
__device__ float g_t1     [(size_t)NTOK*Dn];
__device__ float g_krow   [(size_t)NTOK*Dn];
__device__ float g_merged [(size_t)NTOK*Dn];   // local_merged partial
__device__ float g_joint  [(size_t)NTOK*Hn*128];

// Split-bf16 staging
__device__ __nv_bfloat16 g_ahi [(size_t)NTOK*Dn];
__device__ __nv_bfloat16 g_alo [(size_t)NTOK*Dn];
__device__ __nv_bfloat16 g_wthi[(size_t)6*Dn*Dn];   // WT[w][n][k] = W[w][k][n]
__device__ __nv_bfloat16 g_wtlo[(size_t)6*Dn*Dn];

__device__ __forceinline__ float* cpick(float* ext, int id){
    switch(id){ case 1: return g_q; case 2: return g_k; case 3: return g_v;
                case 4: return g_t1; case 5: return g_krow; }
    return ext;
}
__device__ __forceinline__ void store_split(float v, size_t off){
    __nv_bfloat16 hi = __float2bfloat16_rn(v);
    __nv_bfloat16 lo = __float2bfloat16_rn(v - __bfloat162float(hi));
    g_ahi[off] = hi; g_alo[off] = lo;
}

__device__ __forceinline__ uint32_t smem_u32(const void* p){
    uint32_t a;
    asm("{ .reg .u64 t; cvta.to.shared.u64 t, %1; cvt.u32.u64 %0, t; }" : "=r"(a) : "l"(p));
    return a;
}
__device__ __forceinline__ void cp_async16(uint32_t dst, const void* src){
    asm volatile("cp.async.cg.shared.global [%0], [%1], 16;" :: "r"(dst), "l"(src) : "memory");
}
__device__ __forceinline__ void cp_commit(){
    asm volatile("cp.async.commit_group;" ::: "memory");
}
template<int N> __device__ __forceinline__ void cp_wait(){
    asm volatile("cp.async.wait_group %0;" :: "n"(N) : "memory");
}
__device__ __forceinline__ void mma16816(float* c, const uint32_t* a, const uint32_t* b){
    asm volatile("mma.sync.aligned.m16n8k16.row.col.f32.bf16.bf16.f32 "
                 "{%0,%1,%2,%3}, {%4,%5,%6,%7}, {%8,%9}, {%0,%1,%2,%3};"
                 : "+f"(c[0]), "+f"(c[1]), "+f"(c[2]), "+f"(c[3])
                 : "r"(a[0]), "r"(a[1]), "r"(a[2]), "r"(a[3]), "r"(b[0]), "r"(b[1]));
}

// ---------------------------------------------------------------------------
// Split conversion: x fp32 -> (hi,lo) bf16
// ---------------------------------------------------------------------------
__global__ void __launch_bounds__(256)
convert_act(const float* __restrict__ src)
{
    size_t i = (size_t)blockIdx.x*256 + threadIdx.x;
    float4 v = ((const float4*)src)[i];
    __nv_bfloat16 hx = __float2bfloat16_rn(v.x);
    __nv_bfloat16 hy = __float2bfloat16_rn(v.y);
    __nv_bfloat16 hz = __float2bfloat16_rn(v.z);
    __nv_bfloat16 hw = __float2bfloat16_rn(v.w);
    __nv_bfloat16 lx = __float2bfloat16_rn(v.x - __bfloat162float(hx));
    __nv_bfloat16 ly = __float2bfloat16_rn(v.y - __bfloat162float(hy));
    __nv_bfloat16 lz = __float2bfloat16_rn(v.z - __bfloat162float(hz));
    __nv_bfloat16 lw = __float2bfloat16_rn(v.w - __bfloat162float(hw));
    __nv_bfloat162 h0(hx,hy), h1(hz,hw), l0(lx,ly), l1(lz,lw);
    uint2 hv, lv;
    hv.x = *(uint32_t*)&h0; hv.y = *(uint32_t*)&h1;
    lv.x = *(uint32_t*)&l0; lv.y = *(uint32_t*)&l1;
    ((uint2*)g_ahi)[i] = hv;
    ((uint2*)g_alo)[i] = lv;
}

// ---------------------------------------------------------------------------
// Weight transpose+split: WT[w][n][k] = split(W[w][k][n])
// ---------------------------------------------------------------------------
__global__ void __launch_bounds__(256)
convert_wt(const float* __restrict__ W0, const float* __restrict__ W1,
           const float* __restrict__ W2, const float* __restrict__ W3,
           const float* __restrict__ W4, const float* __restrict__ W5)
{
    const float* Ws[6] = {W0,W1,W2,W3,W4,W5};
    const float* W = Ws[blockIdx.z];
    __shared__ float tile[32][33];
    int n0 = blockIdx.x*32, k0 = blockIdx.y*32;
    int tx = threadIdx.x & 31, ty = threadIdx.x >> 5;
    #pragma unroll
    for (int j = 0; j < 4; j++){
        int r = ty + j*8;
        tile[r][tx] = W[(size_t)(k0+r)*Dn + n0 + tx];
    }
    __syncthreads();
    size_t wbase = (size_t)blockIdx.z*Dn*Dn;
    #pragma unroll
    for (int j = 0; j < 4; j++){
        int r = ty + j*8;
        float a = tile[tx][r];
        __nv_bfloat16 hi = __float2bfloat16_rn(a);
        __nv_bfloat16 lo = __float2bfloat16_rn(a - __bfloat162float(hi));
        size_t o = wbase + (size_t)(n0+r)*Dn + k0 + tx;
        g_wthi[o] = hi;
        g_wtlo[o] = lo;
    }
}

// ---------------------------------------------------------------------------
// HMMA GEMM: C[16384,1024] = alpha * A @ W[widx] (+R)
// Split-bf16, 3 mma products. Tile 128x128, BK=32, double-buffered cp.async.
// Buffer: 4 matrices x [128][40] bf16 = 40960 B; two buffers = 81920 B -> occ 2.
// widx == -1: fused QKV mode (blockIdx.z selects weight/output/alpha).
// ---------------------------------------------------------------------------
#define AST  40
#define TSZB (128*AST*2)          // 10240 B per matrix
#define BUFB (4*TSZB)             // 40960 B per buffer
#define HG_SMEM (2*BUFB)          // 81920 B

__global__ void __launch_bounds__(256,2)
hmma_gemm(int widx, float* Cext, int Cid, const float* __restrict__ R, float alpha)
{
    extern __shared__ char smem[];
    uint32_t sb = smem_u32(smem);
    int tid = threadIdx.x, lane = tid & 31, wid = tid >> 5;
    int wm = wid & 1, wn = wid >> 1;           // 2 x 4 warp grid
    int m0 = blockIdx.y*128, n0 = blockIdx.x*128;

    if (widx < 0){                             // fused QKV
        widx = blockIdx.z;
        Cid  = blockIdx.z + 1;
        alpha = (blockIdx.z == 0) ? 0.125f : 1.f;
    }
    float* C = cpick(Cext, Cid);

    const __nv_bfloat16* srcs[4];
    srcs[0] = g_ahi  + (size_t)m0*Dn;
    srcs[1] = g_alo  + (size_t)m0*Dn;
    srcs[2] = g_wthi + (size_t)widx*Dn*Dn + (size_t)n0*Dn;
    srcs[3] = g_wtlo + (size_t)widx*Dn*Dn + (size_t)n0*Dn;

    // fill chunk c (k0 = c*32) into buffer `buf`
    auto fill = [&](int c, int buf){
        int k0 = c*32;
        uint32_t base = sb + buf*BUFB;
        #pragma unroll
        for (int t = 0; t < 4; t++){
            #pragma unroll
            for (int it = 0; it < 2; it++){
                int idx = it*256 + tid;
                int r = idx >> 2, cc = idx & 3;
                cp_async16(base + t*TSZB + r*(AST*2) + cc*16,
                           srcs[t] + (size_t)r*Dn + k0 + cc*8);
            }
        }
        cp_commit();
    };

    float acc[4][4][4];
    #pragma unroll
    for (int i=0;i<4;i++)
        #pragma unroll
        for (int j=0;j<4;j++)
            #pragma unroll
            for (int q=0;q<4;q++) acc[i][j][q]=0.f;

    fill(0, 0);

    for (int c = 0; c < 32; c++){
        int buf = c & 1;
        if (c < 31){ fill(c+1, buf^1); cp_wait<1>(); }
        else       { cp_wait<0>(); }
        __syncthreads();

        const __nv_bfloat16* Ah = (const __nv_bfloat16*)(smem + buf*BUFB);
        const __nv_bfloat16* Al = (const __nv_bfloat16*)(smem + buf*BUFB + TSZB);
        const __nv_bfloat16* Bh = (const __nv_bfloat16*)(smem + buf*BUFB + 2*TSZB);
        const __nv_bfloat16* Bl = (const __nv_bfloat16*)(smem + buf*BUFB + 3*TSZB);

        #pragma unroll
        for (int ks = 0; ks < 2; ks++){
            int k16 = ks*16;
            uint32_t ah[4][4], al[4][4], bh[4][2], bl[4][2];
            #pragma unroll
            for (int i = 0; i < 4; i++){
                int row = wm*64 + i*16 + (lane>>2);
                int off = row*AST + k16 + 2*(lane&3);
                ah[i][0] = *(const uint32_t*)(Ah + off);
                ah[i][1] = *(const uint32_t*)(Ah + off + 8*AST);
                ah[i][2] = *(const uint32_t*)(Ah + off + 8);
                ah[i][3] = *(const uint32_t*)(Ah + off + 8*AST + 8);
                al[i][0] = *(const uint32_t*)(Al + off);
                al[i][1] = *(const uint32_t*)(Al + off + 8*AST);
                al[i][2] = *(const uint32_t*)(Al + off + 8);
                al[i][3] = *(const uint32_t*)(Al + off + 8*AST + 8);
            }
            #pragma unroll
            for (int j = 0; j < 4; j++){
                int nrow = wn*32 + j*8 + (lane>>2);
                int off = nrow*AST + k16 + 2*(lane&3);
                bh[j][0] = *(const uint32_t*)(Bh + off);
                bh[j][1] = *(const uint32_t*)(Bh + off + 8);
                bl[j][0] = *(const uint32_t*)(Bl + off);
                bl[j][1] = *(const uint32_t*)(Bl + off + 8);
            }
            #pragma unroll
            for (int i = 0; i < 4; i++)
                #pragma unroll
                for (int j = 0; j < 4; j++){
                    mma16816(acc[i][j], ah[i], bh[j]);
                    mma16816(acc[i][j], ah[i], bl[j]);
                    mma16816(acc[i][j], al[i], bh[j]);
                }
        }
        __syncthreads();
    }

    // Epilogue
    #pragma unroll
    for (int i = 0; i < 4; i++){
        int row = m0 + wm*64 + i*16 + (lane>>2);
        #pragma unroll
        for (int j = 0; j < 4; j++){
            int col = n0 + wn*32 + j*8 + 2*(lane&3);
            size_t o0 = (size_t)row*Dn + col;
            size_t o1 = (size_t)(row+8)*Dn + col;
            float2 v0, v1;
            v0.x = alpha*acc[i][j][0]; v0.y = alpha*acc[i][j][1];
            v1.x = alpha*acc[i][j][2]; v1.y = alpha*acc[i][j][3];
            if (R){
                float2 r0 = *(const float2*)(R + o0);
                float2 r1 = *(const float2*)(R + o1);
                v0.x += r0.x; v0.y += r0.y; v1.x += r1.x; v1.y += r1.y;
            }
            *(float2*)(C + o0) = v0;
            *(float2*)(C + o1) = v1;
        }
    }
}

// ---------------------------------------------------------------------------
// Local attention per (h, seg, b). Conflict-free mapping: quad owns keys/dims
// {quad, quad+4, ..., quad+60}. Also writes bf16 split of rowattn.
// ---------------------------------------------------------------------------
__global__ void __launch_bounds__(256)
local_attn_kernel()
{
    extern __shared__ float sm[];
    float* qs = sm;
    float* ks = sm + 64*65;
    float* vs = sm + 2*64*65;

    int h = blockIdx.x, seg = blockIdx.y, b = blockIdx.z;
    int tid = threadIdx.x;
    size_t tok0 = ((size_t)b*NSn + seg)*SEGn;

    for (int i = tid; i < 64*64; i += 256) {
        int r = i >> 6, c = i & 63;
        size_t off = (tok0 + r)*Dn + h*HDn + c;
        qs[r*65+c] = g_q[off];
        ks[r*65+c] = g_k[off];
        vs[r*65+c] = g_v[off];
    }
    __syncthreads();

    int row = tid >> 2, quad = tid & 3;    // quad owns keys c*4+quad
    float lg[16];
    #pragma unroll
    for (int c=0;c<16;c++) lg[c]=0.f;
    for (int d = 0; d < 64; d++) {
        float qd = qs[row*65+d];
        #pragma unroll
        for (int c=0;c<16;c++) lg[c] += qd * ks[(c*4+quad)*65 + d];
    }

    size_t jb = ((tok0 + row)*Hn + h)*128;
    #pragma unroll
    for (int c=0;c<16;c++) {
        int col = c*4+quad;
        g_joint[jb + col] = lg[c] + (row < col ? NEGV : 0.f);
    }

    float m = -1e30f;
    #pragma unroll
    for (int c=0;c<16;c++) m = fmaxf(m, lg[c]);
    m = fmaxf(m, __shfl_xor_sync(0xffffffffu, m, 1));
    m = fmaxf(m, __shfl_xor_sync(0xffffffffu, m, 2));
    float ssum = 0.f;
    #pragma unroll
    for (int c=0;c<16;c++){ lg[c] = __expf(lg[c]-m); ssum += lg[c]; }
    ssum += __shfl_xor_sync(0xffffffffu, ssum, 1);
    ssum += __shfl_xor_sync(0xffffffffu, ssum, 2);
    float inv = 1.f/ssum;

    __syncthreads();
    #pragma unroll
    for (int c=0;c<16;c++) ks[row*65 + c*4+quad] = lg[c];   // semantic col
    __syncthreads();

    float o[16];
    #pragma unroll
    for (int j=0;j<16;j++) o[j]=0.f;
    for (int c2=0;c2<64;c2++){
        float p = ks[row*65+c2];
        #pragma unroll
        for (int j=0;j<16;j++) o[j] += p * vs[c2*65 + j*4 + quad];
    }
    size_t ob = (tok0+row)*Dn + h*HDn;
    #pragma unroll
    for (int j=0;j<16;j++){
        float val = o[j]*inv;
        size_t off = ob + j*4 + quad;
        g_rowattn[off] = val;
        store_split(val, off);
    }
}

// ---------------------------------------------------------------------------
// LayerNorm over D=1024 per token: writes bf16 split directly (feeds GEMM krow)
// ---------------------------------------------------------------------------
__global__ void __launch_bounds__(256)
ln_kernel(const float* __restrict__ scale, const float* __restrict__ bias)
{
    size_t row = blockIdx.x;
    int tid = threadIdx.x;
    float4 v = ((const float4*)(g_t1 + row*Dn))[tid];
    float s  = v.x+v.y+v.z+v.w;
    float ss = v.x*v.x+v.y*v.y+v.z*v.z+v.w*v.w;
    #pragma unroll
    for (int o=16;o;o>>=1){
        s  += __shfl_xor_sync(0xffffffffu, s, o);
        ss += __shfl_xor_sync(0xffffffffu, ss, o);
    }
    __shared__ float sh[16];
    int w = tid>>5, lane = tid&31;
    if (lane==0){ sh[w]=s; sh[8+w]=ss; }
    __syncthreads();
    if (tid==0){
        float a=0.f,b2=0.f;
        #pragma unroll
        for (int i=0;i<8;i++){ a+=sh[i]; b2+=sh[8+i]; }
        float mu  = a*(1.f/Dn);
        float var = b2*(1.f/Dn) - mu*mu;
        sh[0]=mu; sh[1]=rsqrtf(var + 1e-6f);
    }
    __syncthreads();
    float mu = sh[0], rstd = sh[1];
    float4 sc = ((const float4*)scale)[tid];
    float4 bi = ((const float4*)bias)[tid];
    float o0=(v.x-mu)*rstd*sc.x+bi.x;
    float o1=(v.y-mu)*rstd*sc.y+bi.y;
    float o2=(v.z-mu)*rstd*sc.z+bi.z;
    float o3=(v.w-mu)*rstd*sc.w+bi.w;
    __nv_bfloat16 h0=__float2bfloat16_rn(o0), h1=__float2bfloat16_rn(o1);
    __nv_bfloat16 h2=__float2bfloat16_rn(o2), h3=__float2bfloat16_rn(o3);
    __nv_bfloat16 l0=__float2bfloat16_rn(o0-__bfloat162float(h0));
    __nv_bfloat16 l1=__float2bfloat16_rn(o1-__bfloat162float(h1));
    __nv_bfloat16 l2=__float2bfloat16_rn(o2-__bfloat162float(h2));
    __nv_bfloat16 l3=__float2bfloat16_rn(o3-__bfloat162float(h3));
    __nv_bfloat162 hp0(h0,h1), hp1(h2,h3), lp0(l0,l1), lp1(l2,l3);
    uint2 hv, lv;
    hv.x=*(uint32_t*)&hp0; hv.y=*(uint32_t*)&hp1;
    lv.x=*(uint32_t*)&lp0; lv.y=*(uint32_t*)&lp1;
    ((uint2*)g_ahi)[row*256 + tid] = hv;
    ((uint2*)g_alo)[row*256 + tid] = lv;
}

// ---------------------------------------------------------------------------
// Global logits + fused joint softmax per (h, l, b).
// Computes masked global logits, loads local masked logits from g_joint,
// softmaxes the 128-wide row, writes normalized probs back to g_joint.
// ---------------------------------------------------------------------------
__global__ void __launch_bounds__(256)
global_logits_kernel()
{
    __shared__ float qg[64][65];
    __shared__ float kg[64][65];
    int h = blockIdx.x, l = blockIdx.y, b = blockIdx.z;
    int tid = threadIdx.x;
    for (int i = tid; i < 64*64; i += 256){
        int r = i>>6, c = i&63;
        size_t t = ((size_t)b*NSn + r)*SEGn + l;
        qg[r][c] = g_q   [t*Dn + h*HDn + c];
        kg[r][c] = g_krow[t*Dn + h*HDn + c];
    }
    __syncthreads();
    int row = tid>>2, quad = tid&3;        // quad owns ksegs c*4+quad
    float lg[16];
    #pragma unroll
    for (int c=0;c<16;c++) lg[c]=0.f;
    for (int d=0; d<64; d++){
        float qd = qg[row][d];
        #pragma unroll
        for (int c=0;c<16;c++) lg[c] += qd * kg[c*4+quad][d];
    }
    #pragma unroll
    for (int c=0;c<16;c++){
        int col = c*4+quad;
        lg[c] += (row <= col ? NEGV : 0.f);
    }

    // fused softmax over [local(64) | global(64)]
    size_t t  = ((size_t)b*NSn + row)*SEGn + l;
    size_t jb = (t*Hn + h)*128;
    float4 loc[4];
    #pragma unroll
    for (int j4=0;j4<4;j4++)
        loc[j4] = *(const float4*)(g_joint + jb + quad*16 + j4*4);

    float m = -1e30f;
    #pragma unroll
    for (int c=0;c<16;c++) m = fmaxf(m, lg[c]);
    #pragma unroll
    for (int j4=0;j4<4;j4++)
        m = fmaxf(m, fmaxf(fmaxf(loc[j4].x,loc[j4].y),fmaxf(loc[j4].z,loc[j4].w)));
    m = fmaxf(m, __shfl_xor_sync(0xffffffffu, m, 1));
    m = fmaxf(m, __shfl_xor_sync(0xffffffffu, m, 2));

    float ssum = 0.f;
    #pragma unroll
    for (int c=0;c<16;c++){ lg[c] = __expf(lg[c]-m); ssum += lg[c]; }
    #pragma unroll
    for (int j4=0;j4<4;j4++){
        loc[j4].x = __expf(loc[j4].x-m); loc[j4].y = __expf(loc[j4].y-m);
        loc[j4].z = __expf(loc[j4].z-m); loc[j4].w = __expf(loc[j4].w-m);
        ssum += loc[j4].x+loc[j4].y+loc[j4].z+loc[j4].w;
    }
    ssum += __shfl_xor_sync(0xffffffffu, ssum, 1);
    ssum += __shfl_xor_sync(0xffffffffu, ssum, 2);
    float inv = 1.f/ssum;

    #pragma unroll
    for (int j4=0;j4<4;j4++){
        loc[j4].x*=inv; loc[j4].y*=inv; loc[j4].z*=inv; loc[j4].w*=inv;
        *(float4*)(g_joint + jb + quad*16 + j4*4) = loc[j4];
    }
    #pragma unroll
    for (int c=0;c<16;c++)
        g_joint[jb + 64 + c*4+quad] = lg[c]*inv;
}

// ---------------------------------------------------------------------------
// local_merged per (h, seg, b): merged = latt @ v (writes g_merged)
// ---------------------------------------------------------------------------
__global__ void __launch_bounds__(256)
local_merged_kernel()
{
    __shared__ float ps[64][65];
    __shared__ float vs[64][65];
    int h = blockIdx.x, seg = blockIdx.y, b = blockIdx.z;
    int tid = threadIdx.x;
    size_t tok0 = ((size_t)b*NSn + seg)*SEGn;
    for (int i=tid;i<64*64;i+=256){
        int r=i>>6,c=i&63;
        ps[r][c] = g_joint[((tok0+r)*Hn+h)*128 + c];
        vs[r][c] = g_v[(tok0+r)*Dn + h*HDn + c];
    }
    __syncthreads();
    int row=tid>>2, quad=tid&3;
    float o[16];
    #pragma unroll
    for (int j=0;j<16;j++) o[j]=0.f;
    for (int c=0;c<64;c++){
        float pv = ps[row][c];
        #pragma unroll
        for (int j=0;j<16;j++) o[j]+=pv*vs[c][j*4+quad];
    }
    size_t ob=(tok0+row)*Dn + h*HDn;
    #pragma unroll
    for (int j=0;j<16;j++) g_merged[ob + j*4+quad]=o[j];
}

// ---------------------------------------------------------------------------
// global_merged per (h, l, b): merged += gatt @ row_attn; writes bf16 split
// of the final merged (consumed by the output GEMM).
// ---------------------------------------------------------------------------
__global__ void __launch_bounds__(256)
global_merged_kernel()
{
    __shared__ float ga[64][65];
    __shared__ float ra[64][65];
    int h = blockIdx.x, l = blockIdx.y, b = blockIdx.z;
    int tid = threadIdx.x;
    for (int i=tid;i<64*64;i+=256){
        int r=i>>6,c=i&63;
        size_t t = ((size_t)b*NSn + r)*SEGn + l;
        ga[r][c] = g_joint[(t*Hn+h)*128 + 64 + c];
        ra[r][c] = g_rowattn[t*Dn + h*HDn + c];
    }
    __syncthreads();
    int row=tid>>2, quad=tid&3;
    float o[16];
    #pragma unroll
    for (int j=0;j<16;j++) o[j]=0.f;
    for (int c=0;c<64;c++){
        float gv = ga[row][c];
        #pragma unroll
        for (int j=0;j<16;j++) o[j]+=gv*ra[c][j*4+quad];
    }
    size_t t  = ((size_t)b*NSn + row)*SEGn + l;
    size_t ob = t*Dn + h*HDn;
    #pragma unroll
    for (int j=0;j<16;j++){
        size_t off = ob + j*4+quad;
        store_split(g_merged[off] + o[j], off);
    }
}

// ---------------------------------------------------------------------------
// Launch
// ---------------------------------------------------------------------------
extern "C" void kernel_launch(void* const* d_in, const int* in_sizes, int n_in,
                              void* d_out, int out_size)
{
    const float* x    = (const float*)d_in[0];
    const float* Wq   = (const float*)d_in[1];
    const float* Wk   = (const float*)d_in[2];
    const float* Wv   = (const float*)d_in[3];
    const float* Wro  = (const float*)d_in[4];
    const float* lns  = (const float*)d_in[5];
    const float* lnb  = (const float*)d_in[6];
    const float* Wk2  = (const float*)d_in[7];
    const float* Wout = (const float*)d_in[8];
    float* out = (float*)d_out;

    const int LA_SMEM = 3*64*65*4;
    cudaFuncSetAttribute(local_attn_kernel,
                         cudaFuncAttributeMaxDynamicSharedMemorySize, LA_SMEM);
    cudaFuncSetAttribute(hmma_gemm,
                         cudaFuncAttributeMaxDynamicSharedMemorySize, HG_SMEM);

    dim3 gg(8, 128);
    dim3 gq(8, 128, 3);         // fused QKV
    dim3 ga(Hn, NSn, Bn);
    dim3 gl(Hn, SEGn, Bn);
    const int ACT_BLKS = (NTOK*Dn/4)/256;

    convert_wt<<<dim3(32,32,6),256>>>(Wq, Wk, Wv, Wro, Wk2, Wout);

    convert_act<<<ACT_BLKS,256>>>(x);
    hmma_gemm<<<gq,256,HG_SMEM>>>(-1, nullptr,0, nullptr, 0.f);     // q,k,v

    local_attn_kernel<<<ga,256,LA_SMEM>>>();                        // + rowattn split

    hmma_gemm<<<gg,256,HG_SMEM>>>(3, nullptr,4, x, 1.f);            // t1 = rowattn@Wro + x
    ln_kernel<<<NTOK,256>>>(lns, lnb);                              // -> ahi/alo (t2)
    hmma_gemm<<<gg,256,HG_SMEM>>>(4, nullptr,5, nullptr, 1.f);      // krow

    global_logits_kernel<<<gl,256>>>();                             // + joint softmax
    local_merged_kernel<<<ga,256>>>();
    global_merged_kernel<<<gl,256>>>();                             // + merged split

    hmma_gemm<<<gg,256,HG_SMEM>>>(5, out,0, nullptr, 1.f);
}

// round 9
// speedup vs baseline: 2.2947x; 1.0920x over previous
#include <cuda_runtime.h>
#include <cuda_bf16.h>
#include <math.h>
#include <stdint.h>

// Problem constants
#define Bn   4
#define Sn   4096
#define Dn   1024
#define Hn   16
#define HDn  64
#define SEGn 64
#define NSn  64
#define NTOK (Bn*Sn)          // 16384
#define NEGV (-1.0e10f)

// ---------------------------------------------------------------------------
// Scratch (device globals)
// ---------------------------------------------------------------------------
__device__ float g_q      [(size_t)NTOK*Dn];
__device__ float g_k      [(size_t)NTOK*Dn];
__device__ float g_v      [(size_t)NTOK*Dn];
__device__ float g_rowattn[(size_t)NTOK*Dn];
__device__ float g_t1     [(size_t)NTOK*Dn];
__device__ float g_krow   [(size_t)NTOK*Dn];
__device__ float g_merged [(size_t)NTOK*Dn];   // local_merged partial
__device__ float g_joint  [(size_t)NTOK*Hn*128];

// Split-bf16 staging
__device__ __nv_bfloat16 g_ahi [(size_t)NTOK*Dn];
__device__ __nv_bfloat16 g_alo [(size_t)NTOK*Dn];
__device__ __nv_bfloat16 g_wthi[(size_t)6*Dn*Dn];   // WT[w][n][k] = W[w][k][n]
__device__ __nv_bfloat16 g_wtlo[(size_t)6*Dn*Dn];

__device__ __forceinline__ float* cpick(float* ext, int id){
    switch(id){ case 1: return g_q; case 2: return g_k; case 3: return g_v;
                case 4: return g_t1; case 5: return g_krow; }
    return ext;
}

// vector split store: 4 consecutive values at 4-aligned offset
__device__ __forceinline__ void store_split4(float4 v, size_t off){
    __nv_bfloat16 h0=__float2bfloat16_rn(v.x), h1=__float2bfloat16_rn(v.y);
    __nv_bfloat16 h2=__float2bfloat16_rn(v.z), h3=__float2bfloat16_rn(v.w);
    __nv_bfloat16 l0=__float2bfloat16_rn(v.x-__bfloat162float(h0));
    __nv_bfloat16 l1=__float2bfloat16_rn(v.y-__bfloat162float(h1));
    __nv_bfloat16 l2=__float2bfloat16_rn(v.z-__bfloat162float(h2));
    __nv_bfloat16 l3=__float2bfloat16_rn(v.w-__bfloat162float(h3));
    __nv_bfloat162 hp0(h0,h1), hp1(h2,h3), lp0(l0,l1), lp1(l2,l3);
    uint2 hv, lv;
    hv.x=*(uint32_t*)&hp0; hv.y=*(uint32_t*)&hp1;
    lv.x=*(uint32_t*)&lp0; lv.y=*(uint32_t*)&lp1;
    *(uint2*)(g_ahi + off) = hv;
    *(uint2*)(g_alo + off) = lv;
}

__device__ __forceinline__ uint32_t smem_u32(const void* p){
    uint32_t a;
    asm("{ .reg .u64 t; cvta.to.shared.u64 t, %1; cvt.u32.u64 %0, t; }" : "=r"(a) : "l"(p));
    return a;
}
__device__ __forceinline__ void cp_async16(uint32_t dst, const void* src){
    asm volatile("cp.async.cg.shared.global [%0], [%1], 16;" :: "r"(dst), "l"(src) : "memory");
}
__device__ __forceinline__ void cp_commit(){
    asm volatile("cp.async.commit_group;" ::: "memory");
}
template<int N> __device__ __forceinline__ void cp_wait(){
    asm volatile("cp.async.wait_group %0;" :: "n"(N) : "memory");
}
__device__ __forceinline__ void mma16816(float* c, const uint32_t* a, const uint32_t* b){
    asm volatile("mma.sync.aligned.m16n8k16.row.col.f32.bf16.bf16.f32 "
                 "{%0,%1,%2,%3}, {%4,%5,%6,%7}, {%8,%9}, {%0,%1,%2,%3};"
                 : "+f"(c[0]), "+f"(c[1]), "+f"(c[2]), "+f"(c[3])
                 : "r"(a[0]), "r"(a[1]), "r"(a[2]), "r"(a[3]), "r"(b[0]), "r"(b[1]));
}

// ---------------------------------------------------------------------------
// Split conversion: x fp32 -> (hi,lo) bf16
// ---------------------------------------------------------------------------
__global__ void __launch_bounds__(256)
convert_act(const float* __restrict__ src)
{
    size_t i = (size_t)blockIdx.x*256 + threadIdx.x;
    float4 v = ((const float4*)src)[i];
    store_split4(v, i*4);
}

// ---------------------------------------------------------------------------
// Weight transpose+split: WT[w][n][k] = split(W[w][k][n])
// ---------------------------------------------------------------------------
__global__ void __launch_bounds__(256)
convert_wt(const float* __restrict__ W0, const float* __restrict__ W1,
           const float* __restrict__ W2, const float* __restrict__ W3,
           const float* __restrict__ W4, const float* __restrict__ W5)
{
    const float* Ws[6] = {W0,W1,W2,W3,W4,W5};
    const float* W = Ws[blockIdx.z];
    __shared__ float tile[32][33];
    int n0 = blockIdx.x*32, k0 = blockIdx.y*32;
    int tx = threadIdx.x & 31, ty = threadIdx.x >> 5;
    #pragma unroll
    for (int j = 0; j < 4; j++){
        int r = ty + j*8;
        tile[r][tx] = W[(size_t)(k0+r)*Dn + n0 + tx];
    }
    __syncthreads();
    size_t wbase = (size_t)blockIdx.z*Dn*Dn;
    #pragma unroll
    for (int j = 0; j < 4; j++){
        int r = ty + j*8;
        float a = tile[tx][r];
        __nv_bfloat16 hi = __float2bfloat16_rn(a);
        __nv_bfloat16 lo = __float2bfloat16_rn(a - __bfloat162float(hi));
        size_t o = wbase + (size_t)(n0+r)*Dn + k0 + tx;
        g_wthi[o] = hi;
        g_wtlo[o] = lo;
    }
}

// ---------------------------------------------------------------------------
// HMMA GEMM: unchanged from R7 (BK=32, occ 2, fused-QKV mode)
// ---------------------------------------------------------------------------
#define AST  40
#define TSZB (128*AST*2)          // 10240 B per matrix
#define BUFB (4*TSZB)             // 40960 B per buffer
#define HG_SMEM (2*BUFB)          // 81920 B

__global__ void __launch_bounds__(256,2)
hmma_gemm(int widx, float* Cext, int Cid, const float* __restrict__ R, float alpha)
{
    extern __shared__ char smem[];
    uint32_t sb = smem_u32(smem);
    int tid = threadIdx.x, lane = tid & 31, wid = tid >> 5;
    int wm = wid & 1, wn = wid >> 1;
    int m0 = blockIdx.y*128, n0 = blockIdx.x*128;

    if (widx < 0){
        widx = blockIdx.z;
        Cid  = blockIdx.z + 1;
        alpha = (blockIdx.z == 0) ? 0.125f : 1.f;
    }
    float* C = cpick(Cext, Cid);

    const __nv_bfloat16* srcs[4];
    srcs[0] = g_ahi  + (size_t)m0*Dn;
    srcs[1] = g_alo  + (size_t)m0*Dn;
    srcs[2] = g_wthi + (size_t)widx*Dn*Dn + (size_t)n0*Dn;
    srcs[3] = g_wtlo + (size_t)widx*Dn*Dn + (size_t)n0*Dn;

    auto fill = [&](int c, int buf){
        int k0 = c*32;
        uint32_t base = sb + buf*BUFB;
        #pragma unroll
        for (int t = 0; t < 4; t++){
            #pragma unroll
            for (int it = 0; it < 2; it++){
                int idx = it*256 + tid;
                int r = idx >> 2, cc = idx & 3;
                cp_async16(base + t*TSZB + r*(AST*2) + cc*16,
                           srcs[t] + (size_t)r*Dn + k0 + cc*8);
            }
        }
        cp_commit();
    };

    float acc[4][4][4];
    #pragma unroll
    for (int i=0;i<4;i++)
        #pragma unroll
        for (int j=0;j<4;j++)
            #pragma unroll
            for (int q=0;q<4;q++) acc[i][j][q]=0.f;

    fill(0, 0);

    for (int c = 0; c < 32; c++){
        int buf = c & 1;
        if (c < 31){ fill(c+1, buf^1); cp_wait<1>(); }
        else       { cp_wait<0>(); }
        __syncthreads();

        const __nv_bfloat16* Ah = (const __nv_bfloat16*)(smem + buf*BUFB);
        const __nv_bfloat16* Al = (const __nv_bfloat16*)(smem + buf*BUFB + TSZB);
        const __nv_bfloat16* Bh = (const __nv_bfloat16*)(smem + buf*BUFB + 2*TSZB);
        const __nv_bfloat16* Bl = (const __nv_bfloat16*)(smem + buf*BUFB + 3*TSZB);

        #pragma unroll
        for (int ks = 0; ks < 2; ks++){
            int k16 = ks*16;
            uint32_t ah[4][4], al[4][4], bh[4][2], bl[4][2];
            #pragma unroll
            for (int i = 0; i < 4; i++){
                int row = wm*64 + i*16 + (lane>>2);
                int off = row*AST + k16 + 2*(lane&3);
                ah[i][0] = *(const uint32_t*)(Ah + off);
                ah[i][1] = *(const uint32_t*)(Ah + off + 8*AST);
                ah[i][2] = *(const uint32_t*)(Ah + off + 8);
                ah[i][3] = *(const uint32_t*)(Ah + off + 8*AST + 8);
                al[i][0] = *(const uint32_t*)(Al + off);
                al[i][1] = *(const uint32_t*)(Al + off + 8*AST);
                al[i][2] = *(const uint32_t*)(Al + off + 8);
                al[i][3] = *(const uint32_t*)(Al + off + 8*AST + 8);
            }
            #pragma unroll
            for (int j = 0; j < 4; j++){
                int nrow = wn*32 + j*8 + (lane>>2);
                int off = nrow*AST + k16 + 2*(lane&3);
                bh[j][0] = *(const uint32_t*)(Bh + off);
                bh[j][1] = *(const uint32_t*)(Bh + off + 8);
                bl[j][0] = *(const uint32_t*)(Bl + off);
                bl[j][1] = *(const uint32_t*)(Bl + off + 8);
            }
            #pragma unroll
            for (int i = 0; i < 4; i++)
                #pragma unroll
                for (int j = 0; j < 4; j++){
                    mma16816(acc[i][j], ah[i], bh[j]);
                    mma16816(acc[i][j], ah[i], bl[j]);
                    mma16816(acc[i][j], al[i], bh[j]);
                }
        }
        __syncthreads();
    }

    #pragma unroll
    for (int i = 0; i < 4; i++){
        int row = m0 + wm*64 + i*16 + (lane>>2);
        #pragma unroll
        for (int j = 0; j < 4; j++){
            int col = n0 + wn*32 + j*8 + 2*(lane&3);
            size_t o0 = (size_t)row*Dn + col;
            size_t o1 = (size_t)(row+8)*Dn + col;
            float2 v0, v1;
            v0.x = alpha*acc[i][j][0]; v0.y = alpha*acc[i][j][1];
            v1.x = alpha*acc[i][j][2]; v1.y = alpha*acc[i][j][3];
            if (R){
                float2 r0 = *(const float2*)(R + o0);
                float2 r1 = *(const float2*)(R + o1);
                v0.x += r0.x; v0.y += r0.y; v1.x += r1.x; v1.y += r1.y;
            }
            *(float2*)(C + o0) = v0;
            *(float2*)(C + o1) = v1;
        }
    }
}

// ---------------------------------------------------------------------------
// Block-kernel thread map (all 4 attention kernels):
//   row = tid & 63, part = tid >> 6. A warp's 32 lanes share `part` and span
//   32 rows -> streamed operand loads (LDS.128 on [64][68] tiles) are warp-
//   broadcast; per-row scalars on [64][65] tiles are bank-conflict-free.
// ---------------------------------------------------------------------------
#define PS 65
#define PV 68

// Local attention per (h, seg, b): masked logits -> joint, unmasked softmax,
// row_attn (fp32 + bf16 split).
__global__ void __launch_bounds__(256)
local_attn_kernel()
{
    extern __shared__ float sm[];
    float* qs  = sm;                 // [64*PS] q, reused for probs
    float* k4  = sm + 64*PS;         // [64*PV]
    float* v4  = k4 + 64*PV;         // [64*PV]
    float* red = v4 + 64*PV;         // [256]

    int h = blockIdx.x, seg = blockIdx.y, b = blockIdx.z;
    int tid = threadIdx.x;
    size_t tok0 = ((size_t)b*NSn + seg)*SEGn;

    for (int i = tid; i < 64*64; i += 256) {
        int r = i >> 6, c = i & 63;
        size_t off = (tok0 + r)*Dn + h*HDn + c;
        qs[r*PS+c] = g_q[off];
        k4[r*PV+c] = g_k[off];
        v4[r*PV+c] = g_v[off];
    }
    __syncthreads();

    int row = tid & 63, part = tid >> 6;
    const float4* kf = (const float4*)k4;
    float lg[16];
    #pragma unroll
    for (int c=0;c<16;c++) lg[c]=0.f;
    for (int d4 = 0; d4 < 16; d4++) {
        float q0 = qs[row*PS + d4*4+0];
        float q1 = qs[row*PS + d4*4+1];
        float q2 = qs[row*PS + d4*4+2];
        float q3 = qs[row*PS + d4*4+3];
        #pragma unroll
        for (int c=0;c<16;c++){
            float4 kv = kf[(part*16+c)*17 + d4];
            lg[c] += q0*kv.x + q1*kv.y + q2*kv.z + q3*kv.w;
        }
    }

    // masked logits -> joint (contiguous float4 per thread)
    size_t jb = ((tok0 + row)*Hn + h)*128 + part*16;
    #pragma unroll
    for (int c4=0;c4<4;c4++){
        float4 w;
        int c0 = part*16 + c4*4;
        w.x = lg[c4*4+0] + (row < c0+0 ? NEGV : 0.f);
        w.y = lg[c4*4+1] + (row < c0+1 ? NEGV : 0.f);
        w.z = lg[c4*4+2] + (row < c0+2 ? NEGV : 0.f);
        w.w = lg[c4*4+3] + (row < c0+3 ? NEGV : 0.f);
        *(float4*)(g_joint + jb + c4*4) = w;
    }

    // unmasked softmax: cross-part reduction via smem
    float m = -1e30f;
    #pragma unroll
    for (int c=0;c<16;c++) m = fmaxf(m, lg[c]);
    red[tid] = m;
    __syncthreads();
    float mm = fmaxf(fmaxf(red[row], red[64+row]), fmaxf(red[128+row], red[192+row]));
    float ssum = 0.f;
    #pragma unroll
    for (int c=0;c<16;c++){ lg[c] = __expf(lg[c]-mm); ssum += lg[c]; }
    __syncthreads();
    red[tid] = ssum;
    // store unnormalized probs into qs (logits phase done; all q reads complete)
    #pragma unroll
    for (int c=0;c<16;c++) qs[row*PS + part*16 + c] = lg[c];
    __syncthreads();
    float inv = 1.f/(red[row] + red[64+row] + red[128+row] + red[192+row]);

    // PV: o over dims part*16..+16
    const float4* vf = (const float4*)v4;
    float4 o[4];
    #pragma unroll
    for (int j=0;j<4;j++) o[j] = make_float4(0.f,0.f,0.f,0.f);
    for (int c2=0;c2<64;c2++){
        float p = qs[row*PS+c2];
        #pragma unroll
        for (int j4=0;j4<4;j4++){
            float4 vv = vf[c2*17 + part*4 + j4];
            o[j4].x += p*vv.x; o[j4].y += p*vv.y;
            o[j4].z += p*vv.z; o[j4].w += p*vv.w;
        }
    }
    size_t ob = (tok0+row)*Dn + h*HDn + part*16;
    #pragma unroll
    for (int j4=0;j4<4;j4++){
        float4 val;
        val.x = o[j4].x*inv; val.y = o[j4].y*inv;
        val.z = o[j4].z*inv; val.w = o[j4].w*inv;
        *(float4*)(g_rowattn + ob + j4*4) = val;
        store_split4(val, ob + j4*4);
    }
}

// ---------------------------------------------------------------------------
// LayerNorm over D=1024 per token: writes bf16 split directly
// ---------------------------------------------------------------------------
__global__ void __launch_bounds__(256)
ln_kernel(const float* __restrict__ scale, const float* __restrict__ bias)
{
    size_t row = blockIdx.x;
    int tid = threadIdx.x;
    float4 v = ((const float4*)(g_t1 + row*Dn))[tid];
    float s  = v.x+v.y+v.z+v.w;
    float ss = v.x*v.x+v.y*v.y+v.z*v.z+v.w*v.w;
    #pragma unroll
    for (int o=16;o;o>>=1){
        s  += __shfl_xor_sync(0xffffffffu, s, o);
        ss += __shfl_xor_sync(0xffffffffu, ss, o);
    }
    __shared__ float sh[16];
    int w = tid>>5, lane = tid&31;
    if (lane==0){ sh[w]=s; sh[8+w]=ss; }
    __syncthreads();
    if (tid==0){
        float a=0.f,b2=0.f;
        #pragma unroll
        for (int i=0;i<8;i++){ a+=sh[i]; b2+=sh[8+i]; }
        float mu  = a*(1.f/Dn);
        float var = b2*(1.f/Dn) - mu*mu;
        sh[0]=mu; sh[1]=rsqrtf(var + 1e-6f);
    }
    __syncthreads();
    float mu = sh[0], rstd = sh[1];
    float4 sc = ((const float4*)scale)[tid];
    float4 bi = ((const float4*)bias)[tid];
    float4 o4;
    o4.x=(v.x-mu)*rstd*sc.x+bi.x;
    o4.y=(v.y-mu)*rstd*sc.y+bi.y;
    o4.z=(v.z-mu)*rstd*sc.z+bi.z;
    o4.w=(v.w-mu)*rstd*sc.w+bi.w;
    store_split4(o4, row*Dn + tid*4);
}

// ---------------------------------------------------------------------------
// Global logits + fused joint softmax per (h, l, b)
// ---------------------------------------------------------------------------
__global__ void __launch_bounds__(256)
global_logits_kernel()
{
    __shared__ float qg [64*PS];
    __shared__ float kg4[64*PV];
    __shared__ float red[256];
    int h = blockIdx.x, l = blockIdx.y, b = blockIdx.z;
    int tid = threadIdx.x;
    for (int i = tid; i < 64*64; i += 256){
        int r = i>>6, c = i&63;
        size_t t = ((size_t)b*NSn + r)*SEGn + l;
        qg [r*PS+c] = g_q   [t*Dn + h*HDn + c];
        kg4[r*PV+c] = g_krow[t*Dn + h*HDn + c];
    }
    __syncthreads();

    int row = tid & 63, part = tid >> 6;   // row = qseg, part owns ksegs
    const float4* kf = (const float4*)kg4;
    float lg[16];
    #pragma unroll
    for (int c=0;c<16;c++) lg[c]=0.f;
    for (int d4=0; d4<16; d4++){
        float q0 = qg[row*PS + d4*4+0];
        float q1 = qg[row*PS + d4*4+1];
        float q2 = qg[row*PS + d4*4+2];
        float q3 = qg[row*PS + d4*4+3];
        #pragma unroll
        for (int c=0;c<16;c++){
            float4 kv = kf[(part*16+c)*17 + d4];
            lg[c] += q0*kv.x + q1*kv.y + q2*kv.z + q3*kv.w;
        }
    }
    #pragma unroll
    for (int c=0;c<16;c++){
        int col = part*16+c;
        lg[c] += (row <= col ? NEGV : 0.f);
    }

    // fused softmax over [local(64) | global(64)]
    size_t t  = ((size_t)b*NSn + row)*SEGn + l;
    size_t jb = (t*Hn + h)*128;
    float4 loc[4];
    #pragma unroll
    for (int j4=0;j4<4;j4++)
        loc[j4] = *(const float4*)(g_joint + jb + part*16 + j4*4);

    float m = -1e30f;
    #pragma unroll
    for (int c=0;c<16;c++) m = fmaxf(m, lg[c]);
    #pragma unroll
    for (int j4=0;j4<4;j4++)
        m = fmaxf(m, fmaxf(fmaxf(loc[j4].x,loc[j4].y),fmaxf(loc[j4].z,loc[j4].w)));
    red[tid] = m;
    __syncthreads();
    float mm = fmaxf(fmaxf(red[row], red[64+row]), fmaxf(red[128+row], red[192+row]));

    float ssum = 0.f;
    #pragma unroll
    for (int c=0;c<16;c++){ lg[c] = __expf(lg[c]-mm); ssum += lg[c]; }
    #pragma unroll
    for (int j4=0;j4<4;j4++){
        loc[j4].x = __expf(loc[j4].x-mm); loc[j4].y = __expf(loc[j4].y-mm);
        loc[j4].z = __expf(loc[j4].z-mm); loc[j4].w = __expf(loc[j4].w-mm);
        ssum += loc[j4].x+loc[j4].y+loc[j4].z+loc[j4].w;
    }
    __syncthreads();
    red[tid] = ssum;
    __syncthreads();
    float inv = 1.f/(red[row] + red[64+row] + red[128+row] + red[192+row]);

    #pragma unroll
    for (int j4=0;j4<4;j4++){
        loc[j4].x*=inv; loc[j4].y*=inv; loc[j4].z*=inv; loc[j4].w*=inv;
        *(float4*)(g_joint + jb + part*16 + j4*4) = loc[j4];
    }
    #pragma unroll
    for (int c4=0;c4<4;c4++){
        float4 w;
        w.x = lg[c4*4+0]*inv; w.y = lg[c4*4+1]*inv;
        w.z = lg[c4*4+2]*inv; w.w = lg[c4*4+3]*inv;
        *(float4*)(g_joint + jb + 64 + part*16 + c4*4) = w;
    }
}

// ---------------------------------------------------------------------------
// local_merged per (h, seg, b): merged = latt @ v (writes g_merged)
// ---------------------------------------------------------------------------
__global__ void __launch_bounds__(256)
local_merged_kernel()
{
    __shared__ float ps[64*PS];
    __shared__ float v4[64*PV];
    int h = blockIdx.x, seg = blockIdx.y, b = blockIdx.z;
    int tid = threadIdx.x;
    size_t tok0 = ((size_t)b*NSn + seg)*SEGn;
    for (int i=tid;i<64*64;i+=256){
        int r=i>>6,c=i&63;
        ps[r*PS+c] = g_joint[((tok0+r)*Hn+h)*128 + c];
        v4[r*PV+c] = g_v[(tok0+r)*Dn + h*HDn + c];
    }
    __syncthreads();
    int row = tid & 63, part = tid >> 6;
    const float4* vf = (const float4*)v4;
    float4 o[4];
    #pragma unroll
    for (int j=0;j<4;j++) o[j] = make_float4(0.f,0.f,0.f,0.f);
    for (int c=0;c<64;c++){
        float p = ps[row*PS+c];
        #pragma unroll
        for (int j4=0;j4<4;j4++){
            float4 vv = vf[c*17 + part*4 + j4];
            o[j4].x += p*vv.x; o[j4].y += p*vv.y;
            o[j4].z += p*vv.z; o[j4].w += p*vv.w;
        }
    }
    size_t ob = (tok0+row)*Dn + h*HDn + part*16;
    #pragma unroll
    for (int j4=0;j4<4;j4++)
        *(float4*)(g_merged + ob + j4*4) = o[j4];
}

// ---------------------------------------------------------------------------
// global_merged per (h, l, b): final merged = g_merged + gatt@row_attn,
// written only as bf16 split (consumed by output GEMM).
// ---------------------------------------------------------------------------
__global__ void __launch_bounds__(256)
global_merged_kernel()
{
    __shared__ float ga [64*PS];
    __shared__ float ra4[64*PV];
    int h = blockIdx.x, l = blockIdx.y, b = blockIdx.z;
    int tid = threadIdx.x;
    for (int i=tid;i<64*64;i+=256){
        int r=i>>6,c=i&63;
        size_t t = ((size_t)b*NSn + r)*SEGn + l;
        ga [r*PS+c] = g_joint[(t*Hn+h)*128 + 64 + c];
        ra4[r*PV+c] = g_rowattn[t*Dn + h*HDn + c];
    }
    __syncthreads();
    int row = tid & 63, part = tid >> 6;
    const float4* rf = (const float4*)ra4;
    float4 o[4];
    #pragma unroll
    for (int j=0;j<4;j++) o[j] = make_float4(0.f,0.f,0.f,0.f);
    for (int c=0;c<64;c++){
        float gv = ga[row*PS+c];
        #pragma unroll
        for (int j4=0;j4<4;j4++){
            float4 vv = rf[c*17 + part*4 + j4];
            o[j4].x += gv*vv.x; o[j4].y += gv*vv.y;
            o[j4].z += gv*vv.z; o[j4].w += gv*vv.w;
        }
    }
    size_t t  = ((size_t)b*NSn + row)*SEGn + l;
    size_t ob = t*Dn + h*HDn + part*16;
    #pragma unroll
    for (int j4=0;j4<4;j4++){
        float4 mv = *(const float4*)(g_merged + ob + j4*4);
        float4 val;
        val.x = mv.x + o[j4].x; val.y = mv.y + o[j4].y;
        val.z = mv.z + o[j4].z; val.w = mv.w + o[j4].w;
        store_split4(val, ob + j4*4);
    }
}

// ---------------------------------------------------------------------------
// Launch
// ---------------------------------------------------------------------------
extern "C" void kernel_launch(void* const* d_in, const int* in_sizes, int n_in,
                              void* d_out, int out_size)
{
    const float* x    = (const float*)d_in[0];
    const float* Wq   = (const float*)d_in[1];
    const float* Wk   = (const float*)d_in[2];
    const float* Wv   = (const float*)d_in[3];
    const float* Wro  = (const float*)d_in[4];
    const float* lns  = (const float*)d_in[5];
    const float* lnb  = (const float*)d_in[6];
    const float* Wk2  = (const float*)d_in[7];
    const float* Wout = (const float*)d_in[8];
    float* out = (float*)d_out;

    const int LA_SMEM = (64*PS + 2*64*PV + 256)*4;   // 52,480 B
    cudaFuncSetAttribute(local_attn_kernel,
                         cudaFuncAttributeMaxDynamicSharedMemorySize, LA_SMEM);
    cudaFuncSetAttribute(hmma_gemm,
                         cudaFuncAttributeMaxDynamicSharedMemorySize, HG_SMEM);

    dim3 gg(8, 128);
    dim3 gq(8, 128, 3);         // fused QKV
    dim3 ga(Hn, NSn, Bn);
    dim3 gl(Hn, SEGn, Bn);
    const int ACT_BLKS = (NTOK*Dn/4)/256;

    convert_wt<<<dim3(32,32,6),256>>>(Wq, Wk, Wv, Wro, Wk2, Wout);

    convert_act<<<ACT_BLKS,256>>>(x);
    hmma_gemm<<<gq,256,HG_SMEM>>>(-1, nullptr,0, nullptr, 0.f);     // q,k,v

    local_attn_kernel<<<ga,256,LA_SMEM>>>();                        // + rowattn split

    hmma_gemm<<<gg,256,HG_SMEM>>>(3, nullptr,4, x, 1.f);            // t1 = rowattn@Wro + x
    ln_kernel<<<NTOK,256>>>(lns, lnb);                              // -> ahi/alo
    hmma_gemm<<<gg,256,HG_SMEM>>>(4, nullptr,5, nullptr, 1.f);      // krow

    global_logits_kernel<<<gl,256>>>();                             // + joint softmax
    local_merged_kernel<<<ga,256>>>();
    global_merged_kernel<<<gl,256>>>();                             // + merged split

    hmma_gemm<<<gg,256,HG_SMEM>>>(5, out,0, nullptr, 1.f);
}

// round 10
// speedup vs baseline: 2.3214x; 1.0116x over previous
#include <cuda_runtime.h>
#include <cuda_bf16.h>
#include <math.h>
#include <stdint.h>

// Problem constants
#define Bn   4
#define Sn   4096
#define Dn   1024
#define Hn   16
#define HDn  64
#define SEGn 64
#define NSn  64
#define NTOK (Bn*Sn)          // 16384
#define NEGV (-1.0e10f)

// ---------------------------------------------------------------------------
// Scratch (device globals)
// ---------------------------------------------------------------------------
__device__ float g_q      [(size_t)NTOK*Dn];
__device__ float g_k      [(size_t)NTOK*Dn];
__device__ float g_v      [(size_t)NTOK*Dn];
__device__ float g_rowattn[(size_t)NTOK*Dn];
__device__ float g_t1     [(size_t)NTOK*Dn];
__device__ float g_krow   [(size_t)NTOK*Dn];
__device__ float g_merged [(size_t)NTOK*Dn];   // global_merged partial
__device__ float g_joint  [(size_t)NTOK*Hn*128]; // [0:64] local logits -> local probs

// Split-bf16 staging
__device__ __nv_bfloat16 g_ahi [(size_t)NTOK*Dn];
__device__ __nv_bfloat16 g_alo [(size_t)NTOK*Dn];
__device__ __nv_bfloat16 g_wthi[(size_t)6*Dn*Dn];   // WT[w][n][k] = W[w][k][n]
__device__ __nv_bfloat16 g_wtlo[(size_t)6*Dn*Dn];

__device__ __forceinline__ float* cpick(float* ext, int id){
    switch(id){ case 1: return g_q; case 2: return g_k; case 3: return g_v;
                case 4: return g_t1; case 5: return g_krow; }
    return ext;
}

// vector split store: 4 consecutive values at 4-aligned offset
__device__ __forceinline__ void store_split4(float4 v, size_t off){
    __nv_bfloat16 h0=__float2bfloat16_rn(v.x), h1=__float2bfloat16_rn(v.y);
    __nv_bfloat16 h2=__float2bfloat16_rn(v.z), h3=__float2bfloat16_rn(v.w);
    __nv_bfloat16 l0=__float2bfloat16_rn(v.x-__bfloat162float(h0));
    __nv_bfloat16 l1=__float2bfloat16_rn(v.y-__bfloat162float(h1));
    __nv_bfloat16 l2=__float2bfloat16_rn(v.z-__bfloat162float(h2));
    __nv_bfloat16 l3=__float2bfloat16_rn(v.w-__bfloat162float(h3));
    __nv_bfloat162 hp0(h0,h1), hp1(h2,h3), lp0(l0,l1), lp1(l2,l3);
    uint2 hv, lv;
    hv.x=*(uint32_t*)&hp0; hv.y=*(uint32_t*)&hp1;
    lv.x=*(uint32_t*)&lp0; lv.y=*(uint32_t*)&lp1;
    *(uint2*)(g_ahi + off) = hv;
    *(uint2*)(g_alo + off) = lv;
}

__device__ __forceinline__ uint32_t smem_u32(const void* p){
    uint32_t a;
    asm("{ .reg .u64 t; cvta.to.shared.u64 t, %1; cvt.u32.u64 %0, t; }" : "=r"(a) : "l"(p));
    return a;
}
__device__ __forceinline__ void cp_async16(uint32_t dst, const void* src){
    asm volatile("cp.async.cg.shared.global [%0], [%1], 16;" :: "r"(dst), "l"(src) : "memory");
}
__device__ __forceinline__ void cp_commit(){
    asm volatile("cp.async.commit_group;" ::: "memory");
}
template<int N> __device__ __forceinline__ void cp_wait(){
    asm volatile("cp.async.wait_group %0;" :: "n"(N) : "memory");
}
__device__ __forceinline__ void mma16816(float* c, const uint32_t* a, const uint32_t* b){
    asm volatile("mma.sync.aligned.m16n8k16.row.col.f32.bf16.bf16.f32 "
                 "{%0,%1,%2,%3}, {%4,%5,%6,%7}, {%8,%9}, {%0,%1,%2,%3};"
                 : "+f"(c[0]), "+f"(c[1]), "+f"(c[2]), "+f"(c[3])
                 : "r"(a[0]), "r"(a[1]), "r"(a[2]), "r"(a[3]), "r"(b[0]), "r"(b[1]));
}

// ---------------------------------------------------------------------------
// Split conversion: x fp32 -> (hi,lo) bf16
// ---------------------------------------------------------------------------
__global__ void __launch_bounds__(256)
convert_act(const float* __restrict__ src)
{
    size_t i = (size_t)blockIdx.x*256 + threadIdx.x;
    float4 v = ((const float4*)src)[i];
    store_split4(v, i*4);
}

// ---------------------------------------------------------------------------
// Weight transpose+split: WT[w][n][k] = split(W[w][k][n])
// ---------------------------------------------------------------------------
__global__ void __launch_bounds__(256)
convert_wt(const float* __restrict__ W0, const float* __restrict__ W1,
           const float* __restrict__ W2, const float* __restrict__ W3,
           const float* __restrict__ W4, const float* __restrict__ W5)
{
    const float* Ws[6] = {W0,W1,W2,W3,W4,W5};
    const float* W = Ws[blockIdx.z];
    __shared__ float tile[32][33];
    int n0 = blockIdx.x*32, k0 = blockIdx.y*32;
    int tx = threadIdx.x & 31, ty = threadIdx.x >> 5;
    #pragma unroll
    for (int j = 0; j < 4; j++){
        int r = ty + j*8;
        tile[r][tx] = W[(size_t)(k0+r)*Dn + n0 + tx];
    }
    __syncthreads();
    size_t wbase = (size_t)blockIdx.z*Dn*Dn;
    #pragma unroll
    for (int j = 0; j < 4; j++){
        int r = ty + j*8;
        float a = tile[tx][r];
        __nv_bfloat16 hi = __float2bfloat16_rn(a);
        __nv_bfloat16 lo = __float2bfloat16_rn(a - __bfloat162float(hi));
        size_t o = wbase + (size_t)(n0+r)*Dn + k0 + tx;
        g_wthi[o] = hi;
        g_wtlo[o] = lo;
    }
}

// ---------------------------------------------------------------------------
// HMMA GEMM (unchanged, BK=32, occ 2, fused-QKV mode)
// ---------------------------------------------------------------------------
#define AST  40
#define TSZB (128*AST*2)          // 10240 B per matrix
#define BUFB (4*TSZB)             // 40960 B per buffer
#define HG_SMEM (2*BUFB)          // 81920 B

__global__ void __launch_bounds__(256,2)
hmma_gemm(int widx, float* Cext, int Cid, const float* __restrict__ R, float alpha)
{
    extern __shared__ char smem[];
    uint32_t sb = smem_u32(smem);
    int tid = threadIdx.x, lane = tid & 31, wid = tid >> 5;
    int wm = wid & 1, wn = wid >> 1;
    int m0 = blockIdx.y*128, n0 = blockIdx.x*128;

    if (widx < 0){
        widx = blockIdx.z;
        Cid  = blockIdx.z + 1;
        alpha = (blockIdx.z == 0) ? 0.125f : 1.f;
    }
    float* C = cpick(Cext, Cid);

    const __nv_bfloat16* srcs[4];
    srcs[0] = g_ahi  + (size_t)m0*Dn;
    srcs[1] = g_alo  + (size_t)m0*Dn;
    srcs[2] = g_wthi + (size_t)widx*Dn*Dn + (size_t)n0*Dn;
    srcs[3] = g_wtlo + (size_t)widx*Dn*Dn + (size_t)n0*Dn;

    auto fill = [&](int c, int buf){
        int k0 = c*32;
        uint32_t base = sb + buf*BUFB;
        #pragma unroll
        for (int t = 0; t < 4; t++){
            #pragma unroll
            for (int it = 0; it < 2; it++){
                int idx = it*256 + tid;
                int r = idx >> 2, cc = idx & 3;
                cp_async16(base + t*TSZB + r*(AST*2) + cc*16,
                           srcs[t] + (size_t)r*Dn + k0 + cc*8);
            }
        }
        cp_commit();
    };

    float acc[4][4][4];
    #pragma unroll
    for (int i=0;i<4;i++)
        #pragma unroll
        for (int j=0;j<4;j++)
            #pragma unroll
            for (int q=0;q<4;q++) acc[i][j][q]=0.f;

    fill(0, 0);

    for (int c = 0; c < 32; c++){
        int buf = c & 1;
        if (c < 31){ fill(c+1, buf^1); cp_wait<1>(); }
        else       { cp_wait<0>(); }
        __syncthreads();

        const __nv_bfloat16* Ah = (const __nv_bfloat16*)(smem + buf*BUFB);
        const __nv_bfloat16* Al = (const __nv_bfloat16*)(smem + buf*BUFB + TSZB);
        const __nv_bfloat16* Bh = (const __nv_bfloat16*)(smem + buf*BUFB + 2*TSZB);
        const __nv_bfloat16* Bl = (const __nv_bfloat16*)(smem + buf*BUFB + 3*TSZB);

        #pragma unroll
        for (int ks = 0; ks < 2; ks++){
            int k16 = ks*16;
            uint32_t ah[4][4], al[4][4], bh[4][2], bl[4][2];
            #pragma unroll
            for (int i = 0; i < 4; i++){
                int row = wm*64 + i*16 + (lane>>2);
                int off = row*AST + k16 + 2*(lane&3);
                ah[i][0] = *(const uint32_t*)(Ah + off);
                ah[i][1] = *(const uint32_t*)(Ah + off + 8*AST);
                ah[i][2] = *(const uint32_t*)(Ah + off + 8);
                ah[i][3] = *(const uint32_t*)(Ah + off + 8*AST + 8);
                al[i][0] = *(const uint32_t*)(Al + off);
                al[i][1] = *(const uint32_t*)(Al + off + 8*AST);
                al[i][2] = *(const uint32_t*)(Al + off + 8);
                al[i][3] = *(const uint32_t*)(Al + off + 8*AST + 8);
            }
            #pragma unroll
            for (int j = 0; j < 4; j++){
                int nrow = wn*32 + j*8 + (lane>>2);
                int off = nrow*AST + k16 + 2*(lane&3);
                bh[j][0] = *(const uint32_t*)(Bh + off);
                bh[j][1] = *(const uint32_t*)(Bh + off + 8);
                bl[j][0] = *(const uint32_t*)(Bl + off);
                bl[j][1] = *(const uint32_t*)(Bl + off + 8);
            }
            #pragma unroll
            for (int i = 0; i < 4; i++)
                #pragma unroll
                for (int j = 0; j < 4; j++){
                    mma16816(acc[i][j], ah[i], bh[j]);
                    mma16816(acc[i][j], ah[i], bl[j]);
                    mma16816(acc[i][j], al[i], bh[j]);
                }
        }
        __syncthreads();
    }

    #pragma unroll
    for (int i = 0; i < 4; i++){
        int row = m0 + wm*64 + i*16 + (lane>>2);
        #pragma unroll
        for (int j = 0; j < 4; j++){
            int col = n0 + wn*32 + j*8 + 2*(lane&3);
            size_t o0 = (size_t)row*Dn + col;
            size_t o1 = (size_t)(row+8)*Dn + col;
            float2 v0, v1;
            v0.x = alpha*acc[i][j][0]; v0.y = alpha*acc[i][j][1];
            v1.x = alpha*acc[i][j][2]; v1.y = alpha*acc[i][j][3];
            if (R){
                float2 r0 = *(const float2*)(R + o0);
                float2 r1 = *(const float2*)(R + o1);
                v0.x += r0.x; v0.y += r0.y; v1.x += r1.x; v1.y += r1.y;
            }
            *(float2*)(C + o0) = v0;
            *(float2*)(C + o1) = v1;
        }
    }
}

// ---------------------------------------------------------------------------
// Block-kernel thread map: row = tid & 63, part = tid >> 6. Streamed operands
// are warp-broadcast LDS.128 on [64][68] tiles; per-row scalars conflict-free.
// ---------------------------------------------------------------------------
#define PV 68

// Local attention per (h, seg, b): masked logits -> joint, unmasked softmax,
// row_attn (fp32 + bf16 split).
__global__ void __launch_bounds__(256)
local_attn_kernel()
{
    extern __shared__ float sm[];
    float* qs  = sm;                 // [64*PV] q, reused for probs
    float* k4  = sm + 64*PV;
    float* v4  = k4 + 64*PV;
    float* red = v4 + 64*PV;         // [256]

    int h = blockIdx.x, seg = blockIdx.y, b = blockIdx.z;
    int tid = threadIdx.x;
    size_t tok0 = ((size_t)b*NSn + seg)*SEGn;

    for (int i = tid; i < 64*64; i += 256) {
        int r = i >> 6, c = i & 63;
        size_t off = (tok0 + r)*Dn + h*HDn + c;
        qs[r*PV+c] = g_q[off];
        k4[r*PV+c] = g_k[off];
        v4[r*PV+c] = g_v[off];
    }
    __syncthreads();

    int row = tid & 63, part = tid >> 6;
    const float4* qf = (const float4*)qs;
    const float4* kf = (const float4*)k4;
    float lg[16];
    #pragma unroll
    for (int c=0;c<16;c++) lg[c]=0.f;
    for (int d4 = 0; d4 < 16; d4++) {
        float4 qv = qf[row*17 + d4];
        #pragma unroll
        for (int c=0;c<16;c++){
            float4 kv = kf[(part*16+c)*17 + d4];
            lg[c] += qv.x*kv.x + qv.y*kv.y + qv.z*kv.z + qv.w*kv.w;
        }
    }

    // masked logits -> joint
    size_t jb = ((tok0 + row)*Hn + h)*128 + part*16;
    #pragma unroll
    for (int c4=0;c4<4;c4++){
        float4 w;
        int c0 = part*16 + c4*4;
        w.x = lg[c4*4+0] + (row < c0+0 ? NEGV : 0.f);
        w.y = lg[c4*4+1] + (row < c0+1 ? NEGV : 0.f);
        w.z = lg[c4*4+2] + (row < c0+2 ? NEGV : 0.f);
        w.w = lg[c4*4+3] + (row < c0+3 ? NEGV : 0.f);
        *(float4*)(g_joint + jb + c4*4) = w;
    }

    // unmasked softmax: cross-part reduction via smem
    float m = -1e30f;
    #pragma unroll
    for (int c=0;c<16;c++) m = fmaxf(m, lg[c]);
    red[tid] = m;
    __syncthreads();
    float mm = fmaxf(fmaxf(red[row], red[64+row]), fmaxf(red[128+row], red[192+row]));
    float ssum = 0.f;
    #pragma unroll
    for (int c=0;c<16;c++){ lg[c] = __expf(lg[c]-mm); ssum += lg[c]; }
    __syncthreads();
    red[tid] = ssum;
    // unnormalized probs into qs (all q reads complete)
    float* qw = qs + row*PV + part*16;
    #pragma unroll
    for (int c4=0;c4<4;c4++)
        *(float4*)(qw + c4*4) = make_float4(lg[c4*4], lg[c4*4+1], lg[c4*4+2], lg[c4*4+3]);
    __syncthreads();
    float inv = 1.f/(red[row] + red[64+row] + red[128+row] + red[192+row]);

    // PV over dims part*16..+16
    const float4* vf = (const float4*)v4;
    float4 o[4];
    #pragma unroll
    for (int j=0;j<4;j++) o[j] = make_float4(0.f,0.f,0.f,0.f);
    for (int c2=0;c2<64;c2++){
        float p = qs[row*PV+c2];
        #pragma unroll
        for (int j4=0;j4<4;j4++){
            float4 vv = vf[c2*17 + part*4 + j4];
            o[j4].x += p*vv.x; o[j4].y += p*vv.y;
            o[j4].z += p*vv.z; o[j4].w += p*vv.w;
        }
    }
    size_t ob = (tok0+row)*Dn + h*HDn + part*16;
    #pragma unroll
    for (int j4=0;j4<4;j4++){
        float4 val;
        val.x = o[j4].x*inv; val.y = o[j4].y*inv;
        val.z = o[j4].z*inv; val.w = o[j4].w*inv;
        *(float4*)(g_rowattn + ob + j4*4) = val;
        store_split4(val, ob + j4*4);
    }
}

// ---------------------------------------------------------------------------
// LayerNorm over D=1024 per token: writes bf16 split directly
// ---------------------------------------------------------------------------
__global__ void __launch_bounds__(256)
ln_kernel(const float* __restrict__ scale, const float* __restrict__ bias)
{
    size_t row = blockIdx.x;
    int tid = threadIdx.x;
    float4 v = ((const float4*)(g_t1 + row*Dn))[tid];
    float s  = v.x+v.y+v.z+v.w;
    float ss = v.x*v.x+v.y*v.y+v.z*v.z+v.w*v.w;
    #pragma unroll
    for (int o=16;o;o>>=1){
        s  += __shfl_xor_sync(0xffffffffu, s, o);
        ss += __shfl_xor_sync(0xffffffffu, ss, o);
    }
    __shared__ float sh[16];
    int w = tid>>5, lane = tid&31;
    if (lane==0){ sh[w]=s; sh[8+w]=ss; }
    __syncthreads();
    if (tid==0){
        float a=0.f,b2=0.f;
        #pragma unroll
        for (int i=0;i<8;i++){ a+=sh[i]; b2+=sh[8+i]; }
        float mu  = a*(1.f/Dn);
        float var = b2*(1.f/Dn) - mu*mu;
        sh[0]=mu; sh[1]=rsqrtf(var + 1e-6f);
    }
    __syncthreads();
    float mu = sh[0], rstd = sh[1];
    float4 sc = ((const float4*)scale)[tid];
    float4 bi = ((const float4*)bias)[tid];
    float4 o4;
    o4.x=(v.x-mu)*rstd*sc.x+bi.x;
    o4.y=(v.y-mu)*rstd*sc.y+bi.y;
    o4.z=(v.z-mu)*rstd*sc.z+bi.z;
    o4.w=(v.w-mu)*rstd*sc.w+bi.w;
    store_split4(o4, row*Dn + tid*4);
}

// ---------------------------------------------------------------------------
// FUSED global logits + joint softmax + global merge, per (h, l, b).
// Writes: normalized local probs -> g_joint[0:64]; global merge -> g_merged.
// ---------------------------------------------------------------------------
__global__ void __launch_bounds__(256)
global_fused_kernel()
{
    extern __shared__ float sm[];
    float* qg  = sm;                 // [64*PV] q, reused for gatt probs
    float* kg  = sm + 64*PV;         // krow
    float* ra  = kg + 64*PV;         // rowattn
    float* red = ra + 64*PV;         // [256]

    int h = blockIdx.x, l = blockIdx.y, b = blockIdx.z;
    int tid = threadIdx.x;
    for (int i = tid; i < 64*64; i += 256){
        int r = i>>6, c = i&63;
        size_t t = ((size_t)b*NSn + r)*SEGn + l;
        size_t off = t*Dn + h*HDn + c;
        qg[r*PV+c] = g_q[off];
        kg[r*PV+c] = g_krow[off];
        ra[r*PV+c] = g_rowattn[off];
    }
    __syncthreads();

    int row = tid & 63, part = tid >> 6;   // row = qseg
    const float4* qf = (const float4*)qg;
    const float4* kf = (const float4*)kg;
    float lg[16];
    #pragma unroll
    for (int c=0;c<16;c++) lg[c]=0.f;
    for (int d4=0; d4<16; d4++){
        float4 qv = qf[row*17 + d4];
        #pragma unroll
        for (int c=0;c<16;c++){
            float4 kv = kf[(part*16+c)*17 + d4];
            lg[c] += qv.x*kv.x + qv.y*kv.y + qv.z*kv.z + qv.w*kv.w;
        }
    }
    #pragma unroll
    for (int c=0;c<16;c++){
        int col = part*16+c;
        lg[c] += (row <= col ? NEGV : 0.f);
    }

    // fused softmax over [local(64) | global(64)]
    size_t t  = ((size_t)b*NSn + row)*SEGn + l;
    size_t jb = (t*Hn + h)*128;
    float4 loc[4];
    #pragma unroll
    for (int j4=0;j4<4;j4++)
        loc[j4] = *(const float4*)(g_joint + jb + part*16 + j4*4);

    float m = -1e30f;
    #pragma unroll
    for (int c=0;c<16;c++) m = fmaxf(m, lg[c]);
    #pragma unroll
    for (int j4=0;j4<4;j4++)
        m = fmaxf(m, fmaxf(fmaxf(loc[j4].x,loc[j4].y),fmaxf(loc[j4].z,loc[j4].w)));
    red[tid] = m;
    __syncthreads();
    float mm = fmaxf(fmaxf(red[row], red[64+row]), fmaxf(red[128+row], red[192+row]));

    float ssum = 0.f;
    #pragma unroll
    for (int c=0;c<16;c++){ lg[c] = __expf(lg[c]-mm); ssum += lg[c]; }
    #pragma unroll
    for (int j4=0;j4<4;j4++){
        loc[j4].x = __expf(loc[j4].x-mm); loc[j4].y = __expf(loc[j4].y-mm);
        loc[j4].z = __expf(loc[j4].z-mm); loc[j4].w = __expf(loc[j4].w-mm);
        ssum += loc[j4].x+loc[j4].y+loc[j4].z+loc[j4].w;
    }
    __syncthreads();
    red[tid] = ssum;
    __syncthreads();
    float inv = 1.f/(red[row] + red[64+row] + red[128+row] + red[192+row]);

    // normalized local probs -> joint (for local_merged finalizer)
    #pragma unroll
    for (int j4=0;j4<4;j4++){
        loc[j4].x*=inv; loc[j4].y*=inv; loc[j4].z*=inv; loc[j4].w*=inv;
        *(float4*)(g_joint + jb + part*16 + j4*4) = loc[j4];
    }

    // gatt probs into qg (q reads complete), then merge with rowattn
    __syncthreads();
    float* qw = qg + row*PV + part*16;
    #pragma unroll
    for (int c4=0;c4<4;c4++)
        *(float4*)(qw + c4*4) = make_float4(lg[c4*4]*inv, lg[c4*4+1]*inv,
                                            lg[c4*4+2]*inv, lg[c4*4+3]*inv);
    __syncthreads();

    const float4* rf = (const float4*)ra;
    float4 o[4];
    #pragma unroll
    for (int j=0;j<4;j++) o[j] = make_float4(0.f,0.f,0.f,0.f);
    for (int c=0;c<64;c++){
        float gv = qg[row*PV+c];
        #pragma unroll
        for (int j4=0;j4<4;j4++){
            float4 vv = rf[c*17 + part*4 + j4];
            o[j4].x += gv*vv.x; o[j4].y += gv*vv.y;
            o[j4].z += gv*vv.z; o[j4].w += gv*vv.w;
        }
    }
    size_t ob = t*Dn + h*HDn + part*16;
    #pragma unroll
    for (int j4=0;j4<4;j4++)
        *(float4*)(g_merged + ob + j4*4) = o[j4];
}

// ---------------------------------------------------------------------------
// local_merged finalizer per (h, seg, b): merged = g_merged + latt@v,
// written only as bf16 split (consumed by output GEMM).
// ---------------------------------------------------------------------------
__global__ void __launch_bounds__(256)
local_merged_kernel()
{
    __shared__ float ps[64*PV];
    __shared__ float v4[64*PV];
    int h = blockIdx.x, seg = blockIdx.y, b = blockIdx.z;
    int tid = threadIdx.x;
    size_t tok0 = ((size_t)b*NSn + seg)*SEGn;
    for (int i=tid;i<64*64;i+=256){
        int r=i>>6,c=i&63;
        ps[r*PV+c] = g_joint[((tok0+r)*Hn+h)*128 + c];
        v4[r*PV+c] = g_v[(tok0+r)*Dn + h*HDn + c];
    }
    __syncthreads();
    int row = tid & 63, part = tid >> 6;
    const float4* vf = (const float4*)v4;
    float4 o[4];
    #pragma unroll
    for (int j=0;j<4;j++) o[j] = make_float4(0.f,0.f,0.f,0.f);
    for (int c=0;c<64;c++){
        float p = ps[row*PV+c];
        #pragma unroll
        for (int j4=0;j4<4;j4++){
            float4 vv = vf[c*17 + part*4 + j4];
            o[j4].x += p*vv.x; o[j4].y += p*vv.y;
            o[j4].z += p*vv.z; o[j4].w += p*vv.w;
        }
    }
    size_t ob = (tok0+row)*Dn + h*HDn + part*16;
    #pragma unroll
    for (int j4=0;j4<4;j4++){
        float4 mv = *(const float4*)(g_merged + ob + j4*4);
        float4 val;
        val.x = mv.x + o[j4].x; val.y = mv.y + o[j4].y;
        val.z = mv.z + o[j4].z; val.w = mv.w + o[j4].w;
        store_split4(val, ob + j4*4);
    }
}

// ---------------------------------------------------------------------------
// Launch
// ---------------------------------------------------------------------------
extern "C" void kernel_launch(void* const* d_in, const int* in_sizes, int n_in,
                              void* d_out, int out_size)
{
    const float* x    = (const float*)d_in[0];
    const float* Wq   = (const float*)d_in[1];
    const float* Wk   = (const float*)d_in[2];
    const float* Wv   = (const float*)d_in[3];
    const float* Wro  = (const float*)d_in[4];
    const float* lns  = (const float*)d_in[5];
    const float* lnb  = (const float*)d_in[6];
    const float* Wk2  = (const float*)d_in[7];
    const float* Wout = (const float*)d_in[8];
    float* out = (float*)d_out;

    const int BK_SMEM = (3*64*PV + 256)*4;   // 53,248 B
    cudaFuncSetAttribute(local_attn_kernel,
                         cudaFuncAttributeMaxDynamicSharedMemorySize, BK_SMEM);
    cudaFuncSetAttribute(global_fused_kernel,
                         cudaFuncAttributeMaxDynamicSharedMemorySize, BK_SMEM);
    cudaFuncSetAttribute(hmma_gemm,
                         cudaFuncAttributeMaxDynamicSharedMemorySize, HG_SMEM);

    dim3 gg(8, 128);
    dim3 gq(8, 128, 3);         // fused QKV
    dim3 ga(Hn, NSn, Bn);
    dim3 gl(Hn, SEGn, Bn);
    const int ACT_BLKS = (NTOK*Dn/4)/256;

    convert_wt<<<dim3(32,32,6),256>>>(Wq, Wk, Wv, Wro, Wk2, Wout);

    convert_act<<<ACT_BLKS,256>>>(x);
    hmma_gemm<<<gq,256,HG_SMEM>>>(-1, nullptr,0, nullptr, 0.f);     // q,k,v

    local_attn_kernel<<<ga,256,BK_SMEM>>>();                        // + rowattn split

    hmma_gemm<<<gg,256,HG_SMEM>>>(3, nullptr,4, x, 1.f);            // t1 = rowattn@Wro + x
    ln_kernel<<<NTOK,256>>>(lns, lnb);                              // -> ahi/alo
    hmma_gemm<<<gg,256,HG_SMEM>>>(4, nullptr,5, nullptr, 1.f);      // krow

    global_fused_kernel<<<gl,256,BK_SMEM>>>();                      // logits+softmax+gmerge
    local_merged_kernel<<<ga,256>>>();                              // finalize + split

    hmma_gemm<<<gg,256,HG_SMEM>>>(5, out,0, nullptr, 1.f);
}

// round 12
// speedup vs baseline: 2.4925x; 1.0737x over previous
#include <cuda_runtime.h>
#include <cuda_bf16.h>
#include <math.h>
#include <stdint.h>

// Problem constants
#define Bn   4
#define Sn   4096
#define Dn   1024
#define Hn   16
#define HDn  64
#define SEGn 64
#define NSn  64
#define NTOK (Bn*Sn)          // 16384
#define NEGV (-1.0e10f)

// ---------------------------------------------------------------------------
// Scratch (device globals)
// ---------------------------------------------------------------------------
__device__ float g_q      [(size_t)NTOK*Dn];
__device__ float g_k      [(size_t)NTOK*Dn];
__device__ float g_v      [(size_t)NTOK*Dn];
__device__ float g_rowattn[(size_t)NTOK*Dn];
__device__ float g_t1     [(size_t)NTOK*Dn];
__device__ float g_krow   [(size_t)NTOK*Dn];
__device__ float g_merged [(size_t)NTOK*Dn];   // global_merged partial
__device__ float g_joint  [(size_t)NTOK*Hn*128]; // [0:64] local logits -> local probs

// Split-bf16 staging
__device__ __nv_bfloat16 g_ahi [(size_t)NTOK*Dn];
__device__ __nv_bfloat16 g_alo [(size_t)NTOK*Dn];
__device__ __nv_bfloat16 g_wthi[(size_t)6*Dn*Dn];   // WT[w][n][k] = W[w][k][n]
__device__ __nv_bfloat16 g_wtlo[(size_t)6*Dn*Dn];

__device__ __forceinline__ float* cpick(float* ext, int id){
    switch(id){ case 1: return g_q; case 2: return g_k; case 3: return g_v;
                case 4: return g_t1; case 5: return g_krow; }
    return ext;
}

__device__ __forceinline__ uint32_t pack_hi(float a, float b){
    __nv_bfloat162 t(__float2bfloat16_rn(a), __float2bfloat16_rn(b));
    return *(uint32_t*)&t;
}
__device__ __forceinline__ uint32_t pack_lo(float a, float b){
    float ha = __bfloat162float(__float2bfloat16_rn(a));
    float hb = __bfloat162float(__float2bfloat16_rn(b));
    __nv_bfloat162 t(__float2bfloat16_rn(a-ha), __float2bfloat16_rn(b-hb));
    return *(uint32_t*)&t;
}
// split store of 2 consecutive values (off must be even)
__device__ __forceinline__ void store_split2(float a, float b, size_t off){
    *(uint32_t*)(g_ahi + off) = pack_hi(a,b);
    *(uint32_t*)(g_alo + off) = pack_lo(a,b);
}
// vector split store: 4 consecutive values at 4-aligned offset
__device__ __forceinline__ void store_split4(float4 v, size_t off){
    uint2 hv, lv;
    hv.x = pack_hi(v.x,v.y); hv.y = pack_hi(v.z,v.w);
    lv.x = pack_lo(v.x,v.y); lv.y = pack_lo(v.z,v.w);
    *(uint2*)(g_ahi + off) = hv;
    *(uint2*)(g_alo + off) = lv;
}

__device__ __forceinline__ uint32_t smem_u32(const void* p){
    uint32_t a;
    asm("{ .reg .u64 t; cvta.to.shared.u64 t, %1; cvt.u32.u64 %0, t; }" : "=r"(a) : "l"(p));
    return a;
}
__device__ __forceinline__ void cp_async16(uint32_t dst, const void* src){
    asm volatile("cp.async.cg.shared.global [%0], [%1], 16;" :: "r"(dst), "l"(src) : "memory");
}
__device__ __forceinline__ void cp_commit(){
    asm volatile("cp.async.commit_group;" ::: "memory");
}
template<int N> __device__ __forceinline__ void cp_wait(){
    asm volatile("cp.async.wait_group %0;" :: "n"(N) : "memory");
}
__device__ __forceinline__ void mma16816(float* c, const uint32_t* a, const uint32_t* b){
    asm volatile("mma.sync.aligned.m16n8k16.row.col.f32.bf16.bf16.f32 "
                 "{%0,%1,%2,%3}, {%4,%5,%6,%7}, {%8,%9}, {%0,%1,%2,%3};"
                 : "+f"(c[0]), "+f"(c[1]), "+f"(c[2]), "+f"(c[3])
                 : "r"(a[0]), "r"(a[1]), "r"(a[2]), "r"(a[3]), "r"(b[0]), "r"(b[1]));
}

// ---------------------------------------------------------------------------
// Split conversion: x fp32 -> (hi,lo) bf16
// ---------------------------------------------------------------------------
__global__ void __launch_bounds__(256)
convert_act(const float* __restrict__ src)
{
    size_t i = (size_t)blockIdx.x*256 + threadIdx.x;
    float4 v = ((const float4*)src)[i];
    store_split4(v, i*4);
}

// ---------------------------------------------------------------------------
// Weight transpose+split: WT[w][n][k] = split(W[w][k][n])
// ---------------------------------------------------------------------------
__global__ void __launch_bounds__(256)
convert_wt(const float* __restrict__ W0, const float* __restrict__ W1,
           const float* __restrict__ W2, const float* __restrict__ W3,
           const float* __restrict__ W4, const float* __restrict__ W5)
{
    const float* Ws[6] = {W0,W1,W2,W3,W4,W5};
    const float* W = Ws[blockIdx.z];
    __shared__ float tile[32][33];
    int n0 = blockIdx.x*32, k0 = blockIdx.y*32;
    int tx = threadIdx.x & 31, ty = threadIdx.x >> 5;
    #pragma unroll
    for (int j = 0; j < 4; j++){
        int r = ty + j*8;
        tile[r][tx] = W[(size_t)(k0+r)*Dn + n0 + tx];
    }
    __syncthreads();
    size_t wbase = (size_t)blockIdx.z*Dn*Dn;
    #pragma unroll
    for (int j = 0; j < 4; j++){
        int r = ty + j*8;
        float a = tile[tx][r];
        __nv_bfloat16 hi = __float2bfloat16_rn(a);
        __nv_bfloat16 lo = __float2bfloat16_rn(a - __bfloat162float(hi));
        size_t o = wbase + (size_t)(n0+r)*Dn + k0 + tx;
        g_wthi[o] = hi;
        g_wtlo[o] = lo;
    }
}

// ---------------------------------------------------------------------------
// HMMA GEMM (unchanged, BK=32, occ 2, fused-QKV mode)
// ---------------------------------------------------------------------------
#define AST  40
#define TSZB (128*AST*2)          // 10240 B per matrix
#define BUFB (4*TSZB)             // 40960 B per buffer
#define HG_SMEM (2*BUFB)          // 81920 B

__global__ void __launch_bounds__(256,2)
hmma_gemm(int widx, float* Cext, int Cid, const float* __restrict__ R, float alpha)
{
    extern __shared__ char smem[];
    uint32_t sb = smem_u32(smem);
    int tid = threadIdx.x, lane = tid & 31, wid = tid >> 5;
    int wm = wid & 1, wn = wid >> 1;
    int m0 = blockIdx.y*128, n0 = blockIdx.x*128;

    if (widx < 0){
        widx = blockIdx.z;
        Cid  = blockIdx.z + 1;
        alpha = (blockIdx.z == 0) ? 0.125f : 1.f;
    }
    float* C = cpick(Cext, Cid);

    const __nv_bfloat16* srcs[4];
    srcs[0] = g_ahi  + (size_t)m0*Dn;
    srcs[1] = g_alo  + (size_t)m0*Dn;
    srcs[2] = g_wthi + (size_t)widx*Dn*Dn + (size_t)n0*Dn;
    srcs[3] = g_wtlo + (size_t)widx*Dn*Dn + (size_t)n0*Dn;

    auto fill = [&](int c, int buf){
        int k0 = c*32;
        uint32_t base = sb + buf*BUFB;
        #pragma unroll
        for (int t = 0; t < 4; t++){
            #pragma unroll
            for (int it = 0; it < 2; it++){
                int idx = it*256 + tid;
                int r = idx >> 2, cc = idx & 3;
                cp_async16(base + t*TSZB + r*(AST*2) + cc*16,
                           srcs[t] + (size_t)r*Dn + k0 + cc*8);
            }
        }
        cp_commit();
    };

    float acc[4][4][4];
    #pragma unroll
    for (int i=0;i<4;i++)
        #pragma unroll
        for (int j=0;j<4;j++)
            #pragma unroll
            for (int q=0;q<4;q++) acc[i][j][q]=0.f;

    fill(0, 0);

    for (int c = 0; c < 32; c++){
        int buf = c & 1;
        if (c < 31){ fill(c+1, buf^1); cp_wait<1>(); }
        else       { cp_wait<0>(); }
        __syncthreads();

        const __nv_bfloat16* Ah = (const __nv_bfloat16*)(smem + buf*BUFB);
        const __nv_bfloat16* Al = (const __nv_bfloat16*)(smem + buf*BUFB + TSZB);
        const __nv_bfloat16* Bh = (const __nv_bfloat16*)(smem + buf*BUFB + 2*TSZB);
        const __nv_bfloat16* Bl = (const __nv_bfloat16*)(smem + buf*BUFB + 3*TSZB);

        #pragma unroll
        for (int ks = 0; ks < 2; ks++){
            int k16 = ks*16;
            uint32_t ah[4][4], al[4][4], bh[4][2], bl[4][2];
            #pragma unroll
            for (int i = 0; i < 4; i++){
                int row = wm*64 + i*16 + (lane>>2);
                int off = row*AST + k16 + 2*(lane&3);
                ah[i][0] = *(const uint32_t*)(Ah + off);
                ah[i][1] = *(const uint32_t*)(Ah + off + 8*AST);
                ah[i][2] = *(const uint32_t*)(Ah + off + 8);
                ah[i][3] = *(const uint32_t*)(Ah + off + 8*AST + 8);
                al[i][0] = *(const uint32_t*)(Al + off);
                al[i][1] = *(const uint32_t*)(Al + off + 8*AST);
                al[i][2] = *(const uint32_t*)(Al + off + 8);
                al[i][3] = *(const uint32_t*)(Al + off + 8*AST + 8);
            }
            #pragma unroll
            for (int j = 0; j < 4; j++){
                int nrow = wn*32 + j*8 + (lane>>2);
                int off = nrow*AST + k16 + 2*(lane&3);
                bh[j][0] = *(const uint32_t*)(Bh + off);
                bh[j][1] = *(const uint32_t*)(Bh + off + 8);
                bl[j][0] = *(const uint32_t*)(Bl + off);
                bl[j][1] = *(const uint32_t*)(Bl + off + 8);
            }
            #pragma unroll
            for (int i = 0; i < 4; i++)
                #pragma unroll
                for (int j = 0; j < 4; j++){
                    mma16816(acc[i][j], ah[i], bh[j]);
                    mma16816(acc[i][j], ah[i], bl[j]);
                    mma16816(acc[i][j], al[i], bh[j]);
                }
        }
        __syncthreads();
    }

    #pragma unroll
    for (int i = 0; i < 4; i++){
        int row = m0 + wm*64 + i*16 + (lane>>2);
        #pragma unroll
        for (int j = 0; j < 4; j++){
            int col = n0 + wn*32 + j*8 + 2*(lane&3);
            size_t o0 = (size_t)row*Dn + col;
            size_t o1 = (size_t)(row+8)*Dn + col;
            float2 v0, v1;
            v0.x = alpha*acc[i][j][0]; v0.y = alpha*acc[i][j][1];
            v1.x = alpha*acc[i][j][2]; v1.y = alpha*acc[i][j][3];
            if (R){
                float2 r0 = *(const float2*)(R + o0);
                float2 r1 = *(const float2*)(R + o1);
                v0.x += r0.x; v0.y += r0.y; v1.x += r1.x; v1.y += r1.y;
            }
            *(float2*)(C + o0) = v0;
            *(float2*)(C + o1) = v1;
        }
    }
}

// ---------------------------------------------------------------------------
// MMA-based local attention per (h, seg, b), 256 threads = 8 warps.
// Warp w: m-band = w&3 (16 rows), n-half = w>>2 (32 cols).
// S = q@k^T (split-bf16, 3 mma products), masked logits -> g_joint,
// unmasked softmax, P@V via mma on transposed V -> rowattn fp32 + split.
// ---------------------------------------------------------------------------
#define KST 72   // bf16 tile k-stride (row = 144 B, frag banks 4g+c: conflict-free)
#define TILE_E (64*KST)

__global__ void __launch_bounds__(256)
local_attn_kernel()
{
    extern __shared__ __nv_bfloat16 bsm[];
    __nv_bfloat16* qh  = bsm;             // also reused for P hi
    __nv_bfloat16* ql  = bsm + TILE_E;    // also reused for P lo
    __nv_bfloat16* kh  = bsm + 2*TILE_E;
    __nv_bfloat16* kl  = bsm + 3*TILE_E;
    __nv_bfloat16* vTh = bsm + 4*TILE_E;  // [dim][key]
    __nv_bfloat16* vTl = bsm + 5*TILE_E;
    float* red = (float*)(bsm + 6*TILE_E); // [256]: [0:128] max, [128:256] sum

    int h = blockIdx.x, seg = blockIdx.y, b = blockIdx.z;
    int tid = threadIdx.x, lane = tid & 31, wid = tid >> 5;
    int g = lane >> 2, c = lane & 3;
    size_t tok0 = ((size_t)b*NSn + seg)*SEGn;

    // Load + split-convert q,k (row-major) and v (transposed)
    for (int i = tid; i < 64*64; i += 256){
        int r = i >> 6, cc = i & 63;
        size_t off = (tok0 + r)*Dn + h*HDn + cc;
        float qv = g_q[off], kv = g_k[off], vv = g_v[off];
        __nv_bfloat16 qH = __float2bfloat16_rn(qv);
        __nv_bfloat16 kH = __float2bfloat16_rn(kv);
        __nv_bfloat16 vH = __float2bfloat16_rn(vv);
        qh[r*KST+cc] = qH; ql[r*KST+cc] = __float2bfloat16_rn(qv - __bfloat162float(qH));
        kh[r*KST+cc] = kH; kl[r*KST+cc] = __float2bfloat16_rn(kv - __bfloat162float(kH));
        vTh[cc*KST+r] = vH; vTl[cc*KST+r] = __float2bfloat16_rn(vv - __bfloat162float(vH));
    }
    __syncthreads();

    int mband = wid & 3, nhalf = wid >> 2;
    int r0 = mband*16, n0 = nhalf*32;
    int rA = r0 + g, rB = rA + 8;

    // --- S = q @ k^T ---
    float accS[4][4];
    #pragma unroll
    for (int t=0;t<4;t++)
        #pragma unroll
        for (int q2=0;q2<4;q2++) accS[t][q2]=0.f;

    #pragma unroll
    for (int kk = 0; kk < 4; kk++){
        int ab = rA*KST + kk*16 + 2*c;
        uint32_t ah[4], al[4];
        ah[0]=*(uint32_t*)(qh+ab); ah[1]=*(uint32_t*)(qh+ab+8*KST);
        ah[2]=*(uint32_t*)(qh+ab+8); ah[3]=*(uint32_t*)(qh+ab+8*KST+8);
        al[0]=*(uint32_t*)(ql+ab); al[1]=*(uint32_t*)(ql+ab+8*KST);
        al[2]=*(uint32_t*)(ql+ab+8); al[3]=*(uint32_t*)(ql+ab+8*KST+8);
        #pragma unroll
        for (int t = 0; t < 4; t++){
            int bb = (n0 + t*8 + g)*KST + kk*16 + 2*c;
            uint32_t bh[2], bl[2];
            bh[0]=*(uint32_t*)(kh+bb); bh[1]=*(uint32_t*)(kh+bb+8);
            bl[0]=*(uint32_t*)(kl+bb); bl[1]=*(uint32_t*)(kl+bb+8);
            mma16816(accS[t], ah, bh);
            mma16816(accS[t], ah, bl);
            mma16816(accS[t], al, bh);
        }
    }

    // masked logits -> g_joint
    size_t jbA = ((tok0 + rA)*Hn + h)*128;
    size_t jbB = ((tok0 + rB)*Hn + h)*128;
    #pragma unroll
    for (int t = 0; t < 4; t++){
        int col0 = n0 + t*8 + 2*c;
        float2 w0, w1;
        w0.x = accS[t][0] + (rA < col0   ? NEGV : 0.f);
        w0.y = accS[t][1] + (rA < col0+1 ? NEGV : 0.f);
        w1.x = accS[t][2] + (rB < col0   ? NEGV : 0.f);
        w1.y = accS[t][3] + (rB < col0+1 ? NEGV : 0.f);
        *(float2*)(g_joint + jbA + col0) = w0;
        *(float2*)(g_joint + jbB + col0) = w1;
    }

    // --- unmasked softmax ---
    float mA = -1e30f, mB = -1e30f;
    #pragma unroll
    for (int t=0;t<4;t++){
        mA = fmaxf(mA, fmaxf(accS[t][0], accS[t][1]));
        mB = fmaxf(mB, fmaxf(accS[t][2], accS[t][3]));
    }
    mA = fmaxf(mA, __shfl_xor_sync(0xffffffffu, mA, 1));
    mA = fmaxf(mA, __shfl_xor_sync(0xffffffffu, mA, 2));
    mB = fmaxf(mB, __shfl_xor_sync(0xffffffffu, mB, 1));
    mB = fmaxf(mB, __shfl_xor_sync(0xffffffffu, mB, 2));
    if (c == 0){ red[nhalf*64 + rA] = mA; red[nhalf*64 + rB] = mB; }
    __syncthreads();
    float mmA = fmaxf(red[rA], red[64+rA]);
    float mmB = fmaxf(red[rB], red[64+rB]);

    float p[4][4];
    float sA = 0.f, sB = 0.f;
    #pragma unroll
    for (int t=0;t<4;t++){
        p[t][0] = __expf(accS[t][0]-mmA); p[t][1] = __expf(accS[t][1]-mmA);
        p[t][2] = __expf(accS[t][2]-mmB); p[t][3] = __expf(accS[t][3]-mmB);
        sA += p[t][0]+p[t][1]; sB += p[t][2]+p[t][3];
    }
    sA += __shfl_xor_sync(0xffffffffu, sA, 1);
    sA += __shfl_xor_sync(0xffffffffu, sA, 2);
    sB += __shfl_xor_sync(0xffffffffu, sB, 1);
    sB += __shfl_xor_sync(0xffffffffu, sB, 2);
    if (c == 0){ red[128 + nhalf*64 + rA] = sA; red[128 + nhalf*64 + rB] = sB; }
    __syncthreads();   // sums visible; q tiles free for reuse
    float invA = 1.f/(red[128+rA] + red[128+64+rA]);
    float invB = 1.f/(red[128+rB] + red[128+64+rB]);

    // store unnormalized P (split) into q region: [row][key]
    #pragma unroll
    for (int t = 0; t < 4; t++){
        int col0 = n0 + t*8 + 2*c;
        *(uint32_t*)(qh + rA*KST + col0) = pack_hi(p[t][0], p[t][1]);
        *(uint32_t*)(ql + rA*KST + col0) = pack_lo(p[t][0], p[t][1]);
        *(uint32_t*)(qh + rB*KST + col0) = pack_hi(p[t][2], p[t][3]);
        *(uint32_t*)(ql + rB*KST + col0) = pack_lo(p[t][2], p[t][3]);
    }
    __syncthreads();

    // --- O = P @ V (vT tiles), full K=64 per warp, n = dims n-half ---
    float accO[4][4];
    #pragma unroll
    for (int t=0;t<4;t++)
        #pragma unroll
        for (int q2=0;q2<4;q2++) accO[t][q2]=0.f;

    #pragma unroll
    for (int kk = 0; kk < 4; kk++){
        int ab = rA*KST + kk*16 + 2*c;
        uint32_t ah[4], al[4];
        ah[0]=*(uint32_t*)(qh+ab); ah[1]=*(uint32_t*)(qh+ab+8*KST);
        ah[2]=*(uint32_t*)(qh+ab+8); ah[3]=*(uint32_t*)(qh+ab+8*KST+8);
        al[0]=*(uint32_t*)(ql+ab); al[1]=*(uint32_t*)(ql+ab+8*KST);
        al[2]=*(uint32_t*)(ql+ab+8); al[3]=*(uint32_t*)(ql+ab+8*KST+8);
        #pragma unroll
        for (int t = 0; t < 4; t++){
            int bb = (n0 + t*8 + g)*KST + kk*16 + 2*c;
            uint32_t bh[2], bl[2];
            bh[0]=*(uint32_t*)(vTh+bb); bh[1]=*(uint32_t*)(vTh+bb+8);
            bl[0]=*(uint32_t*)(vTl+bb); bl[1]=*(uint32_t*)(vTl+bb+8);
            mma16816(accO[t], ah, bh);
            mma16816(accO[t], ah, bl);
            mma16816(accO[t], al, bh);
        }
    }

    // rowattn = O * inv (fp32 + split)
    #pragma unroll
    for (int t = 0; t < 4; t++){
        int col0 = n0 + t*8 + 2*c;   // dim
        size_t oA = (tok0+rA)*Dn + h*HDn + col0;
        size_t oB = (tok0+rB)*Dn + h*HDn + col0;
        float2 vA, vB;
        vA.x = accO[t][0]*invA; vA.y = accO[t][1]*invA;
        vB.x = accO[t][2]*invB; vB.y = accO[t][3]*invB;
        *(float2*)(g_rowattn + oA) = vA;
        *(float2*)(g_rowattn + oB) = vB;
        store_split2(vA.x, vA.y, oA);
        store_split2(vB.x, vB.y, oB);
    }
}
#define LA_SMEM (6*TILE_E*2 + 256*4)   // 56320 B

// ---------------------------------------------------------------------------
// LayerNorm over D=1024 per token: writes bf16 split directly
// ---------------------------------------------------------------------------
__global__ void __launch_bounds__(256)
ln_kernel(const float* __restrict__ scale, const float* __restrict__ bias)
{
    size_t row = blockIdx.x;
    int tid = threadIdx.x;
    float4 v = ((const float4*)(g_t1 + row*Dn))[tid];
    float s  = v.x+v.y+v.z+v.w;
    float ss = v.x*v.x+v.y*v.y+v.z*v.z+v.w*v.w;
    #pragma unroll
    for (int o=16;o;o>>=1){
        s  += __shfl_xor_sync(0xffffffffu, s, o);
        ss += __shfl_xor_sync(0xffffffffu, ss, o);
    }
    __shared__ float sh[16];
    int w = tid>>5, lane = tid&31;
    if (lane==0){ sh[w]=s; sh[8+w]=ss; }
    __syncthreads();
    if (tid==0){
        float a=0.f,b2=0.f;
        #pragma unroll
        for (int i=0;i<8;i++){ a+=sh[i]; b2+=sh[8+i]; }
        float mu  = a*(1.f/Dn);
        float var = b2*(1.f/Dn) - mu*mu;
        sh[0]=mu; sh[1]=rsqrtf(var + 1e-6f);
    }
    __syncthreads();
    float mu = sh[0], rstd = sh[1];
    float4 sc = ((const float4*)scale)[tid];
    float4 bi = ((const float4*)bias)[tid];
    float4 o4;
    o4.x=(v.x-mu)*rstd*sc.x+bi.x;
    o4.y=(v.y-mu)*rstd*sc.y+bi.y;
    o4.z=(v.z-mu)*rstd*sc.z+bi.z;
    o4.w=(v.w-mu)*rstd*sc.w+bi.w;
    store_split4(o4, row*Dn + tid*4);
}

// ---------------------------------------------------------------------------
// FUSED global logits + joint softmax + global merge, per (h, l, b). (scalar)
// ---------------------------------------------------------------------------
#define PV 68
__global__ void __launch_bounds__(256)
global_fused_kernel()
{
    extern __shared__ float sm[];
    float* qg  = sm;                 // [64*PV] q, reused for gatt probs
    float* kg  = sm + 64*PV;         // krow
    float* ra  = kg + 64*PV;         // rowattn
    float* red = ra + 64*PV;         // [256]

    int h = blockIdx.x, l = blockIdx.y, b = blockIdx.z;
    int tid = threadIdx.x;
    for (int i = tid; i < 64*64; i += 256){
        int r = i>>6, c = i&63;
        size_t t = ((size_t)b*NSn + r)*SEGn + l;
        size_t off = t*Dn + h*HDn + c;
        qg[r*PV+c] = g_q[off];
        kg[r*PV+c] = g_krow[off];
        ra[r*PV+c] = g_rowattn[off];
    }
    __syncthreads();

    int row = tid & 63, part = tid >> 6;   // row = qseg
    const float4* qf = (const float4*)qg;
    const float4* kf = (const float4*)kg;
    float lg[16];
    #pragma unroll
    for (int c=0;c<16;c++) lg[c]=0.f;
    for (int d4=0; d4<16; d4++){
        float4 qv = qf[row*17 + d4];
        #pragma unroll
        for (int c=0;c<16;c++){
            float4 kv = kf[(part*16+c)*17 + d4];
            lg[c] += qv.x*kv.x + qv.y*kv.y + qv.z*kv.z + qv.w*kv.w;
        }
    }
    #pragma unroll
    for (int c=0;c<16;c++){
        int col = part*16+c;
        lg[c] += (row <= col ? NEGV : 0.f);
    }

    size_t t  = ((size_t)b*NSn + row)*SEGn + l;
    size_t jb = (t*Hn + h)*128;
    float4 loc[4];
    #pragma unroll
    for (int j4=0;j4<4;j4++)
        loc[j4] = *(const float4*)(g_joint + jb + part*16 + j4*4);

    float m = -1e30f;
    #pragma unroll
    for (int c=0;c<16;c++) m = fmaxf(m, lg[c]);
    #pragma unroll
    for (int j4=0;j4<4;j4++)
        m = fmaxf(m, fmaxf(fmaxf(loc[j4].x,loc[j4].y),fmaxf(loc[j4].z,loc[j4].w)));
    red[tid] = m;
    __syncthreads();
    float mm = fmaxf(fmaxf(red[row], red[64+row]), fmaxf(red[128+row], red[192+row]));

    float ssum = 0.f;
    #pragma unroll
    for (int c=0;c<16;c++){ lg[c] = __expf(lg[c]-mm); ssum += lg[c]; }
    #pragma unroll
    for (int j4=0;j4<4;j4++){
        loc[j4].x = __expf(loc[j4].x-mm); loc[j4].y = __expf(loc[j4].y-mm);
        loc[j4].z = __expf(loc[j4].z-mm); loc[j4].w = __expf(loc[j4].w-mm);
        ssum += loc[j4].x+loc[j4].y+loc[j4].z+loc[j4].w;
    }
    __syncthreads();
    red[tid] = ssum;
    __syncthreads();
    float inv = 1.f/(red[row] + red[64+row] + red[128+row] + red[192+row]);

    #pragma unroll
    for (int j4=0;j4<4;j4++){
        loc[j4].x*=inv; loc[j4].y*=inv; loc[j4].z*=inv; loc[j4].w*=inv;
        *(float4*)(g_joint + jb + part*16 + j4*4) = loc[j4];
    }

    __syncthreads();
    float* qw = qg + row*PV + part*16;
    #pragma unroll
    for (int c4=0;c4<4;c4++)
        *(float4*)(qw + c4*4) = make_float4(lg[c4*4]*inv, lg[c4*4+1]*inv,
                                            lg[c4*4+2]*inv, lg[c4*4+3]*inv);
    __syncthreads();

    const float4* rf = (const float4*)ra;
    float4 o[4];
    #pragma unroll
    for (int j=0;j<4;j++) o[j] = make_float4(0.f,0.f,0.f,0.f);
    for (int c=0;c<64;c++){
        float gv = qg[row*PV+c];
        #pragma unroll
        for (int j4=0;j4<4;j4++){
            float4 vv = rf[c*17 + part*4 + j4];
            o[j4].x += gv*vv.x; o[j4].y += gv*vv.y;
            o[j4].z += gv*vv.z; o[j4].w += gv*vv.w;
        }
    }
    size_t ob = t*Dn + h*HDn + part*16;
    #pragma unroll
    for (int j4=0;j4<4;j4++)
        *(float4*)(g_merged + ob + j4*4) = o[j4];
}

// ---------------------------------------------------------------------------
// MMA-based local_merged finalizer per (h, seg, b):
// merged = g_merged + latt@v, written only as bf16 split.
// ---------------------------------------------------------------------------
__global__ void __launch_bounds__(256)
local_merged_kernel()
{
    __shared__ __nv_bfloat16 ph [TILE_E];
    __shared__ __nv_bfloat16 pl [TILE_E];
    __shared__ __nv_bfloat16 vTh[TILE_E];
    __shared__ __nv_bfloat16 vTl[TILE_E];

    int h = blockIdx.x, seg = blockIdx.y, b = blockIdx.z;
    int tid = threadIdx.x, lane = tid & 31, wid = tid >> 5;
    int g = lane >> 2, c = lane & 3;
    size_t tok0 = ((size_t)b*NSn + seg)*SEGn;

    for (int i = tid; i < 64*64; i += 256){
        int r = i >> 6, cc = i & 63;
        float pv = g_joint[((tok0+r)*Hn+h)*128 + cc];
        float vv = g_v[(tok0+r)*Dn + h*HDn + cc];
        __nv_bfloat16 pH = __float2bfloat16_rn(pv);
        __nv_bfloat16 vH = __float2bfloat16_rn(vv);
        ph[r*KST+cc] = pH;  pl[r*KST+cc]  = __float2bfloat16_rn(pv - __bfloat162float(pH));
        vTh[cc*KST+r] = vH; vTl[cc*KST+r] = __float2bfloat16_rn(vv - __bfloat162float(vH));
    }
    __syncthreads();

    int mband = wid & 3, nhalf = wid >> 2;
    int r0 = mband*16, n0 = nhalf*32;
    int rA = r0 + g, rB = rA + 8;

    float accO[4][4];
    #pragma unroll
    for (int t=0;t<4;t++)
        #pragma unroll
        for (int q2=0;q2<4;q2++) accO[t][q2]=0.f;

    #pragma unroll
    for (int kk = 0; kk < 4; kk++){
        int ab = rA*KST + kk*16 + 2*c;
        uint32_t ah[4], al[4];
        ah[0]=*(uint32_t*)(ph+ab); ah[1]=*(uint32_t*)(ph+ab+8*KST);
        ah[2]=*(uint32_t*)(ph+ab+8); ah[3]=*(uint32_t*)(ph+ab+8*KST+8);
        al[0]=*(uint32_t*)(pl+ab); al[1]=*(uint32_t*)(pl+ab+8*KST);
        al[2]=*(uint32_t*)(pl+ab+8); al[3]=*(uint32_t*)(pl+ab+8*KST+8);
        #pragma unroll
        for (int t = 0; t < 4; t++){
            int bb = (n0 + t*8 + g)*KST + kk*16 + 2*c;
            uint32_t bh[2], bl[2];
            bh[0]=*(uint32_t*)(vTh+bb); bh[1]=*(uint32_t*)(vTh+bb+8);
            bl[0]=*(uint32_t*)(vTl+bb); bl[1]=*(uint32_t*)(vTl+bb+8);
            mma16816(accO[t], ah, bh);
            mma16816(accO[t], ah, bl);
            mma16816(accO[t], al, bh);
        }
    }

    #pragma unroll
    for (int t = 0; t < 4; t++){
        int col0 = n0 + t*8 + 2*c;
        size_t oA = (tok0+rA)*Dn + h*HDn + col0;
        size_t oB = (tok0+rB)*Dn + h*HDn + col0;
        float2 mA = *(const float2*)(g_merged + oA);
        float2 mB = *(const float2*)(g_merged + oB);
        store_split2(mA.x + accO[t][0], mA.y + accO[t][1], oA);
        store_split2(mB.x + accO[t][2], mB.y + accO[t][3], oB);
    }
}

// ---------------------------------------------------------------------------
// Launch
// ---------------------------------------------------------------------------
extern "C" void kernel_launch(void* const* d_in, const int* in_sizes, int n_in,
                              void* d_out, int out_size)
{
    const float* x    = (const float*)d_in[0];
    const float* Wq   = (const float*)d_in[1];
    const float* Wk   = (const float*)d_in[2];
    const float* Wv   = (const float*)d_in[3];
    const float* Wro  = (const float*)d_in[4];
    const float* lns  = (const float*)d_in[5];
    const float* lnb  = (const float*)d_in[6];
    const float* Wk2  = (const float*)d_in[7];
    const float* Wout = (const float*)d_in[8];
    float* out = (float*)d_out;

    const int GF_SMEM = (3*64*PV + 256)*4;   // 53,248 B
    cudaFuncSetAttribute(local_attn_kernel,
                         cudaFuncAttributeMaxDynamicSharedMemorySize, LA_SMEM);
    cudaFuncSetAttribute(global_fused_kernel,
                         cudaFuncAttributeMaxDynamicSharedMemorySize, GF_SMEM);
    cudaFuncSetAttribute(hmma_gemm,
                         cudaFuncAttributeMaxDynamicSharedMemorySize, HG_SMEM);

    dim3 gg(8, 128);
    dim3 gq(8, 128, 3);         // fused QKV
    dim3 ga(Hn, NSn, Bn);
    dim3 gl(Hn, SEGn, Bn);
    const int ACT_BLKS = (NTOK*Dn/4)/256;

    convert_wt<<<dim3(32,32,6),256>>>(Wq, Wk, Wv, Wro, Wk2, Wout);

    convert_act<<<ACT_BLKS,256>>>(x);
    hmma_gemm<<<gq,256,HG_SMEM>>>(-1, nullptr,0, nullptr, 0.f);     // q,k,v

    local_attn_kernel<<<ga,256,LA_SMEM>>>();                        // mma + rowattn split

    hmma_gemm<<<gg,256,HG_SMEM>>>(3, nullptr,4, x, 1.f);            // t1 = rowattn@Wro + x
    ln_kernel<<<NTOK,256>>>(lns, lnb);                              // -> ahi/alo
    hmma_gemm<<<gg,256,HG_SMEM>>>(4, nullptr,5, nullptr, 1.f);      // krow

    global_fused_kernel<<<gl,256,GF_SMEM>>>();                      // logits+softmax+gmerge
    local_merged_kernel<<<ga,256>>>();                              // mma finalize + split

    hmma_gemm<<<gg,256,HG_SMEM>>>(5, out,0, nullptr, 1.f);
}

// round 14
// speedup vs baseline: 2.5921x; 1.0400x over previous
#include <cuda_runtime.h>
#include <cuda_bf16.h>
#include <math.h>
#include <stdint.h>

// Problem constants
#define Bn   4
#define Sn   4096
#define Dn   1024
#define Hn   16
#define HDn  64
#define SEGn 64
#define NSn  64
#define NTOK (Bn*Sn)          // 16384
#define NEGV (-1.0e10f)

// ---------------------------------------------------------------------------
// Scratch (device globals)
// ---------------------------------------------------------------------------
__device__ float g_q      [(size_t)NTOK*Dn];
__device__ float g_k      [(size_t)NTOK*Dn];
__device__ float g_v      [(size_t)NTOK*Dn];
__device__ float g_rowattn[(size_t)NTOK*Dn];
__device__ float g_t1     [(size_t)NTOK*Dn];
__device__ float g_krow   [(size_t)NTOK*Dn];
__device__ float g_merged [(size_t)NTOK*Dn];   // global_merged partial
__device__ float g_joint  [(size_t)NTOK*Hn*128]; // [0:64] local logits -> local probs

// Split-bf16 staging
__device__ __nv_bfloat16 g_ahi [(size_t)NTOK*Dn];
__device__ __nv_bfloat16 g_alo [(size_t)NTOK*Dn];
__device__ __nv_bfloat16 g_wthi[(size_t)6*Dn*Dn];   // WT[w][n][k] = W[w][k][n]
__device__ __nv_bfloat16 g_wtlo[(size_t)6*Dn*Dn];

__device__ __forceinline__ float* cpick(float* ext, int id){
    switch(id){ case 1: return g_q; case 2: return g_k; case 3: return g_v;
                case 4: return g_t1; case 5: return g_krow; }
    return ext;
}

__device__ __forceinline__ uint32_t pack_hi(float a, float b){
    __nv_bfloat162 t(__float2bfloat16_rn(a), __float2bfloat16_rn(b));
    return *(uint32_t*)&t;
}
__device__ __forceinline__ uint32_t pack_lo(float a, float b){
    float ha = __bfloat162float(__float2bfloat16_rn(a));
    float hb = __bfloat162float(__float2bfloat16_rn(b));
    __nv_bfloat162 t(__float2bfloat16_rn(a-ha), __float2bfloat16_rn(b-hb));
    return *(uint32_t*)&t;
}
// split store of 2 consecutive values (off must be even)
__device__ __forceinline__ void store_split2(float a, float b, size_t off){
    *(uint32_t*)(g_ahi + off) = pack_hi(a,b);
    *(uint32_t*)(g_alo + off) = pack_lo(a,b);
}
// vector split store: 4 consecutive values at 4-aligned offset
__device__ __forceinline__ void store_split4(float4 v, size_t off){
    uint2 hv, lv;
    hv.x = pack_hi(v.x,v.y); hv.y = pack_hi(v.z,v.w);
    lv.x = pack_lo(v.x,v.y); lv.y = pack_lo(v.z,v.w);
    *(uint2*)(g_ahi + off) = hv;
    *(uint2*)(g_alo + off) = lv;
}

__device__ __forceinline__ uint32_t smem_u32(const void* p){
    uint32_t a;
    asm("{ .reg .u64 t; cvta.to.shared.u64 t, %1; cvt.u32.u64 %0, t; }" : "=r"(a) : "l"(p));
    return a;
}
__device__ __forceinline__ void cp_async16(uint32_t dst, const void* src){
    asm volatile("cp.async.cg.shared.global [%0], [%1], 16;" :: "r"(dst), "l"(src) : "memory");
}
__device__ __forceinline__ void cp_commit(){
    asm volatile("cp.async.commit_group;" ::: "memory");
}
template<int N> __device__ __forceinline__ void cp_wait(){
    asm volatile("cp.async.wait_group %0;" :: "n"(N) : "memory");
}
__device__ __forceinline__ void mma16816(float* c, const uint32_t* a, const uint32_t* b){
    asm volatile("mma.sync.aligned.m16n8k16.row.col.f32.bf16.bf16.f32 "
                 "{%0,%1,%2,%3}, {%4,%5,%6,%7}, {%8,%9}, {%0,%1,%2,%3};"
                 : "+f"(c[0]), "+f"(c[1]), "+f"(c[2]), "+f"(c[3])
                 : "r"(a[0]), "r"(a[1]), "r"(a[2]), "r"(a[3]), "r"(b[0]), "r"(b[1]));
}

// ---------------------------------------------------------------------------
// Split conversion: x fp32 -> (hi,lo) bf16
// ---------------------------------------------------------------------------
__global__ void __launch_bounds__(256)
convert_act(const float* __restrict__ src)
{
    size_t i = (size_t)blockIdx.x*256 + threadIdx.x;
    float4 v = ((const float4*)src)[i];
    store_split4(v, i*4);
}

// ---------------------------------------------------------------------------
// Weight transpose+split: WT[w][n][k] = split(W[w][k][n])
// ---------------------------------------------------------------------------
__global__ void __launch_bounds__(256)
convert_wt(const float* __restrict__ W0, const float* __restrict__ W1,
           const float* __restrict__ W2, const float* __restrict__ W3,
           const float* __restrict__ W4, const float* __restrict__ W5)
{
    const float* Ws[6] = {W0,W1,W2,W3,W4,W5};
    const float* W = Ws[blockIdx.z];
    __shared__ float tile[32][33];
    int n0 = blockIdx.x*32, k0 = blockIdx.y*32;
    int tx = threadIdx.x & 31, ty = threadIdx.x >> 5;
    #pragma unroll
    for (int j = 0; j < 4; j++){
        int r = ty + j*8;
        tile[r][tx] = W[(size_t)(k0+r)*Dn + n0 + tx];
    }
    __syncthreads();
    size_t wbase = (size_t)blockIdx.z*Dn*Dn;
    #pragma unroll
    for (int j = 0; j < 4; j++){
        int r = ty + j*8;
        float a = tile[tx][r];
        __nv_bfloat16 hi = __float2bfloat16_rn(a);
        __nv_bfloat16 lo = __float2bfloat16_rn(a - __bfloat162float(hi));
        size_t o = wbase + (size_t)(n0+r)*Dn + k0 + tx;
        g_wthi[o] = hi;
        g_wtlo[o] = lo;
    }
}

// ---------------------------------------------------------------------------
// HMMA GEMM (unchanged, BK=32, occ 2, fused-QKV mode)
// ---------------------------------------------------------------------------
#define AST  40
#define TSZB (128*AST*2)          // 10240 B per matrix
#define BUFB (4*TSZB)             // 40960 B per buffer
#define HG_SMEM (2*BUFB)          // 81920 B

__global__ void __launch_bounds__(256,2)
hmma_gemm(int widx, float* Cext, int Cid, const float* __restrict__ R, float alpha)
{
    extern __shared__ char smem[];
    uint32_t sb = smem_u32(smem);
    int tid = threadIdx.x, lane = tid & 31, wid = tid >> 5;
    int wm = wid & 1, wn = wid >> 1;
    int m0 = blockIdx.y*128, n0 = blockIdx.x*128;

    if (widx < 0){
        widx = blockIdx.z;
        Cid  = blockIdx.z + 1;
        alpha = (blockIdx.z == 0) ? 0.125f : 1.f;
    }
    float* C = cpick(Cext, Cid);

    const __nv_bfloat16* srcs[4];
    srcs[0] = g_ahi  + (size_t)m0*Dn;
    srcs[1] = g_alo  + (size_t)m0*Dn;
    srcs[2] = g_wthi + (size_t)widx*Dn*Dn + (size_t)n0*Dn;
    srcs[3] = g_wtlo + (size_t)widx*Dn*Dn + (size_t)n0*Dn;

    auto fill = [&](int c, int buf){
        int k0 = c*32;
        uint32_t base = sb + buf*BUFB;
        #pragma unroll
        for (int t = 0; t < 4; t++){
            #pragma unroll
            for (int it = 0; it < 2; it++){
                int idx = it*256 + tid;
                int r = idx >> 2, cc = idx & 3;
                cp_async16(base + t*TSZB + r*(AST*2) + cc*16,
                           srcs[t] + (size_t)r*Dn + k0 + cc*8);
            }
        }
        cp_commit();
    };

    float acc[4][4][4];
    #pragma unroll
    for (int i=0;i<4;i++)
        #pragma unroll
        for (int j=0;j<4;j++)
            #pragma unroll
            for (int q=0;q<4;q++) acc[i][j][q]=0.f;

    fill(0, 0);

    for (int c = 0; c < 32; c++){
        int buf = c & 1;
        if (c < 31){ fill(c+1, buf^1); cp_wait<1>(); }
        else       { cp_wait<0>(); }
        __syncthreads();

        const __nv_bfloat16* Ah = (const __nv_bfloat16*)(smem + buf*BUFB);
        const __nv_bfloat16* Al = (const __nv_bfloat16*)(smem + buf*BUFB + TSZB);
        const __nv_bfloat16* Bh = (const __nv_bfloat16*)(smem + buf*BUFB + 2*TSZB);
        const __nv_bfloat16* Bl = (const __nv_bfloat16*)(smem + buf*BUFB + 3*TSZB);

        #pragma unroll
        for (int ks = 0; ks < 2; ks++){
            int k16 = ks*16;
            uint32_t ah[4][4], al[4][4], bh[4][2], bl[4][2];
            #pragma unroll
            for (int i = 0; i < 4; i++){
                int row = wm*64 + i*16 + (lane>>2);
                int off = row*AST + k16 + 2*(lane&3);
                ah[i][0] = *(const uint32_t*)(Ah + off);
                ah[i][1] = *(const uint32_t*)(Ah + off + 8*AST);
                ah[i][2] = *(const uint32_t*)(Ah + off + 8);
                ah[i][3] = *(const uint32_t*)(Ah + off + 8*AST + 8);
                al[i][0] = *(const uint32_t*)(Al + off);
                al[i][1] = *(const uint32_t*)(Al + off + 8*AST);
                al[i][2] = *(const uint32_t*)(Al + off + 8);
                al[i][3] = *(const uint32_t*)(Al + off + 8*AST + 8);
            }
            #pragma unroll
            for (int j = 0; j < 4; j++){
                int nrow = wn*32 + j*8 + (lane>>2);
                int off = nrow*AST + k16 + 2*(lane&3);
                bh[j][0] = *(const uint32_t*)(Bh + off);
                bh[j][1] = *(const uint32_t*)(Bh + off + 8);
                bl[j][0] = *(const uint32_t*)(Bl + off);
                bl[j][1] = *(const uint32_t*)(Bl + off + 8);
            }
            #pragma unroll
            for (int i = 0; i < 4; i++)
                #pragma unroll
                for (int j = 0; j < 4; j++){
                    mma16816(acc[i][j], ah[i], bh[j]);
                    mma16816(acc[i][j], ah[i], bl[j]);
                    mma16816(acc[i][j], al[i], bh[j]);
                }
        }
        __syncthreads();
    }

    #pragma unroll
    for (int i = 0; i < 4; i++){
        int row = m0 + wm*64 + i*16 + (lane>>2);
        #pragma unroll
        for (int j = 0; j < 4; j++){
            int col = n0 + wn*32 + j*8 + 2*(lane&3);
            size_t o0 = (size_t)row*Dn + col;
            size_t o1 = (size_t)(row+8)*Dn + col;
            float2 v0, v1;
            v0.x = alpha*acc[i][j][0]; v0.y = alpha*acc[i][j][1];
            v1.x = alpha*acc[i][j][2]; v1.y = alpha*acc[i][j][3];
            if (R){
                float2 r0 = *(const float2*)(R + o0);
                float2 r1 = *(const float2*)(R + o1);
                v0.x += r0.x; v0.y += r0.y; v1.x += r1.x; v1.y += r1.y;
            }
            *(float2*)(C + o0) = v0;
            *(float2*)(C + o1) = v1;
        }
    }
}

// ---------------------------------------------------------------------------
// MMA-based local attention per (h, seg, b), 256 threads = 8 warps.
// ---------------------------------------------------------------------------
#define KST 72   // bf16 tile k-stride (row = 144 B, frag banks conflict-free)
#define TILE_E (64*KST)
#define LA_SMEM (6*TILE_E*2 + 256*4)   // 56320 B

__global__ void __launch_bounds__(256)
local_attn_kernel()
{
    extern __shared__ __nv_bfloat16 bsm[];
    __nv_bfloat16* qh  = bsm;             // also reused for P hi
    __nv_bfloat16* ql  = bsm + TILE_E;    // also reused for P lo
    __nv_bfloat16* kh  = bsm + 2*TILE_E;
    __nv_bfloat16* kl  = bsm + 3*TILE_E;
    __nv_bfloat16* vTh = bsm + 4*TILE_E;  // [dim][key]
    __nv_bfloat16* vTl = bsm + 5*TILE_E;
    float* red = (float*)(bsm + 6*TILE_E); // [256]: [0:128] max, [128:256] sum

    int h = blockIdx.x, seg = blockIdx.y, b = blockIdx.z;
    int tid = threadIdx.x, lane = tid & 31, wid = tid >> 5;
    int g = lane >> 2, c = lane & 3;
    size_t tok0 = ((size_t)b*NSn + seg)*SEGn;

    for (int i = tid; i < 64*64; i += 256){
        int r = i >> 6, cc = i & 63;
        size_t off = (tok0 + r)*Dn + h*HDn + cc;
        float qv = g_q[off], kv = g_k[off], vv = g_v[off];
        __nv_bfloat16 qH = __float2bfloat16_rn(qv);
        __nv_bfloat16 kH = __float2bfloat16_rn(kv);
        __nv_bfloat16 vH = __float2bfloat16_rn(vv);
        qh[r*KST+cc] = qH; ql[r*KST+cc] = __float2bfloat16_rn(qv - __bfloat162float(qH));
        kh[r*KST+cc] = kH; kl[r*KST+cc] = __float2bfloat16_rn(kv - __bfloat162float(kH));
        vTh[cc*KST+r] = vH; vTl[cc*KST+r] = __float2bfloat16_rn(vv - __bfloat162float(vH));
    }
    __syncthreads();

    int mband = wid & 3, nhalf = wid >> 2;
    int r0 = mband*16, n0 = nhalf*32;
    int rA = r0 + g, rB = rA + 8;

    // --- S = q @ k^T ---
    float accS[4][4];
    #pragma unroll
    for (int t=0;t<4;t++)
        #pragma unroll
        for (int q2=0;q2<4;q2++) accS[t][q2]=0.f;

    #pragma unroll
    for (int kk = 0; kk < 4; kk++){
        int ab = rA*KST + kk*16 + 2*c;
        uint32_t ah[4], al[4];
        ah[0]=*(uint32_t*)(qh+ab); ah[1]=*(uint32_t*)(qh+ab+8*KST);
        ah[2]=*(uint32_t*)(qh+ab+8); ah[3]=*(uint32_t*)(qh+ab+8*KST+8);
        al[0]=*(uint32_t*)(ql+ab); al[1]=*(uint32_t*)(ql+ab+8*KST);
        al[2]=*(uint32_t*)(ql+ab+8); al[3]=*(uint32_t*)(ql+ab+8*KST+8);
        #pragma unroll
        for (int t = 0; t < 4; t++){
            int bb = (n0 + t*8 + g)*KST + kk*16 + 2*c;
            uint32_t bh[2], bl[2];
            bh[0]=*(uint32_t*)(kh+bb); bh[1]=*(uint32_t*)(kh+bb+8);
            bl[0]=*(uint32_t*)(kl+bb); bl[1]=*(uint32_t*)(kl+bb+8);
            mma16816(accS[t], ah, bh);
            mma16816(accS[t], ah, bl);
            mma16816(accS[t], al, bh);
        }
    }

    // masked logits -> g_joint
    size_t jbA = ((tok0 + rA)*Hn + h)*128;
    size_t jbB = ((tok0 + rB)*Hn + h)*128;
    #pragma unroll
    for (int t = 0; t < 4; t++){
        int col0 = n0 + t*8 + 2*c;
        float2 w0, w1;
        w0.x = accS[t][0] + (rA < col0   ? NEGV : 0.f);
        w0.y = accS[t][1] + (rA < col0+1 ? NEGV : 0.f);
        w1.x = accS[t][2] + (rB < col0   ? NEGV : 0.f);
        w1.y = accS[t][3] + (rB < col0+1 ? NEGV : 0.f);
        *(float2*)(g_joint + jbA + col0) = w0;
        *(float2*)(g_joint + jbB + col0) = w1;
    }

    // --- unmasked softmax ---
    float mA = -1e30f, mB = -1e30f;
    #pragma unroll
    for (int t=0;t<4;t++){
        mA = fmaxf(mA, fmaxf(accS[t][0], accS[t][1]));
        mB = fmaxf(mB, fmaxf(accS[t][2], accS[t][3]));
    }
    mA = fmaxf(mA, __shfl_xor_sync(0xffffffffu, mA, 1));
    mA = fmaxf(mA, __shfl_xor_sync(0xffffffffu, mA, 2));
    mB = fmaxf(mB, __shfl_xor_sync(0xffffffffu, mB, 1));
    mB = fmaxf(mB, __shfl_xor_sync(0xffffffffu, mB, 2));
    if (c == 0){ red[nhalf*64 + rA] = mA; red[nhalf*64 + rB] = mB; }
    __syncthreads();
    float mmA = fmaxf(red[rA], red[64+rA]);
    float mmB = fmaxf(red[rB], red[64+rB]);

    float p[4][4];
    float sA = 0.f, sB = 0.f;
    #pragma unroll
    for (int t=0;t<4;t++){
        p[t][0] = __expf(accS[t][0]-mmA); p[t][1] = __expf(accS[t][1]-mmA);
        p[t][2] = __expf(accS[t][2]-mmB); p[t][3] = __expf(accS[t][3]-mmB);
        sA += p[t][0]+p[t][1]; sB += p[t][2]+p[t][3];
    }
    sA += __shfl_xor_sync(0xffffffffu, sA, 1);
    sA += __shfl_xor_sync(0xffffffffu, sA, 2);
    sB += __shfl_xor_sync(0xffffffffu, sB, 1);
    sB += __shfl_xor_sync(0xffffffffu, sB, 2);
    if (c == 0){ red[128 + nhalf*64 + rA] = sA; red[128 + nhalf*64 + rB] = sB; }
    __syncthreads();   // sums visible; q tiles free for reuse
    float invA = 1.f/(red[128+rA] + red[128+64+rA]);
    float invB = 1.f/(red[128+rB] + red[128+64+rB]);

    // store unnormalized P (split) into q region: [row][key]
    #pragma unroll
    for (int t = 0; t < 4; t++){
        int col0 = n0 + t*8 + 2*c;
        *(uint32_t*)(qh + rA*KST + col0) = pack_hi(p[t][0], p[t][1]);
        *(uint32_t*)(ql + rA*KST + col0) = pack_lo(p[t][0], p[t][1]);
        *(uint32_t*)(qh + rB*KST + col0) = pack_hi(p[t][2], p[t][3]);
        *(uint32_t*)(ql + rB*KST + col0) = pack_lo(p[t][2], p[t][3]);
    }
    __syncthreads();

    // --- O = P @ V (vT tiles) ---
    float accO[4][4];
    #pragma unroll
    for (int t=0;t<4;t++)
        #pragma unroll
        for (int q2=0;q2<4;q2++) accO[t][q2]=0.f;

    #pragma unroll
    for (int kk = 0; kk < 4; kk++){
        int ab = rA*KST + kk*16 + 2*c;
        uint32_t ah[4], al[4];
        ah[0]=*(uint32_t*)(qh+ab); ah[1]=*(uint32_t*)(qh+ab+8*KST);
        ah[2]=*(uint32_t*)(qh+ab+8); ah[3]=*(uint32_t*)(qh+ab+8*KST+8);
        al[0]=*(uint32_t*)(ql+ab); al[1]=*(uint32_t*)(ql+ab+8*KST);
        al[2]=*(uint32_t*)(ql+ab+8); al[3]=*(uint32_t*)(ql+ab+8*KST+8);
        #pragma unroll
        for (int t = 0; t < 4; t++){
            int bb = (n0 + t*8 + g)*KST + kk*16 + 2*c;
            uint32_t bh[2], bl[2];
            bh[0]=*(uint32_t*)(vTh+bb); bh[1]=*(uint32_t*)(vTh+bb+8);
            bl[0]=*(uint32_t*)(vTl+bb); bl[1]=*(uint32_t*)(vTl+bb+8);
            mma16816(accO[t], ah, bh);
            mma16816(accO[t], ah, bl);
            mma16816(accO[t], al, bh);
        }
    }

    #pragma unroll
    for (int t = 0; t < 4; t++){
        int col0 = n0 + t*8 + 2*c;   // dim
        size_t oA = (tok0+rA)*Dn + h*HDn + col0;
        size_t oB = (tok0+rB)*Dn + h*HDn + col0;
        float2 vA, vB;
        vA.x = accO[t][0]*invA; vA.y = accO[t][1]*invA;
        vB.x = accO[t][2]*invB; vB.y = accO[t][3]*invB;
        *(float2*)(g_rowattn + oA) = vA;
        *(float2*)(g_rowattn + oB) = vB;
        store_split2(vA.x, vA.y, oA);
        store_split2(vB.x, vB.y, oB);
    }
}

// ---------------------------------------------------------------------------
// LayerNorm over D=1024 per token: writes bf16 split directly
// ---------------------------------------------------------------------------
__global__ void __launch_bounds__(256)
ln_kernel(const float* __restrict__ scale, const float* __restrict__ bias)
{
    size_t row = blockIdx.x;
    int tid = threadIdx.x;
    float4 v = ((const float4*)(g_t1 + row*Dn))[tid];
    float s  = v.x+v.y+v.z+v.w;
    float ss = v.x*v.x+v.y*v.y+v.z*v.z+v.w*v.w;
    #pragma unroll
    for (int o=16;o;o>>=1){
        s  += __shfl_xor_sync(0xffffffffu, s, o);
        ss += __shfl_xor_sync(0xffffffffu, ss, o);
    }
    __shared__ float sh[16];
    int w = tid>>5, lane = tid&31;
    if (lane==0){ sh[w]=s; sh[8+w]=ss; }
    __syncthreads();
    if (tid==0){
        float a=0.f,b2=0.f;
        #pragma unroll
        for (int i=0;i<8;i++){ a+=sh[i]; b2+=sh[8+i]; }
        float mu  = a*(1.f/Dn);
        float var = b2*(1.f/Dn) - mu*mu;
        sh[0]=mu; sh[1]=rsqrtf(var + 1e-6f);
    }
    __syncthreads();
    float mu = sh[0], rstd = sh[1];
    float4 sc = ((const float4*)scale)[tid];
    float4 bi = ((const float4*)bias)[tid];
    float4 o4;
    o4.x=(v.x-mu)*rstd*sc.x+bi.x;
    o4.y=(v.y-mu)*rstd*sc.y+bi.y;
    o4.z=(v.z-mu)*rstd*sc.z+bi.z;
    o4.w=(v.w-mu)*rstd*sc.w+bi.w;
    store_split4(o4, row*Dn + tid*4);
}

// ---------------------------------------------------------------------------
// MMA-based FUSED global logits + joint softmax + global merge, per (h, l, b).
// S = q@krow^T (masked row<=col), joint softmax with local logits from
// g_joint (normalized local probs written back), O = gatt@rowattn -> g_merged.
// ---------------------------------------------------------------------------
__global__ void __launch_bounds__(256)
global_fused_kernel()
{
    extern __shared__ __nv_bfloat16 bsm[];
    __nv_bfloat16* qh  = bsm;             // q, reused for gatt hi
    __nv_bfloat16* ql  = bsm + TILE_E;    // q lo, reused for gatt lo
    __nv_bfloat16* kh  = bsm + 2*TILE_E;  // krow
    __nv_bfloat16* kl  = bsm + 3*TILE_E;
    __nv_bfloat16* rTh = bsm + 4*TILE_E;  // rowattn [dim][seg]
    __nv_bfloat16* rTl = bsm + 5*TILE_E;
    float* red = (float*)(bsm + 6*TILE_E); // [256]

    int h = blockIdx.x, l = blockIdx.y, b = blockIdx.z;
    int tid = threadIdx.x, lane = tid & 31, wid = tid >> 5;
    int g = lane >> 2, c = lane & 3;

    for (int i = tid; i < 64*64; i += 256){
        int r = i >> 6, cc = i & 63;
        size_t t = ((size_t)b*NSn + r)*SEGn + l;
        size_t off = t*Dn + h*HDn + cc;
        float qv = g_q[off], kv = g_krow[off], rv = g_rowattn[off];
        __nv_bfloat16 qH = __float2bfloat16_rn(qv);
        __nv_bfloat16 kH = __float2bfloat16_rn(kv);
        __nv_bfloat16 rH = __float2bfloat16_rn(rv);
        qh[r*KST+cc] = qH; ql[r*KST+cc] = __float2bfloat16_rn(qv - __bfloat162float(qH));
        kh[r*KST+cc] = kH; kl[r*KST+cc] = __float2bfloat16_rn(kv - __bfloat162float(kH));
        rTh[cc*KST+r] = rH; rTl[cc*KST+r] = __float2bfloat16_rn(rv - __bfloat162float(rH));
    }
    __syncthreads();

    int mband = wid & 3, nhalf = wid >> 2;
    int n0 = nhalf*32;
    int rA = mband*16 + g, rB = rA + 8;   // qseg rows

    // --- S = q @ krow^T ---
    float accS[4][4];
    #pragma unroll
    for (int t=0;t<4;t++)
        #pragma unroll
        for (int q2=0;q2<4;q2++) accS[t][q2]=0.f;

    #pragma unroll
    for (int kk = 0; kk < 4; kk++){
        int ab = rA*KST + kk*16 + 2*c;
        uint32_t ah[4], al[4];
        ah[0]=*(uint32_t*)(qh+ab); ah[1]=*(uint32_t*)(qh+ab+8*KST);
        ah[2]=*(uint32_t*)(qh+ab+8); ah[3]=*(uint32_t*)(qh+ab+8*KST+8);
        al[0]=*(uint32_t*)(ql+ab); al[1]=*(uint32_t*)(ql+ab+8*KST);
        al[2]=*(uint32_t*)(ql+ab+8); al[3]=*(uint32_t*)(ql+ab+8*KST+8);
        #pragma unroll
        for (int t = 0; t < 4; t++){
            int bb = (n0 + t*8 + g)*KST + kk*16 + 2*c;
            uint32_t bh[2], bl[2];
            bh[0]=*(uint32_t*)(kh+bb); bh[1]=*(uint32_t*)(kh+bb+8);
            bl[0]=*(uint32_t*)(kl+bb); bl[1]=*(uint32_t*)(kl+bb+8);
            mma16816(accS[t], ah, bh);
            mma16816(accS[t], ah, bl);
            mma16816(accS[t], al, bh);
        }
    }

    // mask: qseg <= kseg gets NEG
    #pragma unroll
    for (int t = 0; t < 4; t++){
        int col0 = n0 + t*8 + 2*c;
        accS[t][0] += (rA <= col0   ? NEGV : 0.f);
        accS[t][1] += (rA <= col0+1 ? NEGV : 0.f);
        accS[t][2] += (rB <= col0   ? NEGV : 0.f);
        accS[t][3] += (rB <= col0+1 ? NEGV : 0.f);
    }

    // local masked logits for the same (row, col) ownership
    size_t tA = ((size_t)b*NSn + rA)*SEGn + l;
    size_t tB = ((size_t)b*NSn + rB)*SEGn + l;
    size_t jbA = (tA*Hn + h)*128;
    size_t jbB = (tB*Hn + h)*128;
    float2 locA[4], locB[4];
    #pragma unroll
    for (int t = 0; t < 4; t++){
        int col0 = n0 + t*8 + 2*c;
        locA[t] = *(const float2*)(g_joint + jbA + col0);
        locB[t] = *(const float2*)(g_joint + jbB + col0);
    }

    // --- joint softmax over [local | global] ---
    float mA = -1e30f, mB = -1e30f;
    #pragma unroll
    for (int t=0;t<4;t++){
        mA = fmaxf(mA, fmaxf(fmaxf(accS[t][0], accS[t][1]), fmaxf(locA[t].x, locA[t].y)));
        mB = fmaxf(mB, fmaxf(fmaxf(accS[t][2], accS[t][3]), fmaxf(locB[t].x, locB[t].y)));
    }
    mA = fmaxf(mA, __shfl_xor_sync(0xffffffffu, mA, 1));
    mA = fmaxf(mA, __shfl_xor_sync(0xffffffffu, mA, 2));
    mB = fmaxf(mB, __shfl_xor_sync(0xffffffffu, mB, 1));
    mB = fmaxf(mB, __shfl_xor_sync(0xffffffffu, mB, 2));
    if (c == 0){ red[nhalf*64 + rA] = mA; red[nhalf*64 + rB] = mB; }
    __syncthreads();
    float mmA = fmaxf(red[rA], red[64+rA]);
    float mmB = fmaxf(red[rB], red[64+rB]);

    float p[4][4];
    float sA = 0.f, sB = 0.f;
    #pragma unroll
    for (int t=0;t<4;t++){
        p[t][0] = __expf(accS[t][0]-mmA); p[t][1] = __expf(accS[t][1]-mmA);
        p[t][2] = __expf(accS[t][2]-mmB); p[t][3] = __expf(accS[t][3]-mmB);
        locA[t].x = __expf(locA[t].x-mmA); locA[t].y = __expf(locA[t].y-mmA);
        locB[t].x = __expf(locB[t].x-mmB); locB[t].y = __expf(locB[t].y-mmB);
        sA += p[t][0]+p[t][1] + locA[t].x+locA[t].y;
        sB += p[t][2]+p[t][3] + locB[t].x+locB[t].y;
    }
    sA += __shfl_xor_sync(0xffffffffu, sA, 1);
    sA += __shfl_xor_sync(0xffffffffu, sA, 2);
    sB += __shfl_xor_sync(0xffffffffu, sB, 1);
    sB += __shfl_xor_sync(0xffffffffu, sB, 2);
    if (c == 0){ red[128 + nhalf*64 + rA] = sA; red[128 + nhalf*64 + rB] = sB; }
    __syncthreads();   // all S reads done; q tiles free
    float invA = 1.f/(red[128+rA] + red[128+64+rA]);
    float invB = 1.f/(red[128+rB] + red[128+64+rB]);

    // normalized local probs back to g_joint (consumed by local_merged)
    #pragma unroll
    for (int t = 0; t < 4; t++){
        int col0 = n0 + t*8 + 2*c;
        float2 wA, wB;
        wA.x = locA[t].x*invA; wA.y = locA[t].y*invA;
        wB.x = locB[t].x*invB; wB.y = locB[t].y*invB;
        *(float2*)(g_joint + jbA + col0) = wA;
        *(float2*)(g_joint + jbB + col0) = wB;
    }

    // normalized gatt (split) into q region: [qseg][kseg]
    #pragma unroll
    for (int t = 0; t < 4; t++){
        int col0 = n0 + t*8 + 2*c;
        *(uint32_t*)(qh + rA*KST + col0) = pack_hi(p[t][0]*invA, p[t][1]*invA);
        *(uint32_t*)(ql + rA*KST + col0) = pack_lo(p[t][0]*invA, p[t][1]*invA);
        *(uint32_t*)(qh + rB*KST + col0) = pack_hi(p[t][2]*invB, p[t][3]*invB);
        *(uint32_t*)(ql + rB*KST + col0) = pack_lo(p[t][2]*invB, p[t][3]*invB);
    }
    __syncthreads();

    // --- O = gatt @ rowattn (rT tiles) -> g_merged ---
    float accO[4][4];
    #pragma unroll
    for (int t=0;t<4;t++)
        #pragma unroll
        for (int q2=0;q2<4;q2++) accO[t][q2]=0.f;

    #pragma unroll
    for (int kk = 0; kk < 4; kk++){
        int ab = rA*KST + kk*16 + 2*c;
        uint32_t ah[4], al[4];
        ah[0]=*(uint32_t*)(qh+ab); ah[1]=*(uint32_t*)(qh+ab+8*KST);
        ah[2]=*(uint32_t*)(qh+ab+8); ah[3]=*(uint32_t*)(qh+ab+8*KST+8);
        al[0]=*(uint32_t*)(ql+ab); al[1]=*(uint32_t*)(ql+ab+8*KST);
        al[2]=*(uint32_t*)(ql+ab+8); al[3]=*(uint32_t*)(ql+ab+8*KST+8);
        #pragma unroll
        for (int t = 0; t < 4; t++){
            int bb = (n0 + t*8 + g)*KST + kk*16 + 2*c;
            uint32_t bh[2], bl[2];
            bh[0]=*(uint32_t*)(rTh+bb); bh[1]=*(uint32_t*)(rTh+bb+8);
            bl[0]=*(uint32_t*)(rTl+bb); bl[1]=*(uint32_t*)(rTl+bb+8);
            mma16816(accO[t], ah, bh);
            mma16816(accO[t], ah, bl);
            mma16816(accO[t], al, bh);
        }
    }

    #pragma unroll
    for (int t = 0; t < 4; t++){
        int col0 = n0 + t*8 + 2*c;   // dim
        size_t oA = tA*Dn + h*HDn + col0;
        size_t oB = tB*Dn + h*HDn + col0;
        *(float2*)(g_merged + oA) = make_float2(accO[t][0], accO[t][1]);
        *(float2*)(g_merged + oB) = make_float2(accO[t][2], accO[t][3]);
    }
}

// ---------------------------------------------------------------------------
// MMA-based local_merged finalizer per (h, seg, b):
// merged = g_merged + latt@v, written only as bf16 split.
// ---------------------------------------------------------------------------
__global__ void __launch_bounds__(256)
local_merged_kernel()
{
    __shared__ __nv_bfloat16 ph [TILE_E];
    __shared__ __nv_bfloat16 pl [TILE_E];
    __shared__ __nv_bfloat16 vTh[TILE_E];
    __shared__ __nv_bfloat16 vTl[TILE_E];

    int h = blockIdx.x, seg = blockIdx.y, b = blockIdx.z;
    int tid = threadIdx.x, lane = tid & 31, wid = tid >> 5;
    int g = lane >> 2, c = lane & 3;
    size_t tok0 = ((size_t)b*NSn + seg)*SEGn;

    for (int i = tid; i < 64*64; i += 256){
        int r = i >> 6, cc = i & 63;
        float pv = g_joint[((tok0+r)*Hn+h)*128 + cc];
        float vv = g_v[(tok0+r)*Dn + h*HDn + cc];
        __nv_bfloat16 pH = __float2bfloat16_rn(pv);
        __nv_bfloat16 vH = __float2bfloat16_rn(vv);
        ph[r*KST+cc] = pH;  pl[r*KST+cc]  = __float2bfloat16_rn(pv - __bfloat162float(pH));
        vTh[cc*KST+r] = vH; vTl[cc*KST+r] = __float2bfloat16_rn(vv - __bfloat162float(vH));
    }
    __syncthreads();

    int mband = wid & 3, nhalf = wid >> 2;
    int r0 = mband*16, n0 = nhalf*32;
    int rA = r0 + g, rB = rA + 8;

    float accO[4][4];
    #pragma unroll
    for (int t=0;t<4;t++)
        #pragma unroll
        for (int q2=0;q2<4;q2++) accO[t][q2]=0.f;

    #pragma unroll
    for (int kk = 0; kk < 4; kk++){
        int ab = rA*KST + kk*16 + 2*c;
        uint32_t ah[4], al[4];
        ah[0]=*(uint32_t*)(ph+ab); ah[1]=*(uint32_t*)(ph+ab+8*KST);
        ah[2]=*(uint32_t*)(ph+ab+8); ah[3]=*(uint32_t*)(ph+ab+8*KST+8);
        al[0]=*(uint32_t*)(pl+ab); al[1]=*(uint32_t*)(pl+ab+8*KST);
        al[2]=*(uint32_t*)(pl+ab+8); al[3]=*(uint32_t*)(pl+ab+8*KST+8);
        #pragma unroll
        for (int t = 0; t < 4; t++){
            int bb = (n0 + t*8 + g)*KST + kk*16 + 2*c;
            uint32_t bh[2], bl[2];
            bh[0]=*(uint32_t*)(vTh+bb); bh[1]=*(uint32_t*)(vTh+bb+8);
            bl[0]=*(uint32_t*)(vTl+bb); bl[1]=*(uint32_t*)(vTl+bb+8);
            mma16816(accO[t], ah, bh);
            mma16816(accO[t], ah, bl);
            mma16816(accO[t], al, bh);
        }
    }

    #pragma unroll
    for (int t = 0; t < 4; t++){
        int col0 = n0 + t*8 + 2*c;
        size_t oA = (tok0+rA)*Dn + h*HDn + col0;
        size_t oB = (tok0+rB)*Dn + h*HDn + col0;
        float2 mA = *(const float2*)(g_merged + oA);
        float2 mB = *(const float2*)(g_merged + oB);
        store_split2(mA.x + accO[t][0], mA.y + accO[t][1], oA);
        store_split2(mB.x + accO[t][2], mB.y + accO[t][3], oB);
    }
}

// ---------------------------------------------------------------------------
// Launch
// ---------------------------------------------------------------------------
extern "C" void kernel_launch(void* const* d_in, const int* in_sizes, int n_in,
                              void* d_out, int out_size)
{
    const float* x    = (const float*)d_in[0];
    const float* Wq   = (const float*)d_in[1];
    const float* Wk   = (const float*)d_in[2];
    const float* Wv   = (const float*)d_in[3];
    const float* Wro  = (const float*)d_in[4];
    const float* lns  = (const float*)d_in[5];
    const float* lnb  = (const float*)d_in[6];
    const float* Wk2  = (const float*)d_in[7];
    const float* Wout = (const float*)d_in[8];
    float* out = (float*)d_out;

    cudaFuncSetAttribute(local_attn_kernel,
                         cudaFuncAttributeMaxDynamicSharedMemorySize, LA_SMEM);
    cudaFuncSetAttribute(global_fused_kernel,
                         cudaFuncAttributeMaxDynamicSharedMemorySize, LA_SMEM);
    cudaFuncSetAttribute(hmma_gemm,
                         cudaFuncAttributeMaxDynamicSharedMemorySize, HG_SMEM);

    dim3 gg(8, 128);
    dim3 gq(8, 128, 3);         // fused QKV
    dim3 ga(Hn, NSn, Bn);
    dim3 gl(Hn, SEGn, Bn);
    const int ACT_BLKS = (NTOK*Dn/4)/256;

    convert_wt<<<dim3(32,32,6),256>>>(Wq, Wk, Wv, Wro, Wk2, Wout);

    convert_act<<<ACT_BLKS,256>>>(x);
    hmma_gemm<<<gq,256,HG_SMEM>>>(-1, nullptr,0, nullptr, 0.f);     // q,k,v

    local_attn_kernel<<<ga,256,LA_SMEM>>>();                        // mma + rowattn split

    hmma_gemm<<<gg,256,HG_SMEM>>>(3, nullptr,4, x, 1.f);            // t1 = rowattn@Wro + x
    ln_kernel<<<NTOK,256>>>(lns, lnb);                              // -> ahi/alo
    hmma_gemm<<<gg,256,HG_SMEM>>>(4, nullptr,5, nullptr, 1.f);      // krow

    global_fused_kernel<<<gl,256,LA_SMEM>>>();                      // mma logits+softmax+gmerge
    local_merged_kernel<<<ga,256>>>();                              // mma finalize + split

    hmma_gemm<<<gg,256,HG_SMEM>>>(5, out,0, nullptr, 1.f);
}

// round 15
// speedup vs baseline: 2.8911x; 1.1153x over previous
#include <cuda_runtime.h>
#include <cuda_bf16.h>
#include <math.h>
#include <stdint.h>

// Problem constants
#define Bn   4
#define Sn   4096
#define Dn   1024
#define Hn   16
#define HDn  64
#define SEGn 64
#define NSn  64
#define NTOK (Bn*Sn)          // 16384
#define NEGV (-1.0e10f)

// ---------------------------------------------------------------------------
// Scratch (device globals)
// ---------------------------------------------------------------------------
__device__ float g_q      [(size_t)NTOK*Dn];
__device__ float g_k      [(size_t)NTOK*Dn];
__device__ float g_v      [(size_t)NTOK*Dn];
__device__ float g_rowattn[(size_t)NTOK*Dn];
__device__ float g_t1     [(size_t)NTOK*Dn];
__device__ float g_krow   [(size_t)NTOK*Dn];
__device__ float g_merged [(size_t)NTOK*Dn];   // global_merged partial
__device__ float g_joint  [(size_t)NTOK*Hn*128]; // [0:64] local logits -> local probs

// Split-bf16 staging
__device__ __nv_bfloat16 g_ahi [(size_t)NTOK*Dn];
__device__ __nv_bfloat16 g_alo [(size_t)NTOK*Dn];
__device__ __nv_bfloat16 g_wthi[(size_t)6*Dn*Dn];   // WT[w][n][k] = W[w][k][n]
__device__ __nv_bfloat16 g_wtlo[(size_t)6*Dn*Dn];

__device__ __forceinline__ float* cpick(float* ext, int id){
    switch(id){ case 1: return g_q; case 2: return g_k; case 3: return g_v;
                case 4: return g_t1; case 5: return g_krow; }
    return ext;
}

__device__ __forceinline__ uint32_t pack_hi(float a, float b){
    __nv_bfloat162 t(__float2bfloat16_rn(a), __float2bfloat16_rn(b));
    return *(uint32_t*)&t;
}
__device__ __forceinline__ uint32_t pack_lo(float a, float b){
    float ha = __bfloat162float(__float2bfloat16_rn(a));
    float hb = __bfloat162float(__float2bfloat16_rn(b));
    __nv_bfloat162 t(__float2bfloat16_rn(a-ha), __float2bfloat16_rn(b-hb));
    return *(uint32_t*)&t;
}
__device__ __forceinline__ void store_split2(float a, float b, size_t off){
    *(uint32_t*)(g_ahi + off) = pack_hi(a,b);
    *(uint32_t*)(g_alo + off) = pack_lo(a,b);
}
__device__ __forceinline__ void store_split4(float4 v, size_t off){
    uint2 hv, lv;
    hv.x = pack_hi(v.x,v.y); hv.y = pack_hi(v.z,v.w);
    lv.x = pack_lo(v.x,v.y); lv.y = pack_lo(v.z,v.w);
    *(uint2*)(g_ahi + off) = hv;
    *(uint2*)(g_alo + off) = lv;
}

__device__ __forceinline__ uint32_t smem_u32(const void* p){
    uint32_t a;
    asm("{ .reg .u64 t; cvta.to.shared.u64 t, %1; cvt.u32.u64 %0, t; }" : "=r"(a) : "l"(p));
    return a;
}
__device__ __forceinline__ void cp_async16(uint32_t dst, const void* src){
    asm volatile("cp.async.cg.shared.global [%0], [%1], 16;" :: "r"(dst), "l"(src) : "memory");
}
__device__ __forceinline__ void cp_commit(){
    asm volatile("cp.async.commit_group;" ::: "memory");
}
template<int N> __device__ __forceinline__ void cp_wait(){
    asm volatile("cp.async.wait_group %0;" :: "n"(N) : "memory");
}
__device__ __forceinline__ void mma16816(float* c, const uint32_t* a, const uint32_t* b){
    asm volatile("mma.sync.aligned.m16n8k16.row.col.f32.bf16.bf16.f32 "
                 "{%0,%1,%2,%3}, {%4,%5,%6,%7}, {%8,%9}, {%0,%1,%2,%3};"
                 : "+f"(c[0]), "+f"(c[1]), "+f"(c[2]), "+f"(c[3])
                 : "r"(a[0]), "r"(a[1]), "r"(a[2]), "r"(a[3]), "r"(b[0]), "r"(b[1]));
}
__device__ __forceinline__ void ldsm_x4(uint32_t* r, uint32_t addr){
    asm volatile("ldmatrix.sync.aligned.m8n8.x4.shared.b16 {%0,%1,%2,%3}, [%4];"
                 : "=r"(r[0]), "=r"(r[1]), "=r"(r[2]), "=r"(r[3]) : "r"(addr));
}

// ---------------------------------------------------------------------------
// Split conversion: x fp32 -> (hi,lo) bf16
// ---------------------------------------------------------------------------
__global__ void __launch_bounds__(256)
convert_act(const float* __restrict__ src)
{
    size_t i = (size_t)blockIdx.x*256 + threadIdx.x;
    float4 v = ((const float4*)src)[i];
    store_split4(v, i*4);
}

// ---------------------------------------------------------------------------
// Weight transpose+split: WT[w][n][k] = split(W[w][k][n])
// ---------------------------------------------------------------------------
__global__ void __launch_bounds__(256)
convert_wt(const float* __restrict__ W0, const float* __restrict__ W1,
           const float* __restrict__ W2, const float* __restrict__ W3,
           const float* __restrict__ W4, const float* __restrict__ W5)
{
    const float* Ws[6] = {W0,W1,W2,W3,W4,W5};
    const float* W = Ws[blockIdx.z];
    __shared__ float tile[32][33];
    int n0 = blockIdx.x*32, k0 = blockIdx.y*32;
    int tx = threadIdx.x & 31, ty = threadIdx.x >> 5;
    #pragma unroll
    for (int j = 0; j < 4; j++){
        int r = ty + j*8;
        tile[r][tx] = W[(size_t)(k0+r)*Dn + n0 + tx];
    }
    __syncthreads();
    size_t wbase = (size_t)blockIdx.z*Dn*Dn;
    #pragma unroll
    for (int j = 0; j < 4; j++){
        int r = ty + j*8;
        float a = tile[tx][r];
        __nv_bfloat16 hi = __float2bfloat16_rn(a);
        __nv_bfloat16 lo = __float2bfloat16_rn(a - __bfloat162float(hi));
        size_t o = wbase + (size_t)(n0+r)*Dn + k0 + tx;
        g_wthi[o] = hi;
        g_wtlo[o] = lo;
    }
}

// ---------------------------------------------------------------------------
// HMMA GEMM (BK=32, occ 2, fused-QKV mode) — ldmatrix fragment loads
// ---------------------------------------------------------------------------
#define AST  40
#define TSZB (128*AST*2)          // 10240 B per matrix
#define BUFB (4*TSZB)             // 40960 B per buffer
#define HG_SMEM (2*BUFB)          // 81920 B

__global__ void __launch_bounds__(256,2)
hmma_gemm(int widx, float* Cext, int Cid, const float* __restrict__ R, float alpha)
{
    extern __shared__ char smem[];
    uint32_t sb = smem_u32(smem);
    int tid = threadIdx.x, lane = tid & 31, wid = tid >> 5;
    int wm = wid & 1, wn = wid >> 1;
    int m0 = blockIdx.y*128, n0 = blockIdx.x*128;

    if (widx < 0){
        widx = blockIdx.z;
        Cid  = blockIdx.z + 1;
        alpha = (blockIdx.z == 0) ? 0.125f : 1.f;
    }
    float* C = cpick(Cext, Cid);

    const __nv_bfloat16* srcs[4];
    srcs[0] = g_ahi  + (size_t)m0*Dn;
    srcs[1] = g_alo  + (size_t)m0*Dn;
    srcs[2] = g_wthi + (size_t)widx*Dn*Dn + (size_t)n0*Dn;
    srcs[3] = g_wtlo + (size_t)widx*Dn*Dn + (size_t)n0*Dn;

    auto fill = [&](int c, int buf){
        int k0 = c*32;
        uint32_t base = sb + buf*BUFB;
        #pragma unroll
        for (int t = 0; t < 4; t++){
            #pragma unroll
            for (int it = 0; it < 2; it++){
                int idx = it*256 + tid;
                int r = idx >> 2, cc = idx & 3;
                cp_async16(base + t*TSZB + r*(AST*2) + cc*16,
                           srcs[t] + (size_t)r*Dn + k0 + cc*8);
            }
        }
        cp_commit();
    };

    // ldmatrix lane-dependent byte offsets
    uint32_t aoff = (uint32_t)(((wm*64 + (lane&15))*AST + ((lane>>4)<<3)) * 2);
    uint32_t boff = (uint32_t)(((wn*32 + ((lane>>4)<<3) + (lane&7))*AST + (((lane>>3)&1)<<3)) * 2);

    float acc[4][4][4];
    #pragma unroll
    for (int i=0;i<4;i++)
        #pragma unroll
        for (int j=0;j<4;j++)
            #pragma unroll
            for (int q=0;q<4;q++) acc[i][j][q]=0.f;

    fill(0, 0);

    for (int c = 0; c < 32; c++){
        int buf = c & 1;
        if (c < 31){ fill(c+1, buf^1); cp_wait<1>(); }
        else       { cp_wait<0>(); }
        __syncthreads();

        #pragma unroll
        for (int ks = 0; ks < 2; ks++){
            uint32_t ah[4][4], al[4][4], bh2[2][4], bl2[2][4];
            uint32_t abase = sb + buf*BUFB + aoff + (uint32_t)(ks*32);
            #pragma unroll
            for (int i=0;i<4;i++){
                uint32_t ad = abase + i*(16*AST*2);
                ldsm_x4(ah[i], ad);
                ldsm_x4(al[i], ad + TSZB);
            }
            uint32_t bbase = sb + buf*BUFB + 2*TSZB + boff + (uint32_t)(ks*32);
            #pragma unroll
            for (int tp=0;tp<2;tp++){
                uint32_t bd = bbase + tp*(16*AST*2);
                ldsm_x4(bh2[tp], bd);
                ldsm_x4(bl2[tp], bd + TSZB);
            }
            #pragma unroll
            for (int i = 0; i < 4; i++)
                #pragma unroll
                for (int j = 0; j < 4; j++){
                    const uint32_t* bh = bh2[j>>1] + (j&1)*2;
                    const uint32_t* bl = bl2[j>>1] + (j&1)*2;
                    mma16816(acc[i][j], ah[i], bh);
                    mma16816(acc[i][j], ah[i], bl);
                    mma16816(acc[i][j], al[i], bh);
                }
        }
        __syncthreads();
    }

    #pragma unroll
    for (int i = 0; i < 4; i++){
        int row = m0 + wm*64 + i*16 + (lane>>2);
        #pragma unroll
        for (int j = 0; j < 4; j++){
            int col = n0 + wn*32 + j*8 + 2*(lane&3);
            size_t o0 = (size_t)row*Dn + col;
            size_t o1 = (size_t)(row+8)*Dn + col;
            float2 v0, v1;
            v0.x = alpha*acc[i][j][0]; v0.y = alpha*acc[i][j][1];
            v1.x = alpha*acc[i][j][2]; v1.y = alpha*acc[i][j][3];
            if (R){
                float2 r0 = *(const float2*)(R + o0);
                float2 r1 = *(const float2*)(R + o1);
                v0.x += r0.x; v0.y += r0.y; v1.x += r1.x; v1.y += r1.y;
            }
            *(float2*)(C + o0) = v0;
            *(float2*)(C + o1) = v1;
        }
    }
}

// ---------------------------------------------------------------------------
// MMA attention tiles: KST=72 (144 B rows, ldmatrix conflict-free).
// ---------------------------------------------------------------------------
#define KST 72
#define TILE_E (64*KST)
#define TB (TILE_E*2)                  // tile bytes
#define LA_SMEM (6*TB + 256*4)         // 56320 B

// ldmatrix helpers for attention tiles (byte offsets within tile)
#define ATT_AOFF(lane, r0)  ((uint32_t)((((r0) + ((lane)&15))*KST + (((lane)>>4)<<3))*2))
#define ATT_BOFF(lane, n0)  ((uint32_t)(((((n0) + (((lane)>>4)<<3) + ((lane)&7))*KST) + ((((lane)>>3)&1)<<3))*2))

// ---------------------------------------------------------------------------
// MMA local attention per (h, seg, b)
// ---------------------------------------------------------------------------
__global__ void __launch_bounds__(256)
local_attn_kernel()
{
    extern __shared__ __nv_bfloat16 bsm[];
    __nv_bfloat16* qh  = bsm;             // also reused for P hi
    __nv_bfloat16* ql  = bsm + TILE_E;    // also reused for P lo
    __nv_bfloat16* vTh = bsm + 4*TILE_E;  // [dim][key]
    __nv_bfloat16* vTl = bsm + 5*TILE_E;
    float* red = (float*)(bsm + 6*TILE_E);

    int h = blockIdx.x, seg = blockIdx.y, b = blockIdx.z;
    int tid = threadIdx.x, lane = tid & 31, wid = tid >> 5;
    int g = lane >> 2, c = lane & 3;
    size_t tok0 = ((size_t)b*NSn + seg)*SEGn;
    uint32_t sbB = smem_u32(bsm);

    // Load (float4) + split-convert q,k row-major; v transposed
    for (int i = tid; i < 64*16; i += 256){
        int r = i >> 4, c4 = (i & 15)*4;
        size_t off = (tok0 + r)*Dn + h*HDn + c4;
        float4 qv = *(const float4*)(g_q + off);
        float4 kv = *(const float4*)(g_k + off);
        float4 vv = *(const float4*)(g_v + off);
        uint2 t;
        t.x = pack_hi(qv.x,qv.y); t.y = pack_hi(qv.z,qv.w);
        *(uint2*)(qh + r*KST + c4) = t;
        t.x = pack_lo(qv.x,qv.y); t.y = pack_lo(qv.z,qv.w);
        *(uint2*)(ql + r*KST + c4) = t;
        t.x = pack_hi(kv.x,kv.y); t.y = pack_hi(kv.z,kv.w);
        *(uint2*)(bsm + 2*TILE_E + r*KST + c4) = t;
        t.x = pack_lo(kv.x,kv.y); t.y = pack_lo(kv.z,kv.w);
        *(uint2*)(bsm + 3*TILE_E + r*KST + c4) = t;
        float e[4] = {vv.x, vv.y, vv.z, vv.w};
        #pragma unroll
        for (int j=0;j<4;j++){
            __nv_bfloat16 hV = __float2bfloat16_rn(e[j]);
            vTh[(c4+j)*KST + r] = hV;
            vTl[(c4+j)*KST + r] = __float2bfloat16_rn(e[j] - __bfloat162float(hV));
        }
    }
    __syncthreads();

    int mband = wid & 3, nhalf = wid >> 2;
    int r0 = mband*16, n0 = nhalf*32;
    int rA = r0 + g, rB = rA + 8;
    uint32_t aoff = ATT_AOFF(lane, r0);
    uint32_t boff = ATT_BOFF(lane, n0);

    // --- S = q @ k^T ---
    float accS[4][4];
    #pragma unroll
    for (int t=0;t<4;t++)
        #pragma unroll
        for (int q2=0;q2<4;q2++) accS[t][q2]=0.f;

    #pragma unroll
    for (int kk = 0; kk < 4; kk++){
        uint32_t ah[4], al[4], bh2[2][4], bl2[2][4];
        uint32_t ad = sbB + aoff + kk*32;
        ldsm_x4(ah, ad);
        ldsm_x4(al, ad + TB);
        uint32_t bd = sbB + 2*TB + boff + kk*32;
        ldsm_x4(bh2[0], bd);
        ldsm_x4(bl2[0], bd + TB);
        ldsm_x4(bh2[1], bd + 16*KST*2);
        ldsm_x4(bl2[1], bd + 16*KST*2 + TB);
        #pragma unroll
        for (int t = 0; t < 4; t++){
            const uint32_t* bh = bh2[t>>1] + (t&1)*2;
            const uint32_t* bl = bl2[t>>1] + (t&1)*2;
            mma16816(accS[t], ah, bh);
            mma16816(accS[t], ah, bl);
            mma16816(accS[t], al, bh);
        }
    }

    // masked logits -> g_joint
    size_t jbA = ((tok0 + rA)*Hn + h)*128;
    size_t jbB = ((tok0 + rB)*Hn + h)*128;
    #pragma unroll
    for (int t = 0; t < 4; t++){
        int col0 = n0 + t*8 + 2*c;
        float2 w0, w1;
        w0.x = accS[t][0] + (rA < col0   ? NEGV : 0.f);
        w0.y = accS[t][1] + (rA < col0+1 ? NEGV : 0.f);
        w1.x = accS[t][2] + (rB < col0   ? NEGV : 0.f);
        w1.y = accS[t][3] + (rB < col0+1 ? NEGV : 0.f);
        *(float2*)(g_joint + jbA + col0) = w0;
        *(float2*)(g_joint + jbB + col0) = w1;
    }

    // --- unmasked softmax ---
    float mA = -1e30f, mB = -1e30f;
    #pragma unroll
    for (int t=0;t<4;t++){
        mA = fmaxf(mA, fmaxf(accS[t][0], accS[t][1]));
        mB = fmaxf(mB, fmaxf(accS[t][2], accS[t][3]));
    }
    mA = fmaxf(mA, __shfl_xor_sync(0xffffffffu, mA, 1));
    mA = fmaxf(mA, __shfl_xor_sync(0xffffffffu, mA, 2));
    mB = fmaxf(mB, __shfl_xor_sync(0xffffffffu, mB, 1));
    mB = fmaxf(mB, __shfl_xor_sync(0xffffffffu, mB, 2));
    if (c == 0){ red[nhalf*64 + rA] = mA; red[nhalf*64 + rB] = mB; }
    __syncthreads();
    float mmA = fmaxf(red[rA], red[64+rA]);
    float mmB = fmaxf(red[rB], red[64+rB]);

    float p[4][4];
    float sA = 0.f, sB = 0.f;
    #pragma unroll
    for (int t=0;t<4;t++){
        p[t][0] = __expf(accS[t][0]-mmA); p[t][1] = __expf(accS[t][1]-mmA);
        p[t][2] = __expf(accS[t][2]-mmB); p[t][3] = __expf(accS[t][3]-mmB);
        sA += p[t][0]+p[t][1]; sB += p[t][2]+p[t][3];
    }
    sA += __shfl_xor_sync(0xffffffffu, sA, 1);
    sA += __shfl_xor_sync(0xffffffffu, sA, 2);
    sB += __shfl_xor_sync(0xffffffffu, sB, 1);
    sB += __shfl_xor_sync(0xffffffffu, sB, 2);
    if (c == 0){ red[128 + nhalf*64 + rA] = sA; red[128 + nhalf*64 + rB] = sB; }
    __syncthreads();   // sums visible; q tiles free for reuse
    float invA = 1.f/(red[128+rA] + red[128+64+rA]);
    float invB = 1.f/(red[128+rB] + red[128+64+rB]);

    // store unnormalized P (split) into q region: [row][key]
    #pragma unroll
    for (int t = 0; t < 4; t++){
        int col0 = n0 + t*8 + 2*c;
        *(uint32_t*)(qh + rA*KST + col0) = pack_hi(p[t][0], p[t][1]);
        *(uint32_t*)(ql + rA*KST + col0) = pack_lo(p[t][0], p[t][1]);
        *(uint32_t*)(qh + rB*KST + col0) = pack_hi(p[t][2], p[t][3]);
        *(uint32_t*)(ql + rB*KST + col0) = pack_lo(p[t][2], p[t][3]);
    }
    __syncthreads();

    // --- O = P @ V (vT tiles) ---
    float accO[4][4];
    #pragma unroll
    for (int t=0;t<4;t++)
        #pragma unroll
        for (int q2=0;q2<4;q2++) accO[t][q2]=0.f;

    #pragma unroll
    for (int kk = 0; kk < 4; kk++){
        uint32_t ah[4], al[4], bh2[2][4], bl2[2][4];
        uint32_t ad = sbB + aoff + kk*32;
        ldsm_x4(ah, ad);
        ldsm_x4(al, ad + TB);
        uint32_t bd = sbB + 4*TB + boff + kk*32;
        ldsm_x4(bh2[0], bd);
        ldsm_x4(bl2[0], bd + TB);
        ldsm_x4(bh2[1], bd + 16*KST*2);
        ldsm_x4(bl2[1], bd + 16*KST*2 + TB);
        #pragma unroll
        for (int t = 0; t < 4; t++){
            const uint32_t* bh = bh2[t>>1] + (t&1)*2;
            const uint32_t* bl = bl2[t>>1] + (t&1)*2;
            mma16816(accO[t], ah, bh);
            mma16816(accO[t], ah, bl);
            mma16816(accO[t], al, bh);
        }
    }

    #pragma unroll
    for (int t = 0; t < 4; t++){
        int col0 = n0 + t*8 + 2*c;   // dim
        size_t oA = (tok0+rA)*Dn + h*HDn + col0;
        size_t oB = (tok0+rB)*Dn + h*HDn + col0;
        float2 vA, vB;
        vA.x = accO[t][0]*invA; vA.y = accO[t][1]*invA;
        vB.x = accO[t][2]*invB; vB.y = accO[t][3]*invB;
        *(float2*)(g_rowattn + oA) = vA;
        *(float2*)(g_rowattn + oB) = vB;
        store_split2(vA.x, vA.y, oA);
        store_split2(vB.x, vB.y, oB);
    }
}

// ---------------------------------------------------------------------------
// LayerNorm over D=1024 per token: writes bf16 split directly
// ---------------------------------------------------------------------------
__global__ void __launch_bounds__(256)
ln_kernel(const float* __restrict__ scale, const float* __restrict__ bias)
{
    size_t row = blockIdx.x;
    int tid = threadIdx.x;
    float4 v = ((const float4*)(g_t1 + row*Dn))[tid];
    float s  = v.x+v.y+v.z+v.w;
    float ss = v.x*v.x+v.y*v.y+v.z*v.z+v.w*v.w;
    #pragma unroll
    for (int o=16;o;o>>=1){
        s  += __shfl_xor_sync(0xffffffffu, s, o);
        ss += __shfl_xor_sync(0xffffffffu, ss, o);
    }
    __shared__ float sh[16];
    int w = tid>>5, lane = tid&31;
    if (lane==0){ sh[w]=s; sh[8+w]=ss; }
    __syncthreads();
    if (tid==0){
        float a=0.f,b2=0.f;
        #pragma unroll
        for (int i=0;i<8;i++){ a+=sh[i]; b2+=sh[8+i]; }
        float mu  = a*(1.f/Dn);
        float var = b2*(1.f/Dn) - mu*mu;
        sh[0]=mu; sh[1]=rsqrtf(var + 1e-6f);
    }
    __syncthreads();
    float mu = sh[0], rstd = sh[1];
    float4 sc = ((const float4*)scale)[tid];
    float4 bi = ((const float4*)bias)[tid];
    float4 o4;
    o4.x=(v.x-mu)*rstd*sc.x+bi.x;
    o4.y=(v.y-mu)*rstd*sc.y+bi.y;
    o4.z=(v.z-mu)*rstd*sc.z+bi.z;
    o4.w=(v.w-mu)*rstd*sc.w+bi.w;
    store_split4(o4, row*Dn + tid*4);
}

// ---------------------------------------------------------------------------
// MMA FUSED global logits + joint softmax + global merge, per (h, l, b)
// ---------------------------------------------------------------------------
__global__ void __launch_bounds__(256)
global_fused_kernel()
{
    extern __shared__ __nv_bfloat16 bsm[];
    __nv_bfloat16* qh  = bsm;             // q, reused for gatt hi
    __nv_bfloat16* ql  = bsm + TILE_E;
    __nv_bfloat16* rTh = bsm + 4*TILE_E;  // rowattn [dim][seg]
    __nv_bfloat16* rTl = bsm + 5*TILE_E;
    float* red = (float*)(bsm + 6*TILE_E);

    int h = blockIdx.x, l = blockIdx.y, b = blockIdx.z;
    int tid = threadIdx.x, lane = tid & 31, wid = tid >> 5;
    int g = lane >> 2, c = lane & 3;
    uint32_t sbB = smem_u32(bsm);

    for (int i = tid; i < 64*16; i += 256){
        int r = i >> 4, c4 = (i & 15)*4;
        size_t t = ((size_t)b*NSn + r)*SEGn + l;
        size_t off = t*Dn + h*HDn + c4;
        float4 qv = *(const float4*)(g_q + off);
        float4 kv = *(const float4*)(g_krow + off);
        float4 rv = *(const float4*)(g_rowattn + off);
        uint2 tt;
        tt.x = pack_hi(qv.x,qv.y); tt.y = pack_hi(qv.z,qv.w);
        *(uint2*)(qh + r*KST + c4) = tt;
        tt.x = pack_lo(qv.x,qv.y); tt.y = pack_lo(qv.z,qv.w);
        *(uint2*)(ql + r*KST + c4) = tt;
        tt.x = pack_hi(kv.x,kv.y); tt.y = pack_hi(kv.z,kv.w);
        *(uint2*)(bsm + 2*TILE_E + r*KST + c4) = tt;
        tt.x = pack_lo(kv.x,kv.y); tt.y = pack_lo(kv.z,kv.w);
        *(uint2*)(bsm + 3*TILE_E + r*KST + c4) = tt;
        float e[4] = {rv.x, rv.y, rv.z, rv.w};
        #pragma unroll
        for (int j=0;j<4;j++){
            __nv_bfloat16 hV = __float2bfloat16_rn(e[j]);
            rTh[(c4+j)*KST + r] = hV;
            rTl[(c4+j)*KST + r] = __float2bfloat16_rn(e[j] - __bfloat162float(hV));
        }
    }
    __syncthreads();

    int mband = wid & 3, nhalf = wid >> 2;
    int n0 = nhalf*32;
    int rA = mband*16 + g, rB = rA + 8;   // qseg rows
    uint32_t aoff = ATT_AOFF(lane, mband*16);
    uint32_t boff = ATT_BOFF(lane, n0);

    // --- S = q @ krow^T ---
    float accS[4][4];
    #pragma unroll
    for (int t=0;t<4;t++)
        #pragma unroll
        for (int q2=0;q2<4;q2++) accS[t][q2]=0.f;

    #pragma unroll
    for (int kk = 0; kk < 4; kk++){
        uint32_t ah[4], al[4], bh2[2][4], bl2[2][4];
        uint32_t ad = sbB + aoff + kk*32;
        ldsm_x4(ah, ad);
        ldsm_x4(al, ad + TB);
        uint32_t bd = sbB + 2*TB + boff + kk*32;
        ldsm_x4(bh2[0], bd);
        ldsm_x4(bl2[0], bd + TB);
        ldsm_x4(bh2[1], bd + 16*KST*2);
        ldsm_x4(bl2[1], bd + 16*KST*2 + TB);
        #pragma unroll
        for (int t = 0; t < 4; t++){
            const uint32_t* bh = bh2[t>>1] + (t&1)*2;
            const uint32_t* bl = bl2[t>>1] + (t&1)*2;
            mma16816(accS[t], ah, bh);
            mma16816(accS[t], ah, bl);
            mma16816(accS[t], al, bh);
        }
    }

    // mask: qseg <= kseg gets NEG
    #pragma unroll
    for (int t = 0; t < 4; t++){
        int col0 = n0 + t*8 + 2*c;
        accS[t][0] += (rA <= col0   ? NEGV : 0.f);
        accS[t][1] += (rA <= col0+1 ? NEGV : 0.f);
        accS[t][2] += (rB <= col0   ? NEGV : 0.f);
        accS[t][3] += (rB <= col0+1 ? NEGV : 0.f);
    }

    size_t tA = ((size_t)b*NSn + rA)*SEGn + l;
    size_t tB = ((size_t)b*NSn + rB)*SEGn + l;
    size_t jbA = (tA*Hn + h)*128;
    size_t jbB = (tB*Hn + h)*128;
    float2 locA[4], locB[4];
    #pragma unroll
    for (int t = 0; t < 4; t++){
        int col0 = n0 + t*8 + 2*c;
        locA[t] = *(const float2*)(g_joint + jbA + col0);
        locB[t] = *(const float2*)(g_joint + jbB + col0);
    }

    // --- joint softmax over [local | global] ---
    float mA = -1e30f, mB = -1e30f;
    #pragma unroll
    for (int t=0;t<4;t++){
        mA = fmaxf(mA, fmaxf(fmaxf(accS[t][0], accS[t][1]), fmaxf(locA[t].x, locA[t].y)));
        mB = fmaxf(mB, fmaxf(fmaxf(accS[t][2], accS[t][3]), fmaxf(locB[t].x, locB[t].y)));
    }
    mA = fmaxf(mA, __shfl_xor_sync(0xffffffffu, mA, 1));
    mA = fmaxf(mA, __shfl_xor_sync(0xffffffffu, mA, 2));
    mB = fmaxf(mB, __shfl_xor_sync(0xffffffffu, mB, 1));
    mB = fmaxf(mB, __shfl_xor_sync(0xffffffffu, mB, 2));
    if (c == 0){ red[nhalf*64 + rA] = mA; red[nhalf*64 + rB] = mB; }
    __syncthreads();
    float mmA = fmaxf(red[rA], red[64+rA]);
    float mmB = fmaxf(red[rB], red[64+rB]);

    float p[4][4];
    float sA = 0.f, sB = 0.f;
    #pragma unroll
    for (int t=0;t<4;t++){
        p[t][0] = __expf(accS[t][0]-mmA); p[t][1] = __expf(accS[t][1]-mmA);
        p[t][2] = __expf(accS[t][2]-mmB); p[t][3] = __expf(accS[t][3]-mmB);
        locA[t].x = __expf(locA[t].x-mmA); locA[t].y = __expf(locA[t].y-mmA);
        locB[t].x = __expf(locB[t].x-mmB); locB[t].y = __expf(locB[t].y-mmB);
        sA += p[t][0]+p[t][1] + locA[t].x+locA[t].y;
        sB += p[t][2]+p[t][3] + locB[t].x+locB[t].y;
    }
    sA += __shfl_xor_sync(0xffffffffu, sA, 1);
    sA += __shfl_xor_sync(0xffffffffu, sA, 2);
    sB += __shfl_xor_sync(0xffffffffu, sB, 1);
    sB += __shfl_xor_sync(0xffffffffu, sB, 2);
    if (c == 0){ red[128 + nhalf*64 + rA] = sA; red[128 + nhalf*64 + rB] = sB; }
    __syncthreads();   // all S reads done; q tiles free
    float invA = 1.f/(red[128+rA] + red[128+64+rA]);
    float invB = 1.f/(red[128+rB] + red[128+64+rB]);

    // normalized local probs back to g_joint
    #pragma unroll
    for (int t = 0; t < 4; t++){
        int col0 = n0 + t*8 + 2*c;
        float2 wA, wB;
        wA.x = locA[t].x*invA; wA.y = locA[t].y*invA;
        wB.x = locB[t].x*invB; wB.y = locB[t].y*invB;
        *(float2*)(g_joint + jbA + col0) = wA;
        *(float2*)(g_joint + jbB + col0) = wB;
    }

    // normalized gatt (split) into q region
    #pragma unroll
    for (int t = 0; t < 4; t++){
        int col0 = n0 + t*8 + 2*c;
        *(uint32_t*)(qh + rA*KST + col0) = pack_hi(p[t][0]*invA, p[t][1]*invA);
        *(uint32_t*)(ql + rA*KST + col0) = pack_lo(p[t][0]*invA, p[t][1]*invA);
        *(uint32_t*)(qh + rB*KST + col0) = pack_hi(p[t][2]*invB, p[t][3]*invB);
        *(uint32_t*)(ql + rB*KST + col0) = pack_lo(p[t][2]*invB, p[t][3]*invB);
    }
    __syncthreads();

    // --- O = gatt @ rowattn (rT tiles) -> g_merged ---
    float accO[4][4];
    #pragma unroll
    for (int t=0;t<4;t++)
        #pragma unroll
        for (int q2=0;q2<4;q2++) accO[t][q2]=0.f;

    #pragma unroll
    for (int kk = 0; kk < 4; kk++){
        uint32_t ah[4], al[4], bh2[2][4], bl2[2][4];
        uint32_t ad = sbB + aoff + kk*32;
        ldsm_x4(ah, ad);
        ldsm_x4(al, ad + TB);
        uint32_t bd = sbB + 4*TB + boff + kk*32;
        ldsm_x4(bh2[0], bd);
        ldsm_x4(bl2[0], bd + TB);
        ldsm_x4(bh2[1], bd + 16*KST*2);
        ldsm_x4(bl2[1], bd + 16*KST*2 + TB);
        #pragma unroll
        for (int t = 0; t < 4; t++){
            const uint32_t* bh = bh2[t>>1] + (t&1)*2;
            const uint32_t* bl = bl2[t>>1] + (t&1)*2;
            mma16816(accO[t], ah, bh);
            mma16816(accO[t], ah, bl);
            mma16816(accO[t], al, bh);
        }
    }

    #pragma unroll
    for (int t = 0; t < 4; t++){
        int col0 = n0 + t*8 + 2*c;   // dim
        size_t oA = tA*Dn + h*HDn + col0;
        size_t oB = tB*Dn + h*HDn + col0;
        *(float2*)(g_merged + oA) = make_float2(accO[t][0], accO[t][1]);
        *(float2*)(g_merged + oB) = make_float2(accO[t][2], accO[t][3]);
    }
}

// ---------------------------------------------------------------------------
// MMA local_merged finalizer per (h, seg, b)
// ---------------------------------------------------------------------------
__global__ void __launch_bounds__(256)
local_merged_kernel()
{
    __shared__ __nv_bfloat16 lmsm[4*TILE_E];
    __nv_bfloat16* ph  = lmsm;
    __nv_bfloat16* pl  = lmsm + TILE_E;
    __nv_bfloat16* vTh = lmsm + 2*TILE_E;
    __nv_bfloat16* vTl = lmsm + 3*TILE_E;

    int h = blockIdx.x, seg = blockIdx.y, b = blockIdx.z;
    int tid = threadIdx.x, lane = tid & 31, wid = tid >> 5;
    int g = lane >> 2, c = lane & 3;
    size_t tok0 = ((size_t)b*NSn + seg)*SEGn;
    uint32_t sbB = smem_u32(lmsm);

    for (int i = tid; i < 64*16; i += 256){
        int r = i >> 4, c4 = (i & 15)*4;
        float4 pv = *(const float4*)(g_joint + ((tok0+r)*Hn+h)*128 + c4);
        float4 vv = *(const float4*)(g_v + (tok0+r)*Dn + h*HDn + c4);
        uint2 t;
        t.x = pack_hi(pv.x,pv.y); t.y = pack_hi(pv.z,pv.w);
        *(uint2*)(ph + r*KST + c4) = t;
        t.x = pack_lo(pv.x,pv.y); t.y = pack_lo(pv.z,pv.w);
        *(uint2*)(pl + r*KST + c4) = t;
        float e[4] = {vv.x, vv.y, vv.z, vv.w};
        #pragma unroll
        for (int j=0;j<4;j++){
            __nv_bfloat16 hV = __float2bfloat16_rn(e[j]);
            vTh[(c4+j)*KST + r] = hV;
            vTl[(c4+j)*KST + r] = __float2bfloat16_rn(e[j] - __bfloat162float(hV));
        }
    }
    __syncthreads();

    int mband = wid & 3, nhalf = wid >> 2;
    int r0 = mband*16, n0 = nhalf*32;
    int rA = r0 + g, rB = rA + 8;
    uint32_t aoff = ATT_AOFF(lane, r0);
    uint32_t boff = ATT_BOFF(lane, n0);

    float accO[4][4];
    #pragma unroll
    for (int t=0;t<4;t++)
        #pragma unroll
        for (int q2=0;q2<4;q2++) accO[t][q2]=0.f;

    #pragma unroll
    for (int kk = 0; kk < 4; kk++){
        uint32_t ah[4], al[4], bh2[2][4], bl2[2][4];
        uint32_t ad = sbB + aoff + kk*32;
        ldsm_x4(ah, ad);
        ldsm_x4(al, ad + TB);
        uint32_t bd = sbB + 2*TB + boff + kk*32;
        ldsm_x4(bh2[0], bd);
        ldsm_x4(bl2[0], bd + TB);
        ldsm_x4(bh2[1], bd + 16*KST*2);
        ldsm_x4(bl2[1], bd + 16*KST*2 + TB);
        #pragma unroll
        for (int t = 0; t < 4; t++){
            const uint32_t* bh = bh2[t>>1] + (t&1)*2;
            const uint32_t* bl = bl2[t>>1] + (t&1)*2;
            mma16816(accO[t], ah, bh);
            mma16816(accO[t], ah, bl);
            mma16816(accO[t], al, bh);
        }
    }

    #pragma unroll
    for (int t = 0; t < 4; t++){
        int col0 = n0 + t*8 + 2*c;
        size_t oA = (tok0+rA)*Dn + h*HDn + col0;
        size_t oB = (tok0+rB)*Dn + h*HDn + col0;
        float2 mA = *(const float2*)(g_merged + oA);
        float2 mB = *(const float2*)(g_merged + oB);
        store_split2(mA.x + accO[t][0], mA.y + accO[t][1], oA);
        store_split2(mB.x + accO[t][2], mB.y + accO[t][3], oB);
    }
}

// ---------------------------------------------------------------------------
// Launch
// ---------------------------------------------------------------------------
extern "C" void kernel_launch(void* const* d_in, const int* in_sizes, int n_in,
                              void* d_out, int out_size)
{
    const float* x    = (const float*)d_in[0];
    const float* Wq   = (const float*)d_in[1];
    const float* Wk   = (const float*)d_in[2];
    const float* Wv   = (const float*)d_in[3];
    const float* Wro  = (const float*)d_in[4];
    const float* lns  = (const float*)d_in[5];
    const float* lnb  = (const float*)d_in[6];
    const float* Wk2  = (const float*)d_in[7];
    const float* Wout = (const float*)d_in[8];
    float* out = (float*)d_out;

    cudaFuncSetAttribute(local_attn_kernel,
                         cudaFuncAttributeMaxDynamicSharedMemorySize, LA_SMEM);
    cudaFuncSetAttribute(global_fused_kernel,
                         cudaFuncAttributeMaxDynamicSharedMemorySize, LA_SMEM);
    cudaFuncSetAttribute(hmma_gemm,
                         cudaFuncAttributeMaxDynamicSharedMemorySize, HG_SMEM);

    dim3 gg(8, 128);
    dim3 gq(8, 128, 3);         // fused QKV
    dim3 ga(Hn, NSn, Bn);
    dim3 gl(Hn, SEGn, Bn);
    const int ACT_BLKS = (NTOK*Dn/4)/256;

    convert_wt<<<dim3(32,32,6),256>>>(Wq, Wk, Wv, Wro, Wk2, Wout);

    convert_act<<<ACT_BLKS,256>>>(x);
    hmma_gemm<<<gq,256,HG_SMEM>>>(-1, nullptr,0, nullptr, 0.f);     // q,k,v

    local_attn_kernel<<<ga,256,LA_SMEM>>>();                        // mma + rowattn split

    hmma_gemm<<<gg,256,HG_SMEM>>>(3, nullptr,4, x, 1.f);            // t1 = rowattn@Wro + x
    ln_kernel<<<NTOK,256>>>(lns, lnb);                              // -> ahi/alo
    hmma_gemm<<<gg,256,HG_SMEM>>>(4, nullptr,5, nullptr, 1.f);      // krow

    global_fused_kernel<<<gl,256,LA_SMEM>>>();                      // mma logits+softmax+gmerge
    local_merged_kernel<<<ga,256>>>();                              // mma finalize + split

    hmma_gemm<<<gg,256,HG_SMEM>>>(5, out,0, nullptr, 1.f);
}

// round 16
// speedup vs baseline: 2.9049x; 1.0048x over previous
#include <cuda_runtime.h>
#include <cuda_bf16.h>
#include <math.h>
#include <stdint.h>

// Problem constants
#define Bn   4
#define Sn   4096
#define Dn   1024
#define Hn   16
#define HDn  64
#define SEGn 64
#define NSn  64
#define NTOK (Bn*Sn)          // 16384
#define NEGV (-1.0e10f)

// ---------------------------------------------------------------------------
// Scratch (device globals)
// ---------------------------------------------------------------------------
__device__ float g_t1     [(size_t)NTOK*Dn];
__device__ float g_merged [(size_t)NTOK*Dn];     // global_merged partial
__device__ float g_joint  [(size_t)NTOK*Hn*128]; // [0:64] local logits -> probs

// Split-bf16 tensors (hi/lo pairs)
__device__ __nv_bfloat16 g_ahi [(size_t)NTOK*Dn];   // staging (x, t2, merged)
__device__ __nv_bfloat16 g_alo [(size_t)NTOK*Dn];
__device__ __nv_bfloat16 g_qhi [(size_t)NTOK*Dn];
__device__ __nv_bfloat16 g_qlo [(size_t)NTOK*Dn];
__device__ __nv_bfloat16 g_khi [(size_t)NTOK*Dn];
__device__ __nv_bfloat16 g_klo [(size_t)NTOK*Dn];
__device__ __nv_bfloat16 g_vhi [(size_t)NTOK*Dn];
__device__ __nv_bfloat16 g_vlo [(size_t)NTOK*Dn];
__device__ __nv_bfloat16 g_krhi[(size_t)NTOK*Dn];
__device__ __nv_bfloat16 g_krlo[(size_t)NTOK*Dn];
__device__ __nv_bfloat16 g_rahi[(size_t)NTOK*Dn];   // rowattn split (persistent)
__device__ __nv_bfloat16 g_ralo[(size_t)NTOK*Dn];
__device__ __nv_bfloat16 g_wthi[(size_t)6*Dn*Dn];
__device__ __nv_bfloat16 g_wtlo[(size_t)6*Dn*Dn];

__device__ __forceinline__ float* cpick(float* ext, int id){
    if (id == 4) return g_t1;
    return ext;
}
__device__ __forceinline__ __nv_bfloat16* hpick(int id){
    switch(id){ case 11: return g_qhi; case 12: return g_khi;
                case 13: return g_vhi; case 14: return g_krhi; }
    return g_ahi;
}
__device__ __forceinline__ __nv_bfloat16* lpick(int id){
    switch(id){ case 11: return g_qlo; case 12: return g_klo;
                case 13: return g_vlo; case 14: return g_krlo; }
    return g_alo;
}

__device__ __forceinline__ uint32_t pack_hi(float a, float b){
    __nv_bfloat162 t(__float2bfloat16_rn(a), __float2bfloat16_rn(b));
    return *(uint32_t*)&t;
}
__device__ __forceinline__ uint32_t pack_lo(float a, float b){
    float ha = __bfloat162float(__float2bfloat16_rn(a));
    float hb = __bfloat162float(__float2bfloat16_rn(b));
    __nv_bfloat162 t(__float2bfloat16_rn(a-ha), __float2bfloat16_rn(b-hb));
    return *(uint32_t*)&t;
}
__device__ __forceinline__ void store_split4(float4 v, size_t off){
    uint2 hv, lv;
    hv.x = pack_hi(v.x,v.y); hv.y = pack_hi(v.z,v.w);
    lv.x = pack_lo(v.x,v.y); lv.y = pack_lo(v.z,v.w);
    *(uint2*)(g_ahi + off) = hv;
    *(uint2*)(g_alo + off) = lv;
}

__device__ __forceinline__ uint32_t smem_u32(const void* p){
    uint32_t a;
    asm("{ .reg .u64 t; cvta.to.shared.u64 t, %1; cvt.u32.u64 %0, t; }" : "=r"(a) : "l"(p));
    return a;
}
__device__ __forceinline__ void cp_async16(uint32_t dst, const void* src){
    asm volatile("cp.async.cg.shared.global [%0], [%1], 16;" :: "r"(dst), "l"(src) : "memory");
}
__device__ __forceinline__ void cp_commit(){
    asm volatile("cp.async.commit_group;" ::: "memory");
}
template<int N> __device__ __forceinline__ void cp_wait(){
    asm volatile("cp.async.wait_group %0;" :: "n"(N) : "memory");
}
__device__ __forceinline__ void mma16816(float* c, const uint32_t* a, const uint32_t* b){
    asm volatile("mma.sync.aligned.m16n8k16.row.col.f32.bf16.bf16.f32 "
                 "{%0,%1,%2,%3}, {%4,%5,%6,%7}, {%8,%9}, {%0,%1,%2,%3};"
                 : "+f"(c[0]), "+f"(c[1]), "+f"(c[2]), "+f"(c[3])
                 : "r"(a[0]), "r"(a[1]), "r"(a[2]), "r"(a[3]), "r"(b[0]), "r"(b[1]));
}
__device__ __forceinline__ void ldsm_x4(uint32_t* r, uint32_t addr){
    asm volatile("ldmatrix.sync.aligned.m8n8.x4.shared.b16 {%0,%1,%2,%3}, [%4];"
                 : "=r"(r[0]), "=r"(r[1]), "=r"(r[2]), "=r"(r[3]) : "r"(addr));
}
__device__ __forceinline__ void ldsm_x4_t(uint32_t* r, uint32_t addr){
    asm volatile("ldmatrix.sync.aligned.m8n8.x4.trans.shared.b16 {%0,%1,%2,%3}, [%4];"
                 : "=r"(r[0]), "=r"(r[1]), "=r"(r[2]), "=r"(r[3]) : "r"(addr));
}

// ---------------------------------------------------------------------------
// Split conversion: x fp32 -> staging (hi,lo)
// ---------------------------------------------------------------------------
__global__ void __launch_bounds__(256)
convert_act(const float* __restrict__ src)
{
    size_t i = (size_t)blockIdx.x*256 + threadIdx.x;
    float4 v = ((const float4*)src)[i];
    store_split4(v, i*4);
}

// ---------------------------------------------------------------------------
// Weight transpose+split: WT[w][n][k] = split(W[w][k][n])
// ---------------------------------------------------------------------------
__global__ void __launch_bounds__(256)
convert_wt(const float* __restrict__ W0, const float* __restrict__ W1,
           const float* __restrict__ W2, const float* __restrict__ W3,
           const float* __restrict__ W4, const float* __restrict__ W5)
{
    const float* Ws[6] = {W0,W1,W2,W3,W4,W5};
    const float* W = Ws[blockIdx.z];
    __shared__ float tile[32][33];
    int n0 = blockIdx.x*32, k0 = blockIdx.y*32;
    int tx = threadIdx.x & 31, ty = threadIdx.x >> 5;
    #pragma unroll
    for (int j = 0; j < 4; j++){
        int r = ty + j*8;
        tile[r][tx] = W[(size_t)(k0+r)*Dn + n0 + tx];
    }
    __syncthreads();
    size_t wbase = (size_t)blockIdx.z*Dn*Dn;
    #pragma unroll
    for (int j = 0; j < 4; j++){
        int r = ty + j*8;
        float a = tile[tx][r];
        __nv_bfloat16 hi = __float2bfloat16_rn(a);
        __nv_bfloat16 lo = __float2bfloat16_rn(a - __bfloat162float(hi));
        size_t o = wbase + (size_t)(n0+r)*Dn + k0 + tx;
        g_wthi[o] = hi;
        g_wtlo[o] = lo;
    }
}

// ---------------------------------------------------------------------------
// HMMA GEMM (BK=32, occ 2) — ldmatrix loads; epilogue fp32 OR split-bf16.
// Aid: 0 = staging (ahi/alo), 1 = rowattn (rahi/ralo).
// Cid: 0 = fp32 ext, 4 = fp32 g_t1, 11..14 = split (q,k,v,krow).
// widx < 0: fused QKV (blockIdx.z selects weight; Cid = 11+z).
// ---------------------------------------------------------------------------
#define AST  40
#define TSZB (128*AST*2)          // 10240 B per matrix
#define BUFB (4*TSZB)             // 40960 B per buffer
#define HG_SMEM (2*BUFB)          // 81920 B

__global__ void __launch_bounds__(256,2)
hmma_gemm(int widx, int Aid, float* Cext, int Cid, const float* __restrict__ R, float alpha)
{
    extern __shared__ char smem[];
    uint32_t sb = smem_u32(smem);
    int tid = threadIdx.x, lane = tid & 31, wid = tid >> 5;
    int wm = wid & 1, wn = wid >> 1;
    int m0 = blockIdx.y*128, n0 = blockIdx.x*128;

    if (widx < 0){
        widx = blockIdx.z;
        Cid  = 11 + blockIdx.z;
        alpha = (blockIdx.z == 0) ? 0.125f : 1.f;
    }

    const __nv_bfloat16* srcs[4];
    srcs[0] = (Aid ? g_rahi : g_ahi) + (size_t)m0*Dn;
    srcs[1] = (Aid ? g_ralo : g_alo) + (size_t)m0*Dn;
    srcs[2] = g_wthi + (size_t)widx*Dn*Dn + (size_t)n0*Dn;
    srcs[3] = g_wtlo + (size_t)widx*Dn*Dn + (size_t)n0*Dn;

    auto fill = [&](int c, int buf){
        int k0 = c*32;
        uint32_t base = sb + buf*BUFB;
        #pragma unroll
        for (int t = 0; t < 4; t++){
            #pragma unroll
            for (int it = 0; it < 2; it++){
                int idx = it*256 + tid;
                int r = idx >> 2, cc = idx & 3;
                cp_async16(base + t*TSZB + r*(AST*2) + cc*16,
                           srcs[t] + (size_t)r*Dn + k0 + cc*8);
            }
        }
        cp_commit();
    };

    uint32_t aoff = (uint32_t)(((wm*64 + (lane&15))*AST + ((lane>>4)<<3)) * 2);
    uint32_t boff = (uint32_t)(((wn*32 + ((lane>>4)<<3) + (lane&7))*AST + (((lane>>3)&1)<<3)) * 2);

    float acc[4][4][4];
    #pragma unroll
    for (int i=0;i<4;i++)
        #pragma unroll
        for (int j=0;j<4;j++)
            #pragma unroll
            for (int q=0;q<4;q++) acc[i][j][q]=0.f;

    fill(0, 0);

    for (int c = 0; c < 32; c++){
        int buf = c & 1;
        if (c < 31){ fill(c+1, buf^1); cp_wait<1>(); }
        else       { cp_wait<0>(); }
        __syncthreads();

        #pragma unroll
        for (int ks = 0; ks < 2; ks++){
            uint32_t ah[4][4], al[4][4], bh2[2][4], bl2[2][4];
            uint32_t abase = sb + buf*BUFB + aoff + (uint32_t)(ks*32);
            #pragma unroll
            for (int i=0;i<4;i++){
                uint32_t ad = abase + i*(16*AST*2);
                ldsm_x4(ah[i], ad);
                ldsm_x4(al[i], ad + TSZB);
            }
            uint32_t bbase = sb + buf*BUFB + 2*TSZB + boff + (uint32_t)(ks*32);
            #pragma unroll
            for (int tp=0;tp<2;tp++){
                uint32_t bd = bbase + tp*(16*AST*2);
                ldsm_x4(bh2[tp], bd);
                ldsm_x4(bl2[tp], bd + TSZB);
            }
            #pragma unroll
            for (int i = 0; i < 4; i++)
                #pragma unroll
                for (int j = 0; j < 4; j++){
                    const uint32_t* bh = bh2[j>>1] + (j&1)*2;
                    const uint32_t* bl = bl2[j>>1] + (j&1)*2;
                    mma16816(acc[i][j], ah[i], bh);
                    mma16816(acc[i][j], ah[i], bl);
                    mma16816(acc[i][j], al[i], bh);
                }
        }
        __syncthreads();
    }

    if (Cid >= 11){
        __nv_bfloat16* Hi = hpick(Cid);
        __nv_bfloat16* Lo = lpick(Cid);
        #pragma unroll
        for (int i = 0; i < 4; i++){
            int row = m0 + wm*64 + i*16 + (lane>>2);
            #pragma unroll
            for (int j = 0; j < 4; j++){
                int col = n0 + wn*32 + j*8 + 2*(lane&3);
                size_t o0 = (size_t)row*Dn + col;
                size_t o1 = (size_t)(row+8)*Dn + col;
                float a0 = alpha*acc[i][j][0], a1 = alpha*acc[i][j][1];
                float a2 = alpha*acc[i][j][2], a3 = alpha*acc[i][j][3];
                *(uint32_t*)(Hi + o0) = pack_hi(a0, a1);
                *(uint32_t*)(Lo + o0) = pack_lo(a0, a1);
                *(uint32_t*)(Hi + o1) = pack_hi(a2, a3);
                *(uint32_t*)(Lo + o1) = pack_lo(a2, a3);
            }
        }
    } else {
        float* C = cpick(Cext, Cid);
        #pragma unroll
        for (int i = 0; i < 4; i++){
            int row = m0 + wm*64 + i*16 + (lane>>2);
            #pragma unroll
            for (int j = 0; j < 4; j++){
                int col = n0 + wn*32 + j*8 + 2*(lane&3);
                size_t o0 = (size_t)row*Dn + col;
                size_t o1 = (size_t)(row+8)*Dn + col;
                float2 v0, v1;
                v0.x = alpha*acc[i][j][0]; v0.y = alpha*acc[i][j][1];
                v1.x = alpha*acc[i][j][2]; v1.y = alpha*acc[i][j][3];
                if (R){
                    float2 r0 = *(const float2*)(R + o0);
                    float2 r1 = *(const float2*)(R + o1);
                    v0.x += r0.x; v0.y += r0.y; v1.x += r1.x; v1.y += r1.y;
                }
                *(float2*)(C + o0) = v0;
                *(float2*)(C + o1) = v1;
            }
        }
    }
}

// ---------------------------------------------------------------------------
// Attention tiles: KST=72 (144 B rows, ldmatrix conflict-free, 16B aligned)
// ---------------------------------------------------------------------------
#define KST 72
#define TILEB (64*KST*2)               // 9216 B per tile
#define LA_SMEM (6*TILEB + 1024)       // 56320 B

#define ATT_AOFF(lane, r0)  ((uint32_t)((((r0) + ((lane)&15))*KST + (((lane)>>4)<<3))*2))
#define ATT_BOFF(lane, n0)  ((uint32_t)(((((n0) + (((lane)>>4)<<3) + ((lane)&7))*KST) + ((((lane)>>3)&1)<<3))*2))
// trans (row-major [k][n] tile): row = k-group, byte-col = n-group
#define ATT_TOFF(lane, n0)  ((uint32_t)((((((lane)>>3)&1)*8 + ((lane)&7))*KST + (n0) + (((lane)>>4)<<3))*2))

// ---------------------------------------------------------------------------
// MMA local attention per (h, seg, b): all operands pre-split, cp.async load.
// ---------------------------------------------------------------------------
__global__ void __launch_bounds__(256)
local_attn_kernel()
{
    extern __shared__ __nv_bfloat16 bsm[];
    __nv_bfloat16* qh = bsm;            // reused for P hi/lo
    __nv_bfloat16* ql = bsm + TILEB/2;
    float* red = (float*)((char*)bsm + 6*TILEB);

    int h = blockIdx.x, seg = blockIdx.y, b = blockIdx.z;
    int tid = threadIdx.x, lane = tid & 31, wid = tid >> 5;
    int g = lane >> 2, c = lane & 3;
    size_t tok0 = ((size_t)b*NSn + seg)*SEGn;
    size_t hb = tok0*Dn + h*HDn;
    uint32_t sbB = smem_u32(bsm);

    const __nv_bfloat16* srcs[6] = {g_qhi+hb, g_qlo+hb, g_khi+hb, g_klo+hb, g_vhi+hb, g_vlo+hb};
    #pragma unroll
    for (int t = 0; t < 6; t++){
        #pragma unroll
        for (int it = 0; it < 2; it++){
            int idx = it*256 + tid;
            int r = idx >> 3, cc = idx & 7;
            cp_async16(sbB + t*TILEB + r*(KST*2) + cc*16,
                       srcs[t] + (size_t)r*Dn + cc*8);
        }
    }
    cp_commit(); cp_wait<0>();
    __syncthreads();

    int mband = wid & 3, nhalf = wid >> 2;
    int r0 = mband*16, n0 = nhalf*32;
    int rA = r0 + g, rB = rA + 8;
    uint32_t aoff = ATT_AOFF(lane, r0);
    uint32_t boff = ATT_BOFF(lane, n0);
    uint32_t toff = ATT_TOFF(lane, n0);

    // --- S = q @ k^T ---
    float accS[4][4];
    #pragma unroll
    for (int t=0;t<4;t++)
        #pragma unroll
        for (int q2=0;q2<4;q2++) accS[t][q2]=0.f;

    #pragma unroll
    for (int kk = 0; kk < 4; kk++){
        uint32_t ah[4], al[4], bh2[2][4], bl2[2][4];
        uint32_t ad = sbB + aoff + kk*32;
        ldsm_x4(ah, ad);
        ldsm_x4(al, ad + TILEB);
        uint32_t bd = sbB + 2*TILEB + boff + kk*32;
        ldsm_x4(bh2[0], bd);
        ldsm_x4(bl2[0], bd + TILEB);
        ldsm_x4(bh2[1], bd + 16*KST*2);
        ldsm_x4(bl2[1], bd + 16*KST*2 + TILEB);
        #pragma unroll
        for (int t = 0; t < 4; t++){
            const uint32_t* bh = bh2[t>>1] + (t&1)*2;
            const uint32_t* bl = bl2[t>>1] + (t&1)*2;
            mma16816(accS[t], ah, bh);
            mma16816(accS[t], ah, bl);
            mma16816(accS[t], al, bh);
        }
    }

    // masked logits -> g_joint
    size_t jbA = ((tok0 + rA)*Hn + h)*128;
    size_t jbB = ((tok0 + rB)*Hn + h)*128;
    #pragma unroll
    for (int t = 0; t < 4; t++){
        int col0 = n0 + t*8 + 2*c;
        float2 w0, w1;
        w0.x = accS[t][0] + (rA < col0   ? NEGV : 0.f);
        w0.y = accS[t][1] + (rA < col0+1 ? NEGV : 0.f);
        w1.x = accS[t][2] + (rB < col0   ? NEGV : 0.f);
        w1.y = accS[t][3] + (rB < col0+1 ? NEGV : 0.f);
        *(float2*)(g_joint + jbA + col0) = w0;
        *(float2*)(g_joint + jbB + col0) = w1;
    }

    // --- unmasked softmax ---
    float mA = -1e30f, mB = -1e30f;
    #pragma unroll
    for (int t=0;t<4;t++){
        mA = fmaxf(mA, fmaxf(accS[t][0], accS[t][1]));
        mB = fmaxf(mB, fmaxf(accS[t][2], accS[t][3]));
    }
    mA = fmaxf(mA, __shfl_xor_sync(0xffffffffu, mA, 1));
    mA = fmaxf(mA, __shfl_xor_sync(0xffffffffu, mA, 2));
    mB = fmaxf(mB, __shfl_xor_sync(0xffffffffu, mB, 1));
    mB = fmaxf(mB, __shfl_xor_sync(0xffffffffu, mB, 2));
    if (c == 0){ red[nhalf*64 + rA] = mA; red[nhalf*64 + rB] = mB; }
    __syncthreads();
    float mmA = fmaxf(red[rA], red[64+rA]);
    float mmB = fmaxf(red[rB], red[64+rB]);

    float p[4][4];
    float sA = 0.f, sB = 0.f;
    #pragma unroll
    for (int t=0;t<4;t++){
        p[t][0] = __expf(accS[t][0]-mmA); p[t][1] = __expf(accS[t][1]-mmA);
        p[t][2] = __expf(accS[t][2]-mmB); p[t][3] = __expf(accS[t][3]-mmB);
        sA += p[t][0]+p[t][1]; sB += p[t][2]+p[t][3];
    }
    sA += __shfl_xor_sync(0xffffffffu, sA, 1);
    sA += __shfl_xor_sync(0xffffffffu, sA, 2);
    sB += __shfl_xor_sync(0xffffffffu, sB, 1);
    sB += __shfl_xor_sync(0xffffffffu, sB, 2);
    if (c == 0){ red[128 + nhalf*64 + rA] = sA; red[128 + nhalf*64 + rB] = sB; }
    __syncthreads();
    float invA = 1.f/(red[128+rA] + red[128+64+rA]);
    float invB = 1.f/(red[128+rB] + red[128+64+rB]);

    // unnormalized P (split) into q region
    #pragma unroll
    for (int t = 0; t < 4; t++){
        int col0 = n0 + t*8 + 2*c;
        *(uint32_t*)(qh + rA*KST + col0) = pack_hi(p[t][0], p[t][1]);
        *(uint32_t*)(ql + rA*KST + col0) = pack_lo(p[t][0], p[t][1]);
        *(uint32_t*)(qh + rB*KST + col0) = pack_hi(p[t][2], p[t][3]);
        *(uint32_t*)(ql + rB*KST + col0) = pack_lo(p[t][2], p[t][3]);
    }
    __syncthreads();

    // --- O = P @ V, B via trans-ldmatrix on row-major v tiles ---
    float accO[4][4];
    #pragma unroll
    for (int t=0;t<4;t++)
        #pragma unroll
        for (int q2=0;q2<4;q2++) accO[t][q2]=0.f;

    #pragma unroll
    for (int kk = 0; kk < 4; kk++){
        uint32_t ah[4], al[4], bh2[2][4], bl2[2][4];
        uint32_t ad = sbB + aoff + kk*32;
        ldsm_x4(ah, ad);
        ldsm_x4(al, ad + TILEB);
        uint32_t bd = sbB + 4*TILEB + toff + kk*(16*KST*2);
        ldsm_x4_t(bh2[0], bd);
        ldsm_x4_t(bl2[0], bd + TILEB);
        ldsm_x4_t(bh2[1], bd + 16*2);          // n0+16 dims
        ldsm_x4_t(bl2[1], bd + 16*2 + TILEB);
        #pragma unroll
        for (int t = 0; t < 4; t++){
            const uint32_t* bh = bh2[t>>1] + (t&1)*2;
            const uint32_t* bl = bl2[t>>1] + (t&1)*2;
            mma16816(accO[t], ah, bh);
            mma16816(accO[t], ah, bl);
            mma16816(accO[t], al, bh);
        }
    }

    // rowattn = O * inv, split-only store
    #pragma unroll
    for (int t = 0; t < 4; t++){
        int col0 = n0 + t*8 + 2*c;
        size_t oA = (tok0+rA)*Dn + h*HDn + col0;
        size_t oB = (tok0+rB)*Dn + h*HDn + col0;
        float a0 = accO[t][0]*invA, a1 = accO[t][1]*invA;
        float a2 = accO[t][2]*invB, a3 = accO[t][3]*invB;
        *(uint32_t*)(g_rahi + oA) = pack_hi(a0, a1);
        *(uint32_t*)(g_ralo + oA) = pack_lo(a0, a1);
        *(uint32_t*)(g_rahi + oB) = pack_hi(a2, a3);
        *(uint32_t*)(g_ralo + oB) = pack_lo(a2, a3);
    }
}

// ---------------------------------------------------------------------------
// LayerNorm: writes staging split directly
// ---------------------------------------------------------------------------
__global__ void __launch_bounds__(256)
ln_kernel(const float* __restrict__ scale, const float* __restrict__ bias)
{
    size_t row = blockIdx.x;
    int tid = threadIdx.x;
    float4 v = ((const float4*)(g_t1 + row*Dn))[tid];
    float s  = v.x+v.y+v.z+v.w;
    float ss = v.x*v.x+v.y*v.y+v.z*v.z+v.w*v.w;
    #pragma unroll
    for (int o=16;o;o>>=1){
        s  += __shfl_xor_sync(0xffffffffu, s, o);
        ss += __shfl_xor_sync(0xffffffffu, ss, o);
    }
    __shared__ float sh[16];
    int w = tid>>5, lane = tid&31;
    if (lane==0){ sh[w]=s; sh[8+w]=ss; }
    __syncthreads();
    if (tid==0){
        float a=0.f,b2=0.f;
        #pragma unroll
        for (int i=0;i<8;i++){ a+=sh[i]; b2+=sh[8+i]; }
        float mu  = a*(1.f/Dn);
        float var = b2*(1.f/Dn) - mu*mu;
        sh[0]=mu; sh[1]=rsqrtf(var + 1e-6f);
    }
    __syncthreads();
    float mu = sh[0], rstd = sh[1];
    float4 sc = ((const float4*)scale)[tid];
    float4 bi = ((const float4*)bias)[tid];
    float4 o4;
    o4.x=(v.x-mu)*rstd*sc.x+bi.x;
    o4.y=(v.y-mu)*rstd*sc.y+bi.y;
    o4.z=(v.z-mu)*rstd*sc.z+bi.z;
    o4.w=(v.w-mu)*rstd*sc.w+bi.w;
    store_split4(o4, row*Dn + tid*4);
}

// ---------------------------------------------------------------------------
// MMA FUSED global logits + joint softmax + global merge, per (h, l, b)
// ---------------------------------------------------------------------------
__global__ void __launch_bounds__(256)
global_fused_kernel()
{
    extern __shared__ __nv_bfloat16 bsm[];
    __nv_bfloat16* qh = bsm;            // reused for gatt hi/lo
    __nv_bfloat16* ql = bsm + TILEB/2;
    float* red = (float*)((char*)bsm + 6*TILEB);

    int h = blockIdx.x, l = blockIdx.y, b = blockIdx.z;
    int tid = threadIdx.x, lane = tid & 31, wid = tid >> 5;
    int g = lane >> 2, c = lane & 3;
    uint32_t sbB = smem_u32(bsm);

    const __nv_bfloat16* bases[6] = {g_qhi, g_qlo, g_krhi, g_krlo, g_rahi, g_ralo};
    #pragma unroll
    for (int t = 0; t < 6; t++){
        #pragma unroll
        for (int it = 0; it < 2; it++){
            int idx = it*256 + tid;
            int r = idx >> 3, cc = idx & 7;
            size_t src = (((size_t)b*NSn + r)*SEGn + l)*Dn + h*HDn + cc*8;
            cp_async16(sbB + t*TILEB + r*(KST*2) + cc*16, bases[t] + src);
        }
    }
    cp_commit(); cp_wait<0>();
    __syncthreads();

    int mband = wid & 3, nhalf = wid >> 2;
    int n0 = nhalf*32;
    int rA = mband*16 + g, rB = rA + 8;   // qseg rows
    uint32_t aoff = ATT_AOFF(lane, mband*16);
    uint32_t boff = ATT_BOFF(lane, n0);
    uint32_t toff = ATT_TOFF(lane, n0);

    // --- S = q @ krow^T ---
    float accS[4][4];
    #pragma unroll
    for (int t=0;t<4;t++)
        #pragma unroll
        for (int q2=0;q2<4;q2++) accS[t][q2]=0.f;

    #pragma unroll
    for (int kk = 0; kk < 4; kk++){
        uint32_t ah[4], al[4], bh2[2][4], bl2[2][4];
        uint32_t ad = sbB + aoff + kk*32;
        ldsm_x4(ah, ad);
        ldsm_x4(al, ad + TILEB);
        uint32_t bd = sbB + 2*TILEB + boff + kk*32;
        ldsm_x4(bh2[0], bd);
        ldsm_x4(bl2[0], bd + TILEB);
        ldsm_x4(bh2[1], bd + 16*KST*2);
        ldsm_x4(bl2[1], bd + 16*KST*2 + TILEB);
        #pragma unroll
        for (int t = 0; t < 4; t++){
            const uint32_t* bh = bh2[t>>1] + (t&1)*2;
            const uint32_t* bl = bl2[t>>1] + (t&1)*2;
            mma16816(accS[t], ah, bh);
            mma16816(accS[t], ah, bl);
            mma16816(accS[t], al, bh);
        }
    }

    // mask qseg <= kseg
    #pragma unroll
    for (int t = 0; t < 4; t++){
        int col0 = n0 + t*8 + 2*c;
        accS[t][0] += (rA <= col0   ? NEGV : 0.f);
        accS[t][1] += (rA <= col0+1 ? NEGV : 0.f);
        accS[t][2] += (rB <= col0   ? NEGV : 0.f);
        accS[t][3] += (rB <= col0+1 ? NEGV : 0.f);
    }

    size_t tA = ((size_t)b*NSn + rA)*SEGn + l;
    size_t tB = ((size_t)b*NSn + rB)*SEGn + l;
    size_t jbA = (tA*Hn + h)*128;
    size_t jbB = (tB*Hn + h)*128;
    float2 locA[4], locB[4];
    #pragma unroll
    for (int t = 0; t < 4; t++){
        int col0 = n0 + t*8 + 2*c;
        locA[t] = *(const float2*)(g_joint + jbA + col0);
        locB[t] = *(const float2*)(g_joint + jbB + col0);
    }

    // --- joint softmax ---
    float mA = -1e30f, mB = -1e30f;
    #pragma unroll
    for (int t=0;t<4;t++){
        mA = fmaxf(mA, fmaxf(fmaxf(accS[t][0], accS[t][1]), fmaxf(locA[t].x, locA[t].y)));
        mB = fmaxf(mB, fmaxf(fmaxf(accS[t][2], accS[t][3]), fmaxf(locB[t].x, locB[t].y)));
    }
    mA = fmaxf(mA, __shfl_xor_sync(0xffffffffu, mA, 1));
    mA = fmaxf(mA, __shfl_xor_sync(0xffffffffu, mA, 2));
    mB = fmaxf(mB, __shfl_xor_sync(0xffffffffu, mB, 1));
    mB = fmaxf(mB, __shfl_xor_sync(0xffffffffu, mB, 2));
    if (c == 0){ red[nhalf*64 + rA] = mA; red[nhalf*64 + rB] = mB; }
    __syncthreads();
    float mmA = fmaxf(red[rA], red[64+rA]);
    float mmB = fmaxf(red[rB], red[64+rB]);

    float p[4][4];
    float sA = 0.f, sB = 0.f;
    #pragma unroll
    for (int t=0;t<4;t++){
        p[t][0] = __expf(accS[t][0]-mmA); p[t][1] = __expf(accS[t][1]-mmA);
        p[t][2] = __expf(accS[t][2]-mmB); p[t][3] = __expf(accS[t][3]-mmB);
        locA[t].x = __expf(locA[t].x-mmA); locA[t].y = __expf(locA[t].y-mmA);
        locB[t].x = __expf(locB[t].x-mmB); locB[t].y = __expf(locB[t].y-mmB);
        sA += p[t][0]+p[t][1] + locA[t].x+locA[t].y;
        sB += p[t][2]+p[t][3] + locB[t].x+locB[t].y;
    }
    sA += __shfl_xor_sync(0xffffffffu, sA, 1);
    sA += __shfl_xor_sync(0xffffffffu, sA, 2);
    sB += __shfl_xor_sync(0xffffffffu, sB, 1);
    sB += __shfl_xor_sync(0xffffffffu, sB, 2);
    if (c == 0){ red[128 + nhalf*64 + rA] = sA; red[128 + nhalf*64 + rB] = sB; }
    __syncthreads();
    float invA = 1.f/(red[128+rA] + red[128+64+rA]);
    float invB = 1.f/(red[128+rB] + red[128+64+rB]);

    // normalized local probs back
    #pragma unroll
    for (int t = 0; t < 4; t++){
        int col0 = n0 + t*8 + 2*c;
        float2 wA, wB;
        wA.x = locA[t].x*invA; wA.y = locA[t].y*invA;
        wB.x = locB[t].x*invB; wB.y = locB[t].y*invB;
        *(float2*)(g_joint + jbA + col0) = wA;
        *(float2*)(g_joint + jbB + col0) = wB;
    }

    // normalized gatt (split) into q region
    #pragma unroll
    for (int t = 0; t < 4; t++){
        int col0 = n0 + t*8 + 2*c;
        *(uint32_t*)(qh + rA*KST + col0) = pack_hi(p[t][0]*invA, p[t][1]*invA);
        *(uint32_t*)(ql + rA*KST + col0) = pack_lo(p[t][0]*invA, p[t][1]*invA);
        *(uint32_t*)(qh + rB*KST + col0) = pack_hi(p[t][2]*invB, p[t][3]*invB);
        *(uint32_t*)(ql + rB*KST + col0) = pack_lo(p[t][2]*invB, p[t][3]*invB);
    }
    __syncthreads();

    // --- O = gatt @ rowattn (trans-B on row-major ra tiles) ---
    float accO[4][4];
    #pragma unroll
    for (int t=0;t<4;t++)
        #pragma unroll
        for (int q2=0;q2<4;q2++) accO[t][q2]=0.f;

    #pragma unroll
    for (int kk = 0; kk < 4; kk++){
        uint32_t ah[4], al[4], bh2[2][4], bl2[2][4];
        uint32_t ad = sbB + aoff + kk*32;
        ldsm_x4(ah, ad);
        ldsm_x4(al, ad + TILEB);
        uint32_t bd = sbB + 4*TILEB + toff + kk*(16*KST*2);
        ldsm_x4_t(bh2[0], bd);
        ldsm_x4_t(bl2[0], bd + TILEB);
        ldsm_x4_t(bh2[1], bd + 16*2);
        ldsm_x4_t(bl2[1], bd + 16*2 + TILEB);
        #pragma unroll
        for (int t = 0; t < 4; t++){
            const uint32_t* bh = bh2[t>>1] + (t&1)*2;
            const uint32_t* bl = bl2[t>>1] + (t&1)*2;
            mma16816(accO[t], ah, bh);
            mma16816(accO[t], ah, bl);
            mma16816(accO[t], al, bh);
        }
    }

    #pragma unroll
    for (int t = 0; t < 4; t++){
        int col0 = n0 + t*8 + 2*c;
        size_t oA = tA*Dn + h*HDn + col0;
        size_t oB = tB*Dn + h*HDn + col0;
        *(float2*)(g_merged + oA) = make_float2(accO[t][0], accO[t][1]);
        *(float2*)(g_merged + oB) = make_float2(accO[t][2], accO[t][3]);
    }
}

// ---------------------------------------------------------------------------
// MMA local_merged finalizer per (h, seg, b): P from g_joint (convert),
// v via cp.async + trans-B. Writes staging split for out GEMM.
// ---------------------------------------------------------------------------
#define LM_SMEM (4*TILEB)
__global__ void __launch_bounds__(256)
local_merged_kernel()
{
    extern __shared__ __nv_bfloat16 bsm[];
    __nv_bfloat16* ph = bsm;
    __nv_bfloat16* pl = bsm + TILEB/2;

    int h = blockIdx.x, seg = blockIdx.y, b = blockIdx.z;
    int tid = threadIdx.x, lane = tid & 31, wid = tid >> 5;
    int g = lane >> 2, c = lane & 3;
    size_t tok0 = ((size_t)b*NSn + seg)*SEGn;
    size_t hb = tok0*Dn + h*HDn;
    uint32_t sbB = smem_u32(bsm);

    // v tiles (2,3) via cp.async
    const __nv_bfloat16* vs[2] = {g_vhi+hb, g_vlo+hb};
    #pragma unroll
    for (int t = 0; t < 2; t++){
        #pragma unroll
        for (int it = 0; it < 2; it++){
            int idx = it*256 + tid;
            int r = idx >> 3, cc = idx & 7;
            cp_async16(sbB + (2+t)*TILEB + r*(KST*2) + cc*16,
                       vs[t] + (size_t)r*Dn + cc*8);
        }
    }
    cp_commit();

    // P tiles from g_joint (fp32 -> split), row-major
    for (int i = tid; i < 64*16; i += 256){
        int r = i >> 4, c4 = (i & 15)*4;
        float4 pv = *(const float4*)(g_joint + ((tok0+r)*Hn+h)*128 + c4);
        uint2 t;
        t.x = pack_hi(pv.x,pv.y); t.y = pack_hi(pv.z,pv.w);
        *(uint2*)(ph + r*KST + c4) = t;
        t.x = pack_lo(pv.x,pv.y); t.y = pack_lo(pv.z,pv.w);
        *(uint2*)(pl + r*KST + c4) = t;
    }
    cp_wait<0>();
    __syncthreads();

    int mband = wid & 3, nhalf = wid >> 2;
    int r0 = mband*16, n0 = nhalf*32;
    int rA = r0 + g, rB = rA + 8;
    uint32_t aoff = ATT_AOFF(lane, r0);
    uint32_t toff = ATT_TOFF(lane, n0);

    float accO[4][4];
    #pragma unroll
    for (int t=0;t<4;t++)
        #pragma unroll
        for (int q2=0;q2<4;q2++) accO[t][q2]=0.f;

    #pragma unroll
    for (int kk = 0; kk < 4; kk++){
        uint32_t ah[4], al[4], bh2[2][4], bl2[2][4];
        uint32_t ad = sbB + aoff + kk*32;
        ldsm_x4(ah, ad);
        ldsm_x4(al, ad + TILEB);
        uint32_t bd = sbB + 2*TILEB + toff + kk*(16*KST*2);
        ldsm_x4_t(bh2[0], bd);
        ldsm_x4_t(bl2[0], bd + TILEB);
        ldsm_x4_t(bh2[1], bd + 16*2);
        ldsm_x4_t(bl2[1], bd + 16*2 + TILEB);
        #pragma unroll
        for (int t = 0; t < 4; t++){
            const uint32_t* bh = bh2[t>>1] + (t&1)*2;
            const uint32_t* bl = bl2[t>>1] + (t&1)*2;
            mma16816(accO[t], ah, bh);
            mma16816(accO[t], ah, bl);
            mma16816(accO[t], al, bh);
        }
    }

    #pragma unroll
    for (int t = 0; t < 4; t++){
        int col0 = n0 + t*8 + 2*c;
        size_t oA = (tok0+rA)*Dn + h*HDn + col0;
        size_t oB = (tok0+rB)*Dn + h*HDn + col0;
        float2 mA = *(const float2*)(g_merged + oA);
        float2 mB = *(const float2*)(g_merged + oB);
        float a0 = mA.x + accO[t][0], a1 = mA.y + accO[t][1];
        float a2 = mB.x + accO[t][2], a3 = mB.y + accO[t][3];
        *(uint32_t*)(g_ahi + oA) = pack_hi(a0, a1);
        *(uint32_t*)(g_alo + oA) = pack_lo(a0, a1);
        *(uint32_t*)(g_ahi + oB) = pack_hi(a2, a3);
        *(uint32_t*)(g_alo + oB) = pack_lo(a2, a3);
    }
}

// ---------------------------------------------------------------------------
// Launch
// ---------------------------------------------------------------------------
extern "C" void kernel_launch(void* const* d_in, const int* in_sizes, int n_in,
                              void* d_out, int out_size)
{
    const float* x    = (const float*)d_in[0];
    const float* Wq   = (const float*)d_in[1];
    const float* Wk   = (const float*)d_in[2];
    const float* Wv   = (const float*)d_in[3];
    const float* Wro  = (const float*)d_in[4];
    const float* lns  = (const float*)d_in[5];
    const float* lnb  = (const float*)d_in[6];
    const float* Wk2  = (const float*)d_in[7];
    const float* Wout = (const float*)d_in[8];
    float* out = (float*)d_out;

    cudaFuncSetAttribute(local_attn_kernel,
                         cudaFuncAttributeMaxDynamicSharedMemorySize, LA_SMEM);
    cudaFuncSetAttribute(global_fused_kernel,
                         cudaFuncAttributeMaxDynamicSharedMemorySize, LA_SMEM);
    cudaFuncSetAttribute(local_merged_kernel,
                         cudaFuncAttributeMaxDynamicSharedMemorySize, LM_SMEM);
    cudaFuncSetAttribute(hmma_gemm,
                         cudaFuncAttributeMaxDynamicSharedMemorySize, HG_SMEM);

    dim3 gg(8, 128);
    dim3 gq(8, 128, 3);         // fused QKV
    dim3 ga(Hn, NSn, Bn);
    dim3 gl(Hn, SEGn, Bn);
    const int ACT_BLKS = (NTOK*Dn/4)/256;

    convert_wt<<<dim3(32,32,6),256>>>(Wq, Wk, Wv, Wro, Wk2, Wout);

    convert_act<<<ACT_BLKS,256>>>(x);
    hmma_gemm<<<gq,256,HG_SMEM>>>(-1, 0, nullptr, 0, nullptr, 0.f);   // q,k,v split

    local_attn_kernel<<<ga,256,LA_SMEM>>>();                          // rowattn split

    hmma_gemm<<<gg,256,HG_SMEM>>>(3, 1, nullptr, 4, x, 1.f);          // t1 = rowattn@Wro + x
    ln_kernel<<<NTOK,256>>>(lns, lnb);                                // -> staging split
    hmma_gemm<<<gg,256,HG_SMEM>>>(4, 0, nullptr, 14, nullptr, 1.f);   // krow split

    global_fused_kernel<<<gl,256,LA_SMEM>>>();                        // logits+softmax+gmerge
    local_merged_kernel<<<ga,256,LM_SMEM>>>();                        // finalize -> staging split

    hmma_gemm<<<gg,256,HG_SMEM>>>(5, 0, out, 0, nullptr, 1.f);        // output
}